// round 1
// baseline (speedup 1.0000x reference)
#include <cuda_runtime.h>
#include <cstdint>

#define D_MODEL 1024
#define N_HEAD  16
#define HEAD_DIM 64
#define BATCH   4
#define SEQ     2048
#define BH      (BATCH * N_HEAD)          // 64
#define MROWS   (BATCH * SEQ)             // 8192

// Scratch (device globals; allocation-free per harness rules)
__device__ float g_Q[BH * SEQ * HEAD_DIM];      // [bh][s][hd]
__device__ float g_K[BH * SEQ * HEAD_DIM];
__device__ float g_V[BH * SEQ * HEAD_DIM];
__device__ float g_S[(size_t)BH * SEQ * SEQ];   // scores / probs, 1.07 GB
__device__ float g_A[(size_t)MROWS * D_MODEL];  // attention output [b*s, d_model]

// ---------------------------------------------------------------------------
// Tiled SGEMM + bias: C[M,N] = A[M,K] @ W[K,N] + bias[N]
// BM=128, BN=128, BK=8, 256 threads, 8x8 per thread.
// HEADS=true  -> store into [b,h,s,d] layout (projections)
// HEADS=false -> store row-major [M,N] (output projection)
// ---------------------------------------------------------------------------
template <bool HEADS>
__global__ void __launch_bounds__(256) sgemm_bias_kernel(
    const float* __restrict__ A, const float* __restrict__ W,
    const float* __restrict__ bias, float* __restrict__ out,
    int M, int N, int K)
{
    __shared__ float As[8][128];
    __shared__ float Bs[8][128];

    const int tid = threadIdx.x;
    const int bx = blockIdx.x;   // N tile
    const int by = blockIdx.y;   // M tile
    const int tx = tid & 15;
    const int ty = tid >> 4;

    const int a_row = tid >> 1;          // 0..127
    const int a_col = (tid & 1) * 4;     // 0 or 4
    const int b_row = tid >> 5;          // 0..7
    const int b_col = (tid & 31) * 4;    // 0..124

    const float* Ab = A + (size_t)(by * 128) * K;
    const float* Wb = W + bx * 128;

    float acc[8][8];
#pragma unroll
    for (int i = 0; i < 8; i++)
#pragma unroll
        for (int j = 0; j < 8; j++) acc[i][j] = 0.f;

    for (int k0 = 0; k0 < K; k0 += 8) {
        float4 av = *(const float4*)(Ab + (size_t)a_row * K + k0 + a_col);
        As[a_col + 0][a_row] = av.x;
        As[a_col + 1][a_row] = av.y;
        As[a_col + 2][a_row] = av.z;
        As[a_col + 3][a_row] = av.w;
        float4 bv = *(const float4*)(Wb + (size_t)(k0 + b_row) * N + b_col);
        *(float4*)&Bs[b_row][b_col] = bv;
        __syncthreads();
#pragma unroll
        for (int k = 0; k < 8; k++) {
            float4 a0 = *(const float4*)&As[k][ty * 8];
            float4 a1 = *(const float4*)&As[k][ty * 8 + 4];
            float4 b0 = *(const float4*)&Bs[k][tx * 8];
            float4 b1 = *(const float4*)&Bs[k][tx * 8 + 4];
            float a[8] = {a0.x, a0.y, a0.z, a0.w, a1.x, a1.y, a1.z, a1.w};
            float b[8] = {b0.x, b0.y, b0.z, b0.w, b1.x, b1.y, b1.z, b1.w};
#pragma unroll
            for (int i = 0; i < 8; i++)
#pragma unroll
                for (int j = 0; j < 8; j++) acc[i][j] += a[i] * b[j];
        }
        __syncthreads();
    }

#pragma unroll
    for (int i = 0; i < 8; i++) {
        const int m = by * 128 + ty * 8 + i;
#pragma unroll
        for (int j = 0; j < 8; j++) {
            const int n = bx * 128 + tx * 8 + j;
            const float v = acc[i][j] + bias[n];
            if (HEADS) {
                const int b = m >> 11;        // m / SEQ
                const int s = m & (SEQ - 1);
                const int h = n >> 6;         // n / HEAD_DIM
                const int d = n & 63;
                out[((((size_t)b * N_HEAD + h) * SEQ) + s) * HEAD_DIM + d] = v;
            } else {
                out[(size_t)m * N + n] = v;
            }
        }
    }
}

// ---------------------------------------------------------------------------
// Scores: S[bh][i][j] = dot(Q[bh][i], K[bh][j]) * (1/32), causal mask -> -1e30
// grid (S/64, S/64, BH), 256 threads, 64x64 tile, full K=64 in smem.
// ---------------------------------------------------------------------------
__global__ void __launch_bounds__(256) scores_kernel(
    const float* __restrict__ Q, const float* __restrict__ Kt,
    float* __restrict__ Sg)
{
    const int j0 = blockIdx.x * 64;
    const int i0 = blockIdx.y * 64;
    const int bh = blockIdx.z;
    float* Sout = Sg + (size_t)bh * SEQ * SEQ;
    const int tid = threadIdx.x;

    if (j0 > i0 + 63) {  // fully masked tile
        for (int idx = tid; idx < 64 * 64; idx += 256) {
            const int i = idx >> 6, j = idx & 63;
            Sout[(size_t)(i0 + i) * SEQ + j0 + j] = -1e30f;
        }
        return;
    }

    __shared__ float Qs[64][64];  // [d][m] transposed
    __shared__ float Ks[64][64];  // [d][n] transposed

    const float* Qb = Q + (size_t)bh * SEQ * HEAD_DIM;
    const float* Kb = Kt + (size_t)bh * SEQ * HEAD_DIM;

#pragma unroll
    for (int r = 0; r < 4; r++) {
        const int idx = tid + r * 256;          // over 1024 float4s
        const int row = idx >> 4;
        const int c4 = (idx & 15) * 4;
        float4 qv = *(const float4*)(Qb + (size_t)(i0 + row) * HEAD_DIM + c4);
        Qs[c4 + 0][row] = qv.x; Qs[c4 + 1][row] = qv.y;
        Qs[c4 + 2][row] = qv.z; Qs[c4 + 3][row] = qv.w;
        float4 kv = *(const float4*)(Kb + (size_t)(j0 + row) * HEAD_DIM + c4);
        Ks[c4 + 0][row] = kv.x; Ks[c4 + 1][row] = kv.y;
        Ks[c4 + 2][row] = kv.z; Ks[c4 + 3][row] = kv.w;
    }
    __syncthreads();

    const int tx = tid & 15;
    const int ty = tid >> 4;
    float acc[4][4];
#pragma unroll
    for (int i = 0; i < 4; i++)
#pragma unroll
        for (int j = 0; j < 4; j++) acc[i][j] = 0.f;

#pragma unroll 8
    for (int k = 0; k < 64; k++) {
        float4 a = *(const float4*)&Qs[k][ty * 4];
        float4 b = *(const float4*)&Ks[k][tx * 4];
        float av[4] = {a.x, a.y, a.z, a.w};
        float bv[4] = {b.x, b.y, b.z, b.w};
#pragma unroll
        for (int i = 0; i < 4; i++)
#pragma unroll
            for (int j = 0; j < 4; j++) acc[i][j] += av[i] * bv[j];
    }

    const float scale = 0.03125f;  // 1/sqrt(1024)
#pragma unroll
    for (int i = 0; i < 4; i++) {
        const int gi = i0 + ty * 4 + i;
        float4 v;
        float vv[4];
#pragma unroll
        for (int j = 0; j < 4; j++) {
            const int gj = j0 + tx * 4 + j;
            vv[j] = (gj <= gi) ? acc[i][j] * scale : -1e30f;
        }
        v.x = vv[0]; v.y = vv[1]; v.z = vv[2]; v.w = vv[3];
        *(float4*)(Sout + (size_t)gi * SEQ + j0 + tx * 4) = v;
    }
}

// ---------------------------------------------------------------------------
// Softmax over rows of g_S (length SEQ). One block (256 thr) per row.
// ---------------------------------------------------------------------------
__global__ void __launch_bounds__(256) softmax_kernel(float* __restrict__ Sg)
{
    const size_t row = blockIdx.x;
    float* p = Sg + row * SEQ;
    const int tid = threadIdx.x;

    float v[8];
    float lmax = -1e30f;
#pragma unroll
    for (int i = 0; i < 8; i++) {
        v[i] = p[tid + i * 256];
        lmax = fmaxf(lmax, v[i]);
    }

    __shared__ float red[256];
    red[tid] = lmax;
    __syncthreads();
#pragma unroll
    for (int s = 128; s > 0; s >>= 1) {
        if (tid < s) red[tid] = fmaxf(red[tid], red[tid + s]);
        __syncthreads();
    }
    const float m = red[0];
    __syncthreads();

    float lsum = 0.f;
#pragma unroll
    for (int i = 0; i < 8; i++) {
        v[i] = __expf(v[i] - m);
        lsum += v[i];
    }
    red[tid] = lsum;
    __syncthreads();
#pragma unroll
    for (int s = 128; s > 0; s >>= 1) {
        if (tid < s) red[tid] += red[tid + s];
        __syncthreads();
    }
    const float inv = 1.f / red[0];
#pragma unroll
    for (int i = 0; i < 8; i++) p[tid + i * 256] = v[i] * inv;
}

// ---------------------------------------------------------------------------
// PV: O[bh][i][:] = P[bh][i][:] @ V[bh]. grid (S/64, BH), 256 thr.
// BM=64, BN=64 (=HEAD_DIM), BK=32; causal truncates the K loop.
// Output into g_A as [b*s, h*64+d].
// ---------------------------------------------------------------------------
__global__ void __launch_bounds__(256) pv_kernel(
    const float* __restrict__ P, const float* __restrict__ V,
    float* __restrict__ Og)
{
    const int i0 = blockIdx.x * 64;
    const int bh = blockIdx.y;
    const float* Pb = P + (size_t)bh * SEQ * SEQ;
    const float* Vb = V + (size_t)bh * SEQ * HEAD_DIM;
    const int tid = threadIdx.x;
    const int tx = tid & 15;
    const int ty = tid >> 4;

    __shared__ float Ps[32][64];  // [k][m]
    __shared__ float Vs[32][64];  // [k][n]

    float acc[4][4];
#pragma unroll
    for (int i = 0; i < 4; i++)
#pragma unroll
        for (int j = 0; j < 4; j++) acc[i][j] = 0.f;

    const int kmax = i0 + 64;  // P is exactly 0 beyond the diagonal
    for (int k0 = 0; k0 < kmax; k0 += 32) {
#pragma unroll
        for (int r = 0; r < 2; r++) {
            const int idx = tid + r * 256;       // 512 float4s: 64x32 tile
            const int row = idx >> 3;
            const int c4 = (idx & 7) * 4;
            float4 pv = *(const float4*)(Pb + (size_t)(i0 + row) * SEQ + k0 + c4);
            Ps[c4 + 0][row] = pv.x; Ps[c4 + 1][row] = pv.y;
            Ps[c4 + 2][row] = pv.z; Ps[c4 + 3][row] = pv.w;
        }
#pragma unroll
        for (int r = 0; r < 2; r++) {
            const int idx = tid + r * 256;       // 512 float4s: 32x64 tile
            const int row = idx >> 4;
            const int c4 = (idx & 15) * 4;
            *(float4*)&Vs[row][c4] =
                *(const float4*)(Vb + (size_t)(k0 + row) * HEAD_DIM + c4);
        }
        __syncthreads();
#pragma unroll 8
        for (int k = 0; k < 32; k++) {
            float4 a = *(const float4*)&Ps[k][ty * 4];
            float4 b = *(const float4*)&Vs[k][tx * 4];
            float av[4] = {a.x, a.y, a.z, a.w};
            float bv[4] = {b.x, b.y, b.z, b.w};
#pragma unroll
            for (int i = 0; i < 4; i++)
#pragma unroll
                for (int j = 0; j < 4; j++) acc[i][j] += av[i] * bv[j];
        }
        __syncthreads();
    }

    const int b = bh >> 4;
    const int h = bh & 15;
#pragma unroll
    for (int i = 0; i < 4; i++) {
        const int s = i0 + ty * 4 + i;
        float4 v;
        v.x = acc[i][0]; v.y = acc[i][1]; v.z = acc[i][2]; v.w = acc[i][3];
        *(float4*)(Og + ((size_t)(b * SEQ + s)) * D_MODEL + h * HEAD_DIM + tx * 4) = v;
    }
}

// ---------------------------------------------------------------------------
extern "C" void kernel_launch(void* const* d_in, const int* in_sizes, int n_in,
                              void* d_out, int out_size)
{
    const float* q  = (const float*)d_in[0];
    const float* k  = (const float*)d_in[1];
    const float* v  = (const float*)d_in[2];
    const float* Wq = (const float*)d_in[3];
    const float* bq = (const float*)d_in[4];
    const float* Wk = (const float*)d_in[5];
    const float* bk = (const float*)d_in[6];
    const float* Wv = (const float*)d_in[7];
    const float* bv = (const float*)d_in[8];
    const float* Wo = (const float*)d_in[9];
    const float* bo = (const float*)d_in[10];

    float *Qp, *Kp, *Vp, *Sp, *Ap;
    cudaGetSymbolAddress((void**)&Qp, g_Q);
    cudaGetSymbolAddress((void**)&Kp, g_K);
    cudaGetSymbolAddress((void**)&Vp, g_V);
    cudaGetSymbolAddress((void**)&Sp, g_S);
    cudaGetSymbolAddress((void**)&Ap, g_A);

    dim3 gProj(D_MODEL / 128, MROWS / 128);  // (8, 64)
    sgemm_bias_kernel<true><<<gProj, 256>>>(q, Wq, bq, Qp, MROWS, D_MODEL, D_MODEL);
    sgemm_bias_kernel<true><<<gProj, 256>>>(k, Wk, bk, Kp, MROWS, D_MODEL, D_MODEL);
    sgemm_bias_kernel<true><<<gProj, 256>>>(v, Wv, bv, Vp, MROWS, D_MODEL, D_MODEL);

    scores_kernel<<<dim3(SEQ / 64, SEQ / 64, BH), 256>>>(Qp, Kp, Sp);
    softmax_kernel<<<BH * SEQ, 256>>>(Sp);
    pv_kernel<<<dim3(SEQ / 64, BH), 256>>>(Sp, Vp, Ap);

    sgemm_bias_kernel<false><<<gProj, 256>>>(Ap, Wo, bo, (float*)d_out,
                                             MROWS, D_MODEL, D_MODEL);
}

// round 3
// speedup vs baseline: 1.3374x; 1.3374x over previous
#include <cuda_runtime.h>
#include <cuda_bf16.h>
#include <cstdint>

#define D_MODEL 1024
#define N_HEAD  16
#define HEAD_DIM 64
#define BATCH   4
#define SEQ     2048
#define BH      (BATCH * N_HEAD)          // 64
#define MROWS   (BATCH * SEQ)             // 8192
#define GK      1024
#define GN      1024

// ---------------------------------------------------------------------------
// Scratch (device globals; allocation-free per harness rules)
// ---------------------------------------------------------------------------
__device__ float g_Q[BH * SEQ * HEAD_DIM];      // [bh][s][hd]
__device__ float g_K[BH * SEQ * HEAD_DIM];
__device__ float g_V[BH * SEQ * HEAD_DIM];
__device__ float g_S[(size_t)BH * SEQ * SEQ];   // scores / probs, 1.07 GB
__device__ float g_A[(size_t)MROWS * D_MODEL];  // attention output [b*s, d_model]

// bf16 split operands
__device__ __nv_bfloat16 g_qh[MROWS * D_MODEL], g_ql[MROWS * D_MODEL];
__device__ __nv_bfloat16 g_kh[MROWS * D_MODEL], g_kl[MROWS * D_MODEL];
__device__ __nv_bfloat16 g_vh[MROWS * D_MODEL], g_vl[MROWS * D_MODEL];
__device__ __nv_bfloat16 g_ah[MROWS * D_MODEL], g_al[MROWS * D_MODEL];
// transposed weights [N][K] bf16 hi/lo
__device__ __nv_bfloat16 g_Wqh[D_MODEL * D_MODEL], g_Wql[D_MODEL * D_MODEL];
__device__ __nv_bfloat16 g_Wkh[D_MODEL * D_MODEL], g_Wkl[D_MODEL * D_MODEL];
__device__ __nv_bfloat16 g_Wvh[D_MODEL * D_MODEL], g_Wvl[D_MODEL * D_MODEL];
__device__ __nv_bfloat16 g_Woh[D_MODEL * D_MODEL], g_Wol[D_MODEL * D_MODEL];

// ---------------------------------------------------------------------------
__device__ __forceinline__ uint32_t smem_u32(const void* p) {
    uint32_t a;
    asm("{ .reg .u64 t; cvta.to.shared.u64 t, %1; cvt.u32.u64 %0, t; }"
        : "=r"(a) : "l"(p));
    return a;
}

#define CP_ASYNC16(dst_u32, src_ptr) \
    asm volatile("cp.async.cg.shared.global [%0], [%1], 16;" \
        :: "r"(dst_u32), "l"(src_ptr))

__device__ __forceinline__ void ldsm_x4(uint32_t* r, uint32_t addr) {
    asm volatile("ldmatrix.sync.aligned.m8n8.x4.shared.b16 {%0,%1,%2,%3}, [%4];"
        : "=r"(r[0]), "=r"(r[1]), "=r"(r[2]), "=r"(r[3]) : "r"(addr));
}

__device__ __forceinline__ void mma16816(float* d, const uint32_t* a,
                                         const uint32_t* b) {
    asm volatile(
        "mma.sync.aligned.m16n8k16.row.col.f32.bf16.bf16.f32 "
        "{%0,%1,%2,%3}, {%4,%5,%6,%7}, {%8,%9}, {%0,%1,%2,%3};"
        : "+f"(d[0]), "+f"(d[1]), "+f"(d[2]), "+f"(d[3])
        : "r"(a[0]), "r"(a[1]), "r"(a[2]), "r"(a[3]), "r"(b[0]), "r"(b[1]));
}

// ---------------------------------------------------------------------------
// HMMA bf16-split GEMM: out[M=8192, N=1024] = X @ W + bias
// A terms [M,K] bf16; B terms [N,K] bf16 (K-major = col-major B for mma).
// BM=128, BN=128, BK=32, 8 warps (2x4), warp tile 64x32, double-buffered.
// ---------------------------------------------------------------------------
#define NSTAGES 96   // 3 split terms * (1024/32)

template <bool HEADS>
__global__ void __launch_bounds__(256) gemm_mma_kernel(
    const __nv_bfloat16* __restrict__ Ahi, const __nv_bfloat16* __restrict__ Alo,
    const __nv_bfloat16* __restrict__ Bhi, const __nv_bfloat16* __restrict__ Blo,
    const float* __restrict__ bias, float* __restrict__ out)
{
    __shared__ __nv_bfloat16 As[2][128][40];   // 32 cols + 8 pad (16B-aligned rows)
    __shared__ __nv_bfloat16 Bs[2][128][40];

    const int tid = threadIdx.x;
    const int wid = tid >> 5;
    const int lane = tid & 31;
    const int m0 = blockIdx.y * 128;
    const int n0 = blockIdx.x * 128;
    const int wm = (wid & 1) * 64;    // warp m offset
    const int wn = (wid >> 1) * 32;   // warp n offset

    const __nv_bfloat16* Aterm[3] = {Ahi, Ahi, Alo};
    const __nv_bfloat16* Bterm[3] = {Bhi, Blo, Bhi};

    float acc[4][4][4];
#pragma unroll
    for (int i = 0; i < 4; i++)
#pragma unroll
        for (int j = 0; j < 4; j++)
#pragma unroll
            for (int c = 0; c < 4; c++) acc[i][j][c] = 0.f;

    // loader: 512 16B-chunks each for A and B; thread does 2 of each
    const int ldrow = tid >> 2;            // 0..63  (+64 for second)
    const int ldcol = (tid & 3) * 8;       // 0,8,16,24

    auto issue_load = [&](int stage, int i) {
        const int term = i >> 5;
        const int k0 = (i & 31) << 5;
        const __nv_bfloat16* Ag = Aterm[term];
        const __nv_bfloat16* Bg = Bterm[term];
#pragma unroll
        for (int r = 0; r < 2; r++) {
            const int row = ldrow + r * 64;
            CP_ASYNC16(smem_u32(&As[stage][row][ldcol]),
                       Ag + (size_t)(m0 + row) * GK + k0 + ldcol);
            CP_ASYNC16(smem_u32(&Bs[stage][row][ldcol]),
                       Bg + (size_t)(n0 + row) * GK + k0 + ldcol);
        }
        asm volatile("cp.async.commit_group;" ::: "memory");
    };

    issue_load(0, 0);

    for (int i = 0; i < NSTAGES; i++) {
        const int st = i & 1;
        if (i + 1 < NSTAGES) {
            issue_load(st ^ 1, i + 1);
            asm volatile("cp.async.wait_group 1;" ::: "memory");
        } else {
            asm volatile("cp.async.wait_group 0;" ::: "memory");
        }
        __syncthreads();

#pragma unroll
        for (int ks = 0; ks < 2; ks++) {
            // A fragments: 4 m-blocks of 16
            uint32_t af[4][4];
#pragma unroll
            for (int mi = 0; mi < 4; mi++) {
                const uint32_t addr = smem_u32(
                    &As[st][wm + mi * 16 + (lane & 15)][ks * 16 + (lane >> 4) * 8]);
                ldsm_x4(af[mi], addr);
            }
            // B fragments: 4 n-blocks of 8 (two x4 loads, each covers 16 n)
            uint32_t bf[4][2];
#pragma unroll
            for (int njp = 0; njp < 2; njp++) {
                uint32_t r[4];
                const int t = lane >> 3;            // tile index 0..3
                const int nrow = wn + njp * 16 + (t >> 1) * 8 + (lane & 7);
                const int kcol = ks * 16 + (t & 1) * 8;
                ldsm_x4(r, smem_u32(&Bs[st][nrow][kcol]));
                bf[njp * 2 + 0][0] = r[0]; bf[njp * 2 + 0][1] = r[1];
                bf[njp * 2 + 1][0] = r[2]; bf[njp * 2 + 1][1] = r[3];
            }
#pragma unroll
            for (int mi = 0; mi < 4; mi++)
#pragma unroll
                for (int nj = 0; nj < 4; nj++)
                    mma16816(acc[mi][nj], af[mi], bf[nj]);
        }
        __syncthreads();
    }

    // Epilogue: direct stores with bias; fragment c0,c1 -> (m, n..n+1), c2,c3 -> m+8
#pragma unroll
    for (int mi = 0; mi < 4; mi++) {
#pragma unroll
        for (int nj = 0; nj < 4; nj++) {
            const int n = n0 + wn + nj * 8 + (lane & 3) * 2;
            const float b0 = bias[n], b1 = bias[n + 1];
#pragma unroll
            for (int half = 0; half < 2; half++) {
                const int m = m0 + wm + mi * 16 + (lane >> 2) + half * 8;
                const float v0 = acc[mi][nj][half * 2 + 0] + b0;
                const float v1 = acc[mi][nj][half * 2 + 1] + b1;
                if (HEADS) {
                    const int b = m >> 11;
                    const int s = m & (SEQ - 1);
                    const int h = n >> 6;
                    const int d = n & 63;
                    float2* dst = (float2*)&out[((((size_t)b * N_HEAD + h) * SEQ) + s)
                                                * HEAD_DIM + d];
                    *dst = make_float2(v0, v1);
                } else {
                    *(float2*)&out[(size_t)m * GN + n] = make_float2(v0, v1);
                }
            }
        }
    }
}

// ---------------------------------------------------------------------------
// fp32 -> bf16 hi/lo split (activations), float4 vectorized
// ---------------------------------------------------------------------------
__global__ void __launch_bounds__(256) split_kernel(
    const float4* __restrict__ in, __nv_bfloat162* __restrict__ hi,
    __nv_bfloat162* __restrict__ lo, int n4)
{
    const int stride = gridDim.x * blockDim.x;
    for (int i = blockIdx.x * blockDim.x + threadIdx.x; i < n4; i += stride) {
        float4 v = in[i];
        __nv_bfloat16 hx = __float2bfloat16(v.x);
        __nv_bfloat16 hy = __float2bfloat16(v.y);
        __nv_bfloat16 hz = __float2bfloat16(v.z);
        __nv_bfloat16 hw = __float2bfloat16(v.w);
        __nv_bfloat162 h0; h0.x = hx; h0.y = hy;
        __nv_bfloat162 h1; h1.x = hz; h1.y = hw;
        __nv_bfloat162 l0, l1;
        l0.x = __float2bfloat16(v.x - __bfloat162float(hx));
        l0.y = __float2bfloat16(v.y - __bfloat162float(hy));
        l1.x = __float2bfloat16(v.z - __bfloat162float(hz));
        l1.y = __float2bfloat16(v.w - __bfloat162float(hw));
        hi[i * 2] = h0; hi[i * 2 + 1] = h1;
        lo[i * 2] = l0; lo[i * 2 + 1] = l1;
    }
}

// ---------------------------------------------------------------------------
// W[K,N] -> Wt hi/lo [N,K] bf16 (transpose + split)
// ---------------------------------------------------------------------------
__global__ void __launch_bounds__(256) wsplit_kernel(
    const float* __restrict__ W, __nv_bfloat16* __restrict__ hiT,
    __nv_bfloat16* __restrict__ loT)
{
    __shared__ float t[32][33];
    const int n0 = blockIdx.x * 32, k0 = blockIdx.y * 32;
    const int tx = threadIdx.x & 31, ty = threadIdx.x >> 5;  // 32x8
#pragma unroll
    for (int r = 0; r < 4; r++) {
        const int kl = ty + r * 8;
        t[kl][tx] = W[(size_t)(k0 + kl) * D_MODEL + n0 + tx];
    }
    __syncthreads();
#pragma unroll
    for (int r = 0; r < 4; r++) {
        const int nl = ty + r * 8;
        const float x = t[tx][nl];
        const __nv_bfloat16 h = __float2bfloat16(x);
        hiT[(size_t)(n0 + nl) * D_MODEL + k0 + tx] = h;
        loT[(size_t)(n0 + nl) * D_MODEL + k0 + tx] =
            __float2bfloat16(x - __bfloat162float(h));
    }
}

// ---------------------------------------------------------------------------
// Scores: S[bh][i][j] = dot(Q[bh][i], K[bh][j]) * (1/32), causal mask
// ---------------------------------------------------------------------------
__global__ void __launch_bounds__(256) scores_kernel(
    const float* __restrict__ Q, const float* __restrict__ Kt,
    float* __restrict__ Sg)
{
    const int j0 = blockIdx.x * 64;
    const int i0 = blockIdx.y * 64;
    const int bh = blockIdx.z;
    float* Sout = Sg + (size_t)bh * SEQ * SEQ;
    const int tid = threadIdx.x;

    if (j0 > i0 + 63) {
        for (int idx = tid; idx < 64 * 64; idx += 256) {
            const int i = idx >> 6, j = idx & 63;
            Sout[(size_t)(i0 + i) * SEQ + j0 + j] = -1e30f;
        }
        return;
    }

    __shared__ float Qs[64][64];
    __shared__ float Ks[64][64];

    const float* Qb = Q + (size_t)bh * SEQ * HEAD_DIM;
    const float* Kb = Kt + (size_t)bh * SEQ * HEAD_DIM;

#pragma unroll
    for (int r = 0; r < 4; r++) {
        const int idx = tid + r * 256;
        const int row = idx >> 4;
        const int c4 = (idx & 15) * 4;
        float4 qv = *(const float4*)(Qb + (size_t)(i0 + row) * HEAD_DIM + c4);
        Qs[c4 + 0][row] = qv.x; Qs[c4 + 1][row] = qv.y;
        Qs[c4 + 2][row] = qv.z; Qs[c4 + 3][row] = qv.w;
        float4 kv = *(const float4*)(Kb + (size_t)(j0 + row) * HEAD_DIM + c4);
        Ks[c4 + 0][row] = kv.x; Ks[c4 + 1][row] = kv.y;
        Ks[c4 + 2][row] = kv.z; Ks[c4 + 3][row] = kv.w;
    }
    __syncthreads();

    const int tx = tid & 15;
    const int ty = tid >> 4;
    float acc[4][4];
#pragma unroll
    for (int i = 0; i < 4; i++)
#pragma unroll
        for (int j = 0; j < 4; j++) acc[i][j] = 0.f;

#pragma unroll 8
    for (int k = 0; k < 64; k++) {
        float4 a = *(const float4*)&Qs[k][ty * 4];
        float4 b = *(const float4*)&Ks[k][tx * 4];
        float av[4] = {a.x, a.y, a.z, a.w};
        float bv[4] = {b.x, b.y, b.z, b.w};
#pragma unroll
        for (int i = 0; i < 4; i++)
#pragma unroll
            for (int j = 0; j < 4; j++) acc[i][j] += av[i] * bv[j];
    }

    const float scale = 0.03125f;
#pragma unroll
    for (int i = 0; i < 4; i++) {
        const int gi = i0 + ty * 4 + i;
        float4 v;
        float vv[4];
#pragma unroll
        for (int j = 0; j < 4; j++) {
            const int gj = j0 + tx * 4 + j;
            vv[j] = (gj <= gi) ? acc[i][j] * scale : -1e30f;
        }
        v.x = vv[0]; v.y = vv[1]; v.z = vv[2]; v.w = vv[3];
        *(float4*)(Sout + (size_t)gi * SEQ + j0 + tx * 4) = v;
    }
}

// ---------------------------------------------------------------------------
__global__ void __launch_bounds__(256) softmax_kernel(float* __restrict__ Sg)
{
    const size_t row = blockIdx.x;
    float* p = Sg + row * SEQ;
    const int tid = threadIdx.x;

    float v[8];
    float lmax = -1e30f;
#pragma unroll
    for (int i = 0; i < 8; i++) {
        v[i] = p[tid + i * 256];
        lmax = fmaxf(lmax, v[i]);
    }

    __shared__ float red[256];
    red[tid] = lmax;
    __syncthreads();
#pragma unroll
    for (int s = 128; s > 0; s >>= 1) {
        if (tid < s) red[tid] = fmaxf(red[tid], red[tid + s]);
        __syncthreads();
    }
    const float m = red[0];
    __syncthreads();

    float lsum = 0.f;
#pragma unroll
    for (int i = 0; i < 8; i++) {
        v[i] = __expf(v[i] - m);
        lsum += v[i];
    }
    red[tid] = lsum;
    __syncthreads();
#pragma unroll
    for (int s = 128; s > 0; s >>= 1) {
        if (tid < s) red[tid] += red[tid + s];
        __syncthreads();
    }
    const float inv = 1.f / red[0];
#pragma unroll
    for (int i = 0; i < 8; i++) p[tid + i * 256] = v[i] * inv;
}

// ---------------------------------------------------------------------------
__global__ void __launch_bounds__(256) pv_kernel(
    const float* __restrict__ P, const float* __restrict__ V,
    float* __restrict__ Og)
{
    const int i0 = blockIdx.x * 64;
    const int bh = blockIdx.y;
    const float* Pb = P + (size_t)bh * SEQ * SEQ;
    const float* Vb = V + (size_t)bh * SEQ * HEAD_DIM;
    const int tid = threadIdx.x;
    const int tx = tid & 15;
    const int ty = tid >> 4;

    __shared__ float Ps[32][64];
    __shared__ float Vs[32][64];

    float acc[4][4];
#pragma unroll
    for (int i = 0; i < 4; i++)
#pragma unroll
        for (int j = 0; j < 4; j++) acc[i][j] = 0.f;

    const int kmax = i0 + 64;
    for (int k0 = 0; k0 < kmax; k0 += 32) {
#pragma unroll
        for (int r = 0; r < 2; r++) {
            const int idx = tid + r * 256;
            const int row = idx >> 3;
            const int c4 = (idx & 7) * 4;
            float4 pv = *(const float4*)(Pb + (size_t)(i0 + row) * SEQ + k0 + c4);
            Ps[c4 + 0][row] = pv.x; Ps[c4 + 1][row] = pv.y;
            Ps[c4 + 2][row] = pv.z; Ps[c4 + 3][row] = pv.w;
        }
#pragma unroll
        for (int r = 0; r < 2; r++) {
            const int idx = tid + r * 256;
            const int row = idx >> 4;
            const int c4 = (idx & 15) * 4;
            *(float4*)&Vs[row][c4] =
                *(const float4*)(Vb + (size_t)(k0 + row) * HEAD_DIM + c4);
        }
        __syncthreads();
#pragma unroll 8
        for (int k = 0; k < 32; k++) {
            float4 a = *(const float4*)&Ps[k][ty * 4];
            float4 b = *(const float4*)&Vs[k][tx * 4];
            float av[4] = {a.x, a.y, a.z, a.w};
            float bv[4] = {b.x, b.y, b.z, b.w};
#pragma unroll
            for (int i = 0; i < 4; i++)
#pragma unroll
                for (int j = 0; j < 4; j++) acc[i][j] += av[i] * bv[j];
        }
        __syncthreads();
    }

    const int b = bh >> 4;
    const int h = bh & 15;
#pragma unroll
    for (int i = 0; i < 4; i++) {
        const int s = i0 + ty * 4 + i;
        float4 v;
        v.x = acc[i][0]; v.y = acc[i][1]; v.z = acc[i][2]; v.w = acc[i][3];
        *(float4*)(Og + ((size_t)(b * SEQ + s)) * D_MODEL + h * HEAD_DIM + tx * 4) = v;
    }
}

// ---------------------------------------------------------------------------
extern "C" void kernel_launch(void* const* d_in, const int* in_sizes, int n_in,
                              void* d_out, int out_size)
{
    const float* q  = (const float*)d_in[0];
    const float* k  = (const float*)d_in[1];
    const float* v  = (const float*)d_in[2];
    const float* Wq = (const float*)d_in[3];
    const float* bq = (const float*)d_in[4];
    const float* Wk = (const float*)d_in[5];
    const float* bk = (const float*)d_in[6];
    const float* Wv = (const float*)d_in[7];
    const float* bv = (const float*)d_in[8];
    const float* Wo = (const float*)d_in[9];
    const float* bo = (const float*)d_in[10];

    float *Qp, *Kp, *Vp, *Sp, *Ap;
    cudaGetSymbolAddress((void**)&Qp, g_Q);
    cudaGetSymbolAddress((void**)&Kp, g_K);
    cudaGetSymbolAddress((void**)&Vp, g_V);
    cudaGetSymbolAddress((void**)&Sp, g_S);
    cudaGetSymbolAddress((void**)&Ap, g_A);

    __nv_bfloat16 *qh, *ql, *kh, *kl, *vh, *vl, *ah, *al;
    __nv_bfloat16 *wqh, *wql, *wkh, *wkl, *wvh, *wvl, *woh, *wol;
    cudaGetSymbolAddress((void**)&qh, g_qh);  cudaGetSymbolAddress((void**)&ql, g_ql);
    cudaGetSymbolAddress((void**)&kh, g_kh);  cudaGetSymbolAddress((void**)&kl, g_kl);
    cudaGetSymbolAddress((void**)&vh, g_vh);  cudaGetSymbolAddress((void**)&vl, g_vl);
    cudaGetSymbolAddress((void**)&ah, g_ah);  cudaGetSymbolAddress((void**)&al, g_al);
    cudaGetSymbolAddress((void**)&wqh, g_Wqh); cudaGetSymbolAddress((void**)&wql, g_Wql);
    cudaGetSymbolAddress((void**)&wkh, g_Wkh); cudaGetSymbolAddress((void**)&wkl, g_Wkl);
    cudaGetSymbolAddress((void**)&wvh, g_Wvh); cudaGetSymbolAddress((void**)&wvl, g_Wvl);
    cudaGetSymbolAddress((void**)&woh, g_Woh); cudaGetSymbolAddress((void**)&wol, g_Wol);

    // Weight transpose + split
    dim3 gW(32, 32);
    wsplit_kernel<<<gW, 256>>>(Wq, wqh, wql);
    wsplit_kernel<<<gW, 256>>>(Wk, wkh, wkl);
    wsplit_kernel<<<gW, 256>>>(Wv, wvh, wvl);
    wsplit_kernel<<<gW, 256>>>(Wo, woh, wol);

    // Activation splits
    const int n4 = MROWS * D_MODEL / 4;
    split_kernel<<<2048, 256>>>((const float4*)q, (__nv_bfloat162*)qh,
                                (__nv_bfloat162*)ql, n4);
    split_kernel<<<2048, 256>>>((const float4*)k, (__nv_bfloat162*)kh,
                                (__nv_bfloat162*)kl, n4);
    split_kernel<<<2048, 256>>>((const float4*)v, (__nv_bfloat162*)vh,
                                (__nv_bfloat162*)vl, n4);

    // Projections (HMMA mma.sync), writing into [b,h,s,d] layout
    dim3 gG(GN / 128, MROWS / 128);  // (8, 64)
    gemm_mma_kernel<true><<<gG, 256>>>(qh, ql, wqh, wql, bq, Qp);
    gemm_mma_kernel<true><<<gG, 256>>>(kh, kl, wkh, wkl, bk, Kp);
    gemm_mma_kernel<true><<<gG, 256>>>(vh, vl, wvh, wvl, bv, Vp);

    // Attention (unchanged this round)
    scores_kernel<<<dim3(SEQ / 64, SEQ / 64, BH), 256>>>(Qp, Kp, Sp);
    softmax_kernel<<<BH * SEQ, 256>>>(Sp);
    pv_kernel<<<dim3(SEQ / 64, BH), 256>>>(Sp, Vp, Ap);

    // Output projection
    split_kernel<<<2048, 256>>>((const float4*)Ap, (__nv_bfloat162*)ah,
                                (__nv_bfloat162*)al, n4);
    gemm_mma_kernel<false><<<gG, 256>>>(ah, al, woh, wol, bo, (float*)d_out);
}

// round 4
// speedup vs baseline: 2.2394x; 1.6745x over previous
#include <cuda_runtime.h>
#include <cuda_bf16.h>
#include <cstdint>

#define D_MODEL 1024
#define N_HEAD  16
#define HEAD_DIM 64
#define BATCH   4
#define SEQ     2048
#define BH      (BATCH * N_HEAD)          // 64
#define MROWS   (BATCH * SEQ)             // 8192
#define GK      1024
#define GN      1024

// ---------------------------------------------------------------------------
// Scratch (device globals)
// ---------------------------------------------------------------------------
// inputs split to bf16 hi/lo
__device__ __nv_bfloat16 g_qh[MROWS * D_MODEL], g_ql[MROWS * D_MODEL];
__device__ __nv_bfloat16 g_kh[MROWS * D_MODEL], g_kl[MROWS * D_MODEL];
__device__ __nv_bfloat16 g_vh[MROWS * D_MODEL], g_vl[MROWS * D_MODEL];
// projected Q/K/V, bf16 hi/lo, [bh][s][hd] layout
__device__ __nv_bfloat16 g_Qh[BH * SEQ * HEAD_DIM], g_Ql[BH * SEQ * HEAD_DIM];
__device__ __nv_bfloat16 g_Kh[BH * SEQ * HEAD_DIM], g_Kl[BH * SEQ * HEAD_DIM];
__device__ __nv_bfloat16 g_Vh[BH * SEQ * HEAD_DIM], g_Vl[BH * SEQ * HEAD_DIM];
// attention output bf16 hi/lo, [b*s][d_model]
__device__ __nv_bfloat16 g_ah[MROWS * D_MODEL], g_al[MROWS * D_MODEL];
// transposed weights [N][K] bf16 hi/lo
__device__ __nv_bfloat16 g_Wqh[D_MODEL * D_MODEL], g_Wql[D_MODEL * D_MODEL];
__device__ __nv_bfloat16 g_Wkh[D_MODEL * D_MODEL], g_Wkl[D_MODEL * D_MODEL];
__device__ __nv_bfloat16 g_Wvh[D_MODEL * D_MODEL], g_Wvl[D_MODEL * D_MODEL];
__device__ __nv_bfloat16 g_Woh[D_MODEL * D_MODEL], g_Wol[D_MODEL * D_MODEL];

// ---------------------------------------------------------------------------
__device__ __forceinline__ uint32_t smem_u32(const void* p) {
    uint32_t a;
    asm("{ .reg .u64 t; cvta.to.shared.u64 t, %1; cvt.u32.u64 %0, t; }"
        : "=r"(a) : "l"(p));
    return a;
}

#define CP_ASYNC16(dst_u32, src_ptr) \
    asm volatile("cp.async.cg.shared.global [%0], [%1], 16;" \
        :: "r"(dst_u32), "l"(src_ptr))

__device__ __forceinline__ void ldsm_x4(uint32_t* r, uint32_t addr) {
    asm volatile("ldmatrix.sync.aligned.m8n8.x4.shared.b16 {%0,%1,%2,%3}, [%4];"
        : "=r"(r[0]), "=r"(r[1]), "=r"(r[2]), "=r"(r[3]) : "r"(addr));
}

__device__ __forceinline__ void mma16816(float* d, const uint32_t* a,
                                         const uint32_t* b) {
    asm volatile(
        "mma.sync.aligned.m16n8k16.row.col.f32.bf16.bf16.f32 "
        "{%0,%1,%2,%3}, {%4,%5,%6,%7}, {%8,%9}, {%0,%1,%2,%3};"
        : "+f"(d[0]), "+f"(d[1]), "+f"(d[2]), "+f"(d[3])
        : "r"(a[0]), "r"(a[1]), "r"(a[2]), "r"(a[3]), "r"(b[0]), "r"(b[1]));
}

// ---------------------------------------------------------------------------
// HMMA bf16-split GEMM. MODE 0: fp32 out [M][N].  MODE 1: bf16 hi/lo out in
// [b,h,s,d] heads layout.
// ---------------------------------------------------------------------------
#define NSTAGES 96   // 3 split terms * (1024/32)

template <int MODE>
__global__ void __launch_bounds__(256) gemm_mma_kernel(
    const __nv_bfloat16* __restrict__ Ahi, const __nv_bfloat16* __restrict__ Alo,
    const __nv_bfloat16* __restrict__ Bhi, const __nv_bfloat16* __restrict__ Blo,
    const float* __restrict__ bias, float* __restrict__ out,
    __nv_bfloat16* __restrict__ outh, __nv_bfloat16* __restrict__ outl)
{
    __shared__ __nv_bfloat16 As[2][128][40];
    __shared__ __nv_bfloat16 Bs[2][128][40];

    const int tid = threadIdx.x;
    const int wid = tid >> 5;
    const int lane = tid & 31;
    const int m0 = blockIdx.y * 128;
    const int n0 = blockIdx.x * 128;
    const int wm = (wid & 1) * 64;
    const int wn = (wid >> 1) * 32;

    const __nv_bfloat16* Aterm[3] = {Ahi, Ahi, Alo};
    const __nv_bfloat16* Bterm[3] = {Bhi, Blo, Bhi};

    float acc[4][4][4];
#pragma unroll
    for (int i = 0; i < 4; i++)
#pragma unroll
        for (int j = 0; j < 4; j++)
#pragma unroll
            for (int c = 0; c < 4; c++) acc[i][j][c] = 0.f;

    const int ldrow = tid >> 2;
    const int ldcol = (tid & 3) * 8;

    auto issue_load = [&](int stage, int i) {
        const int term = i >> 5;
        const int k0 = (i & 31) << 5;
        const __nv_bfloat16* Ag = Aterm[term];
        const __nv_bfloat16* Bg = Bterm[term];
#pragma unroll
        for (int r = 0; r < 2; r++) {
            const int row = ldrow + r * 64;
            CP_ASYNC16(smem_u32(&As[stage][row][ldcol]),
                       Ag + (size_t)(m0 + row) * GK + k0 + ldcol);
            CP_ASYNC16(smem_u32(&Bs[stage][row][ldcol]),
                       Bg + (size_t)(n0 + row) * GK + k0 + ldcol);
        }
        asm volatile("cp.async.commit_group;" ::: "memory");
    };

    issue_load(0, 0);

    for (int i = 0; i < NSTAGES; i++) {
        const int st = i & 1;
        if (i + 1 < NSTAGES) {
            issue_load(st ^ 1, i + 1);
            asm volatile("cp.async.wait_group 1;" ::: "memory");
        } else {
            asm volatile("cp.async.wait_group 0;" ::: "memory");
        }
        __syncthreads();

#pragma unroll
        for (int ks = 0; ks < 2; ks++) {
            uint32_t af[4][4];
#pragma unroll
            for (int mi = 0; mi < 4; mi++) {
                const uint32_t addr = smem_u32(
                    &As[st][wm + mi * 16 + (lane & 15)][ks * 16 + (lane >> 4) * 8]);
                ldsm_x4(af[mi], addr);
            }
            uint32_t bf[4][2];
#pragma unroll
            for (int njp = 0; njp < 2; njp++) {
                uint32_t r[4];
                const int t = lane >> 3;
                const int nrow = wn + njp * 16 + (t >> 1) * 8 + (lane & 7);
                const int kcol = ks * 16 + (t & 1) * 8;
                ldsm_x4(r, smem_u32(&Bs[st][nrow][kcol]));
                bf[njp * 2 + 0][0] = r[0]; bf[njp * 2 + 0][1] = r[1];
                bf[njp * 2 + 1][0] = r[2]; bf[njp * 2 + 1][1] = r[3];
            }
#pragma unroll
            for (int mi = 0; mi < 4; mi++)
#pragma unroll
                for (int nj = 0; nj < 4; nj++)
                    mma16816(acc[mi][nj], af[mi], bf[nj]);
        }
        __syncthreads();
    }

#pragma unroll
    for (int mi = 0; mi < 4; mi++) {
#pragma unroll
        for (int nj = 0; nj < 4; nj++) {
            const int n = n0 + wn + nj * 8 + (lane & 3) * 2;
            const float b0 = bias[n], b1 = bias[n + 1];
#pragma unroll
            for (int half = 0; half < 2; half++) {
                const int m = m0 + wm + mi * 16 + (lane >> 2) + half * 8;
                const float v0 = acc[mi][nj][half * 2 + 0] + b0;
                const float v1 = acc[mi][nj][half * 2 + 1] + b1;
                if (MODE == 1) {
                    const int b = m >> 11;
                    const int s = m & (SEQ - 1);
                    const int h = n >> 6;
                    const int d = n & 63;
                    const size_t idx =
                        ((((size_t)b * N_HEAD + h) * SEQ) + s) * HEAD_DIM + d;
                    __nv_bfloat162 hv, lv;
                    hv.x = __float2bfloat16(v0);
                    hv.y = __float2bfloat16(v1);
                    lv.x = __float2bfloat16(v0 - __bfloat162float(hv.x));
                    lv.y = __float2bfloat16(v1 - __bfloat162float(hv.y));
                    *(__nv_bfloat162*)&outh[idx] = hv;
                    *(__nv_bfloat162*)&outl[idx] = lv;
                } else {
                    *(float2*)&out[(size_t)m * GN + n] = make_float2(v0, v1);
                }
            }
        }
    }
}

// ---------------------------------------------------------------------------
// Fused flash attention.  grid (SEQ/128, BH), 256 threads (8 warps x 16 rows).
// Q tile 128x64, K/V tiles 64x64 per iteration.  3-term bf16 split on both
// QK^T and PV for ~fp32 precision.  Writes bf16 hi/lo [b*s][d_model].
// ---------------------------------------------------------------------------
#define FPAD 72

__global__ void __launch_bounds__(256) flash_kernel(
    const __nv_bfloat16* __restrict__ Qh, const __nv_bfloat16* __restrict__ Ql,
    const __nv_bfloat16* __restrict__ Kh, const __nv_bfloat16* __restrict__ Kl,
    const __nv_bfloat16* __restrict__ Vh, const __nv_bfloat16* __restrict__ Vl,
    __nv_bfloat16* __restrict__ Oh, __nv_bfloat16* __restrict__ Ol)
{
    extern __shared__ __nv_bfloat16 sm[];
    __nv_bfloat16* sQh = sm;                       // 128*FPAD
    __nv_bfloat16* sQl = sQh + 128 * FPAD;
    __nv_bfloat16* sKh = sQl + 128 * FPAD;         // 64*FPAD
    __nv_bfloat16* sKl = sKh + 64 * FPAD;
    __nv_bfloat16* sVh = sKl + 64 * FPAD;          // [dim][key]
    __nv_bfloat16* sVl = sVh + 64 * FPAD;

    const int tid = threadIdx.x;
    const int wid = tid >> 5;
    const int lane = tid & 31;
    const int i0 = blockIdx.x * 128;
    const int bh = blockIdx.y;
    const size_t base = (size_t)bh * SEQ * HEAD_DIM;

    // load Q tile (128 x 64 bf16 hi/lo), 16B chunks
    for (int c = tid; c < 1024; c += 256) {
        const int row = c >> 3, c8 = (c & 7) * 8;
        *(uint4*)&sQh[row * FPAD + c8] =
            *(const uint4*)&Qh[base + (size_t)(i0 + row) * HEAD_DIM + c8];
        *(uint4*)&sQl[row * FPAD + c8] =
            *(const uint4*)&Ql[base + (size_t)(i0 + row) * HEAD_DIM + c8];
    }

    float oacc[8][4];
#pragma unroll
    for (int nt = 0; nt < 8; nt++)
#pragma unroll
        for (int c = 0; c < 4; c++) oacc[nt][c] = 0.f;
    float mrow[2] = {-1e30f, -1e30f};
    float lrow[2] = {0.f, 0.f};

    const int r0 = lane >> 2;
    const int nIter = i0 / 64 + 2;

    for (int it = 0; it < nIter; it++) {
        const int kk0 = it * 64;
        // K tile 64x64 hi/lo
        for (int c = tid; c < 512; c += 256) {
            const int row = c >> 3, c8 = (c & 7) * 8;
            *(uint4*)&sKh[row * FPAD + c8] =
                *(const uint4*)&Kh[base + (size_t)(kk0 + row) * HEAD_DIM + c8];
            *(uint4*)&sKl[row * FPAD + c8] =
                *(const uint4*)&Kl[base + (size_t)(kk0 + row) * HEAD_DIM + c8];
        }
        // V tile transposed into [dim][key]
        for (int c = tid; c < 512; c += 256) {
            const int key = c >> 3, d8 = (c & 7) * 8;
            uint4 hv = *(const uint4*)&Vh[base + (size_t)(kk0 + key) * HEAD_DIM + d8];
            uint4 lv = *(const uint4*)&Vl[base + (size_t)(kk0 + key) * HEAD_DIM + d8];
            const __nv_bfloat16* hp = (const __nv_bfloat16*)&hv;
            const __nv_bfloat16* lp = (const __nv_bfloat16*)&lv;
#pragma unroll
            for (int d = 0; d < 8; d++) {
                sVh[(d8 + d) * FPAD + key] = hp[d];
                sVl[(d8 + d) * FPAD + key] = lp[d];
            }
        }
        __syncthreads();

        // ---- S = Q K^T (3-term split), 16 rows x 64 keys per warp ----
        float sacc[8][4];
#pragma unroll
        for (int nt = 0; nt < 8; nt++)
#pragma unroll
            for (int c = 0; c < 4; c++) sacc[nt][c] = 0.f;

#pragma unroll
        for (int term = 0; term < 3; term++) {
            const __nv_bfloat16* As_ = (term == 2) ? sQl : sQh;
            const __nv_bfloat16* Bs_ = (term == 1) ? sKl : sKh;
#pragma unroll
            for (int ks = 0; ks < 4; ks++) {
                uint32_t af[4];
                ldsm_x4(af, smem_u32(&As_[(wid * 16 + (lane & 15)) * FPAD +
                                          ks * 16 + (lane >> 4) * 8]));
                uint32_t bfr[8][2];
#pragma unroll
                for (int njp = 0; njp < 4; njp++) {
                    uint32_t r[4];
                    const int t = lane >> 3;
                    const int nrow = njp * 16 + (t >> 1) * 8 + (lane & 7);
                    const int kcol = ks * 16 + (t & 1) * 8;
                    ldsm_x4(r, smem_u32(&Bs_[nrow * FPAD + kcol]));
                    bfr[njp * 2 + 0][0] = r[0]; bfr[njp * 2 + 0][1] = r[1];
                    bfr[njp * 2 + 1][0] = r[2]; bfr[njp * 2 + 1][1] = r[3];
                }
#pragma unroll
                for (int nt = 0; nt < 8; nt++) mma16816(sacc[nt], af, bfr[nt]);
            }
        }

        // ---- scale + causal mask + online softmax ----
        const float scale = 0.03125f;
        const bool domask = (kk0 + 63 > i0 + wid * 16);
        float tmax[2] = {-1e30f, -1e30f};
#pragma unroll
        for (int nt = 0; nt < 8; nt++) {
#pragma unroll
            for (int c = 0; c < 4; c++) {
                float s = sacc[nt][c] * scale;
                if (domask) {
                    const int gi = i0 + wid * 16 + r0 + (c >> 1) * 8;
                    const int gj = kk0 + nt * 8 + (lane & 3) * 2 + (c & 1);
                    if (gj > gi) s = -1e30f;
                }
                sacc[nt][c] = s;
                tmax[c >> 1] = fmaxf(tmax[c >> 1], s);
            }
        }
#pragma unroll
        for (int h2 = 0; h2 < 2; h2++) {
            tmax[h2] = fmaxf(tmax[h2], __shfl_xor_sync(0xffffffffu, tmax[h2], 1));
            tmax[h2] = fmaxf(tmax[h2], __shfl_xor_sync(0xffffffffu, tmax[h2], 2));
        }
        float fac[2], mnew[2];
#pragma unroll
        for (int h2 = 0; h2 < 2; h2++) {
            mnew[h2] = fmaxf(mrow[h2], tmax[h2]);
            fac[h2] = __expf(mrow[h2] - mnew[h2]);
            mrow[h2] = mnew[h2];
            lrow[h2] *= fac[h2];
        }
#pragma unroll
        for (int nt = 0; nt < 8; nt++)
#pragma unroll
            for (int c = 0; c < 4; c++) oacc[nt][c] *= fac[c >> 1];

#pragma unroll
        for (int nt = 0; nt < 8; nt++) {
#pragma unroll
            for (int c = 0; c < 4; c++) {
                const float p = __expf(sacc[nt][c] - mnew[c >> 1]);
                sacc[nt][c] = p;
                lrow[c >> 1] += p;
            }
        }

        // ---- pack P into A fragments (hi/lo) ----
        uint32_t phi[4][4], plo[4][4];
#pragma unroll
        for (int t = 0; t < 4; t++) {
            const float p00 = sacc[2 * t][0],     p01 = sacc[2 * t][1];
            const float p10 = sacc[2 * t][2],     p11 = sacc[2 * t][3];
            const float p20 = sacc[2 * t + 1][0], p21 = sacc[2 * t + 1][1];
            const float p30 = sacc[2 * t + 1][2], p31 = sacc[2 * t + 1][3];
            __nv_bfloat162 h, l;
            h.x = __float2bfloat16(p00); h.y = __float2bfloat16(p01);
            l.x = __float2bfloat16(p00 - __bfloat162float(h.x));
            l.y = __float2bfloat16(p01 - __bfloat162float(h.y));
            phi[t][0] = *(uint32_t*)&h; plo[t][0] = *(uint32_t*)&l;
            h.x = __float2bfloat16(p10); h.y = __float2bfloat16(p11);
            l.x = __float2bfloat16(p10 - __bfloat162float(h.x));
            l.y = __float2bfloat16(p11 - __bfloat162float(h.y));
            phi[t][1] = *(uint32_t*)&h; plo[t][1] = *(uint32_t*)&l;
            h.x = __float2bfloat16(p20); h.y = __float2bfloat16(p21);
            l.x = __float2bfloat16(p20 - __bfloat162float(h.x));
            l.y = __float2bfloat16(p21 - __bfloat162float(h.y));
            phi[t][2] = *(uint32_t*)&h; plo[t][2] = *(uint32_t*)&l;
            h.x = __float2bfloat16(p30); h.y = __float2bfloat16(p31);
            l.x = __float2bfloat16(p30 - __bfloat162float(h.x));
            l.y = __float2bfloat16(p31 - __bfloat162float(h.y));
            phi[t][3] = *(uint32_t*)&h; plo[t][3] = *(uint32_t*)&l;
        }

        // ---- O += P V (3-term split) ----
#pragma unroll
        for (int term = 0; term < 3; term++) {
            const __nv_bfloat16* Vs_ = (term == 1) ? sVl : sVh;
#pragma unroll
            for (int ks = 0; ks < 4; ks++) {
                const uint32_t* afr = (term == 2) ? plo[ks] : phi[ks];
                uint32_t bfr[8][2];
#pragma unroll
                for (int njp = 0; njp < 4; njp++) {
                    uint32_t r[4];
                    const int t = lane >> 3;
                    const int nrow = njp * 16 + (t >> 1) * 8 + (lane & 7);
                    const int kcol = ks * 16 + (t & 1) * 8;
                    ldsm_x4(r, smem_u32(&Vs_[nrow * FPAD + kcol]));
                    bfr[njp * 2 + 0][0] = r[0]; bfr[njp * 2 + 0][1] = r[1];
                    bfr[njp * 2 + 1][0] = r[2]; bfr[njp * 2 + 1][1] = r[3];
                }
#pragma unroll
                for (int nt = 0; nt < 8; nt++) mma16816(oacc[nt], afr, bfr[nt]);
            }
        }
        __syncthreads();
    }

    // ---- finalize: normalize, write bf16 hi/lo to [b*s][d_model] ----
    float inv[2];
#pragma unroll
    for (int h2 = 0; h2 < 2; h2++) {
        float l = lrow[h2];
        l += __shfl_xor_sync(0xffffffffu, l, 1);
        l += __shfl_xor_sync(0xffffffffu, l, 2);
        inv[h2] = 1.f / l;
    }
    const int b = bh >> 4;
    const int h = bh & 15;
#pragma unroll
    for (int nt = 0; nt < 8; nt++) {
#pragma unroll
        for (int half = 0; half < 2; half++) {
            const int gi = i0 + wid * 16 + r0 + half * 8;
            const int d0 = nt * 8 + (lane & 3) * 2;
            const float v0 = oacc[nt][half * 2 + 0] * inv[half];
            const float v1 = oacc[nt][half * 2 + 1] * inv[half];
            const size_t idx = ((size_t)(b * SEQ + gi)) * D_MODEL + h * HEAD_DIM + d0;
            __nv_bfloat162 hv, lv;
            hv.x = __float2bfloat16(v0);
            hv.y = __float2bfloat16(v1);
            lv.x = __float2bfloat16(v0 - __bfloat162float(hv.x));
            lv.y = __float2bfloat16(v1 - __bfloat162float(hv.y));
            *(__nv_bfloat162*)&Oh[idx] = hv;
            *(__nv_bfloat162*)&Ol[idx] = lv;
        }
    }
}

// ---------------------------------------------------------------------------
// fp32 -> bf16 hi/lo split (activations)
// ---------------------------------------------------------------------------
__global__ void __launch_bounds__(256) split_kernel(
    const float4* __restrict__ in, __nv_bfloat162* __restrict__ hi,
    __nv_bfloat162* __restrict__ lo, int n4)
{
    const int stride = gridDim.x * blockDim.x;
    for (int i = blockIdx.x * blockDim.x + threadIdx.x; i < n4; i += stride) {
        float4 v = in[i];
        __nv_bfloat16 hx = __float2bfloat16(v.x);
        __nv_bfloat16 hy = __float2bfloat16(v.y);
        __nv_bfloat16 hz = __float2bfloat16(v.z);
        __nv_bfloat16 hw = __float2bfloat16(v.w);
        __nv_bfloat162 h0; h0.x = hx; h0.y = hy;
        __nv_bfloat162 h1; h1.x = hz; h1.y = hw;
        __nv_bfloat162 l0, l1;
        l0.x = __float2bfloat16(v.x - __bfloat162float(hx));
        l0.y = __float2bfloat16(v.y - __bfloat162float(hy));
        l1.x = __float2bfloat16(v.z - __bfloat162float(hz));
        l1.y = __float2bfloat16(v.w - __bfloat162float(hw));
        hi[i * 2] = h0; hi[i * 2 + 1] = h1;
        lo[i * 2] = l0; lo[i * 2 + 1] = l1;
    }
}

// ---------------------------------------------------------------------------
// W[K,N] -> Wt hi/lo [N,K] bf16 (transpose + split)
// ---------------------------------------------------------------------------
__global__ void __launch_bounds__(256) wsplit_kernel(
    const float* __restrict__ W, __nv_bfloat16* __restrict__ hiT,
    __nv_bfloat16* __restrict__ loT)
{
    __shared__ float t[32][33];
    const int n0 = blockIdx.x * 32, k0 = blockIdx.y * 32;
    const int tx = threadIdx.x & 31, ty = threadIdx.x >> 5;
#pragma unroll
    for (int r = 0; r < 4; r++) {
        const int kl = ty + r * 8;
        t[kl][tx] = W[(size_t)(k0 + kl) * D_MODEL + n0 + tx];
    }
    __syncthreads();
#pragma unroll
    for (int r = 0; r < 4; r++) {
        const int nl = ty + r * 8;
        const float x = t[tx][nl];
        const __nv_bfloat16 h = __float2bfloat16(x);
        hiT[(size_t)(n0 + nl) * D_MODEL + k0 + tx] = h;
        loT[(size_t)(n0 + nl) * D_MODEL + k0 + tx] =
            __float2bfloat16(x - __bfloat162float(h));
    }
}

// ---------------------------------------------------------------------------
extern "C" void kernel_launch(void* const* d_in, const int* in_sizes, int n_in,
                              void* d_out, int out_size)
{
    const float* q  = (const float*)d_in[0];
    const float* k  = (const float*)d_in[1];
    const float* v  = (const float*)d_in[2];
    const float* Wq = (const float*)d_in[3];
    const float* bq = (const float*)d_in[4];
    const float* Wk = (const float*)d_in[5];
    const float* bk = (const float*)d_in[6];
    const float* Wv = (const float*)d_in[7];
    const float* bv = (const float*)d_in[8];
    const float* Wo = (const float*)d_in[9];
    const float* bo = (const float*)d_in[10];

    __nv_bfloat16 *qh, *ql, *kh, *kl, *vh, *vl, *ah, *al;
    __nv_bfloat16 *Qh, *Ql, *Kh, *Kl, *Vh, *Vl;
    __nv_bfloat16 *wqh, *wql, *wkh, *wkl, *wvh, *wvl, *woh, *wol;
    cudaGetSymbolAddress((void**)&qh, g_qh);  cudaGetSymbolAddress((void**)&ql, g_ql);
    cudaGetSymbolAddress((void**)&kh, g_kh);  cudaGetSymbolAddress((void**)&kl, g_kl);
    cudaGetSymbolAddress((void**)&vh, g_vh);  cudaGetSymbolAddress((void**)&vl, g_vl);
    cudaGetSymbolAddress((void**)&ah, g_ah);  cudaGetSymbolAddress((void**)&al, g_al);
    cudaGetSymbolAddress((void**)&Qh, g_Qh);  cudaGetSymbolAddress((void**)&Ql, g_Ql);
    cudaGetSymbolAddress((void**)&Kh, g_Kh);  cudaGetSymbolAddress((void**)&Kl, g_Kl);
    cudaGetSymbolAddress((void**)&Vh, g_Vh);  cudaGetSymbolAddress((void**)&Vl, g_Vl);
    cudaGetSymbolAddress((void**)&wqh, g_Wqh); cudaGetSymbolAddress((void**)&wql, g_Wql);
    cudaGetSymbolAddress((void**)&wkh, g_Wkh); cudaGetSymbolAddress((void**)&wkl, g_Wkl);
    cudaGetSymbolAddress((void**)&wvh, g_Wvh); cudaGetSymbolAddress((void**)&wvl, g_Wvl);
    cudaGetSymbolAddress((void**)&woh, g_Woh); cudaGetSymbolAddress((void**)&wol, g_Wol);

    static bool attr_set = false;
    if (!attr_set) {
        cudaFuncSetAttribute(flash_kernel,
                             cudaFuncAttributeMaxDynamicSharedMemorySize, 73728);
        attr_set = true;
    }

    // Weight transpose + split
    dim3 gW(32, 32);
    wsplit_kernel<<<gW, 256>>>(Wq, wqh, wql);
    wsplit_kernel<<<gW, 256>>>(Wk, wkh, wkl);
    wsplit_kernel<<<gW, 256>>>(Wv, wvh, wvl);
    wsplit_kernel<<<gW, 256>>>(Wo, woh, wol);

    // Activation splits
    const int n4 = MROWS * D_MODEL / 4;
    split_kernel<<<2048, 256>>>((const float4*)q, (__nv_bfloat162*)qh,
                                (__nv_bfloat162*)ql, n4);
    split_kernel<<<2048, 256>>>((const float4*)k, (__nv_bfloat162*)kh,
                                (__nv_bfloat162*)kl, n4);
    split_kernel<<<2048, 256>>>((const float4*)v, (__nv_bfloat162*)vh,
                                (__nv_bfloat162*)vl, n4);

    // Projections -> bf16 hi/lo in heads layout
    dim3 gG(GN / 128, MROWS / 128);  // (8, 64)
    gemm_mma_kernel<1><<<gG, 256>>>(qh, ql, wqh, wql, bq, nullptr, Qh, Ql);
    gemm_mma_kernel<1><<<gG, 256>>>(kh, kl, wkh, wkl, bk, nullptr, Kh, Kl);
    gemm_mma_kernel<1><<<gG, 256>>>(vh, vl, wvh, wvl, bv, nullptr, Vh, Vl);

    // Fused flash attention -> bf16 hi/lo [b*s][d_model]
    flash_kernel<<<dim3(SEQ / 128, BH), 256, 73728>>>(Qh, Ql, Kh, Kl, Vh, Vl,
                                                      ah, al);

    // Output projection -> fp32 d_out
    gemm_mma_kernel<0><<<gG, 256>>>(ah, al, woh, wol, bo, (float*)d_out,
                                    nullptr, nullptr);
}

// round 6
// speedup vs baseline: 2.9201x; 1.3039x over previous
#include <cuda_runtime.h>
#include <cuda_bf16.h>
#include <cstdint>

#define D_MODEL 1024
#define N_HEAD  16
#define HEAD_DIM 64
#define BATCH   4
#define SEQ     2048
#define BH      (BATCH * N_HEAD)          // 64
#define MROWS   (BATCH * SEQ)             // 8192
#define GK      1024
#define GN      1024

// ---------------------------------------------------------------------------
// Scratch (device globals)
// ---------------------------------------------------------------------------
__device__ __nv_bfloat16 g_qh[MROWS * D_MODEL], g_ql[MROWS * D_MODEL];
__device__ __nv_bfloat16 g_kh[MROWS * D_MODEL], g_kl[MROWS * D_MODEL];
__device__ __nv_bfloat16 g_vh[MROWS * D_MODEL], g_vl[MROWS * D_MODEL];
__device__ __nv_bfloat16 g_Qh[BH * SEQ * HEAD_DIM], g_Ql[BH * SEQ * HEAD_DIM];
__device__ __nv_bfloat16 g_Kh[BH * SEQ * HEAD_DIM], g_Kl[BH * SEQ * HEAD_DIM];
__device__ __nv_bfloat16 g_Vh[BH * SEQ * HEAD_DIM], g_Vl[BH * SEQ * HEAD_DIM];
__device__ __nv_bfloat16 g_ah[MROWS * D_MODEL], g_al[MROWS * D_MODEL];
__device__ __nv_bfloat16 g_Wqh[D_MODEL * D_MODEL], g_Wql[D_MODEL * D_MODEL];
__device__ __nv_bfloat16 g_Wkh[D_MODEL * D_MODEL], g_Wkl[D_MODEL * D_MODEL];
__device__ __nv_bfloat16 g_Wvh[D_MODEL * D_MODEL], g_Wvl[D_MODEL * D_MODEL];
__device__ __nv_bfloat16 g_Woh[D_MODEL * D_MODEL], g_Wol[D_MODEL * D_MODEL];

// ---------------------------------------------------------------------------
__device__ __forceinline__ uint32_t smem_u32(const void* p) {
    uint32_t a;
    asm("{ .reg .u64 t; cvta.to.shared.u64 t, %1; cvt.u32.u64 %0, t; }"
        : "=r"(a) : "l"(p));
    return a;
}

#define CP_ASYNC16(dst_u32, src_ptr) \
    asm volatile("cp.async.cg.shared.global [%0], [%1], 16;" \
        :: "r"(dst_u32), "l"(src_ptr))

__device__ __forceinline__ void ldsm_x4(uint32_t* r, uint32_t addr) {
    asm volatile("ldmatrix.sync.aligned.m8n8.x4.shared.b16 {%0,%1,%2,%3}, [%4];"
        : "=r"(r[0]), "=r"(r[1]), "=r"(r[2]), "=r"(r[3]) : "r"(addr));
}

__device__ __forceinline__ void ldsm_x4_t(uint32_t* r, uint32_t addr) {
    asm volatile("ldmatrix.sync.aligned.m8n8.x4.trans.shared.b16 {%0,%1,%2,%3}, [%4];"
        : "=r"(r[0]), "=r"(r[1]), "=r"(r[2]), "=r"(r[3]) : "r"(addr));
}

__device__ __forceinline__ void mma16816(float* d, const uint32_t* a,
                                         const uint32_t* b) {
    asm volatile(
        "mma.sync.aligned.m16n8k16.row.col.f32.bf16.bf16.f32 "
        "{%0,%1,%2,%3}, {%4,%5,%6,%7}, {%8,%9}, {%0,%1,%2,%3};"
        : "+f"(d[0]), "+f"(d[1]), "+f"(d[2]), "+f"(d[3])
        : "r"(a[0]), "r"(a[1]), "r"(a[2]), "r"(a[3]), "r"(b[0]), "r"(b[1]));
}

// ---------------------------------------------------------------------------
// HMMA bf16-split GEMM with fragment reuse across the 3 split terms.
// smem layout (dynamic, 81920 B): Ahi|Alo|Bhi|Blo, each 2 stages x 128 x 40.
// ---------------------------------------------------------------------------
#define NSLABS  32           // 1024 / 32
#define TILE_E  (128 * 40)   // elements per stage tile
#define GSMEM_BYTES (4 * 2 * TILE_E * 2)   // 81920

template <int MODE>
__global__ void __launch_bounds__(256) gemm_mma_kernel(
    const __nv_bfloat16* __restrict__ Ahi, const __nv_bfloat16* __restrict__ Alo,
    const __nv_bfloat16* __restrict__ Bhi, const __nv_bfloat16* __restrict__ Blo,
    const float* __restrict__ bias, float* __restrict__ out,
    __nv_bfloat16* __restrict__ outh, __nv_bfloat16* __restrict__ outl)
{
    extern __shared__ __nv_bfloat16 gsm[];
    __nv_bfloat16* sAh = gsm;                 // [2][128][40]
    __nv_bfloat16* sAl = sAh + 2 * TILE_E;
    __nv_bfloat16* sBh = sAl + 2 * TILE_E;
    __nv_bfloat16* sBl = sBh + 2 * TILE_E;

    const int tid = threadIdx.x;
    const int wid = tid >> 5;
    const int lane = tid & 31;
    const int m0 = blockIdx.y * 128;
    const int n0 = blockIdx.x * 128;
    const int wm = (wid & 1) * 64;
    const int wn = (wid >> 1) * 32;

    float acc[4][4][4];
#pragma unroll
    for (int i = 0; i < 4; i++)
#pragma unroll
        for (int j = 0; j < 4; j++)
#pragma unroll
            for (int c = 0; c < 4; c++) acc[i][j][c] = 0.f;

    const int ldrow = tid >> 2;            // 0..63 (+64)
    const int ldcol = (tid & 3) * 8;       // 0,8,16,24

    auto issue_load = [&](int stage, int slab) {
        const int k0 = slab << 5;
        const int so = stage * TILE_E;
#pragma unroll
        for (int r = 0; r < 2; r++) {
            const int row = ldrow + r * 64;
            const size_t ga = (size_t)(m0 + row) * GK + k0 + ldcol;
            const size_t gb = (size_t)(n0 + row) * GK + k0 + ldcol;
            const int sof = so + row * 40 + ldcol;
            CP_ASYNC16(smem_u32(&sAh[sof]), Ahi + ga);
            CP_ASYNC16(smem_u32(&sAl[sof]), Alo + ga);
            CP_ASYNC16(smem_u32(&sBh[sof]), Bhi + gb);
            CP_ASYNC16(smem_u32(&sBl[sof]), Blo + gb);
        }
        asm volatile("cp.async.commit_group;" ::: "memory");
    };

    issue_load(0, 0);

    for (int i = 0; i < NSLABS; i++) {
        const int st = i & 1;
        if (i + 1 < NSLABS) {
            issue_load(st ^ 1, i + 1);
            asm volatile("cp.async.wait_group 1;" ::: "memory");
        } else {
            asm volatile("cp.async.wait_group 0;" ::: "memory");
        }
        __syncthreads();
        const int so = st * TILE_E;

#pragma unroll
        for (int ks = 0; ks < 2; ks++) {
            uint32_t afh[4][4], afl[4][4];
#pragma unroll
            for (int mi = 0; mi < 4; mi++) {
                const int sof = so + (wm + mi * 16 + (lane & 15)) * 40 +
                                ks * 16 + (lane >> 4) * 8;
                ldsm_x4(afh[mi], smem_u32(&sAh[sof]));
                ldsm_x4(afl[mi], smem_u32(&sAl[sof]));
            }
            uint32_t bfh[4][2], bfl[4][2];
#pragma unroll
            for (int njp = 0; njp < 2; njp++) {
                const int t = lane >> 3;
                const int sof = so + (wn + njp * 16 + (t >> 1) * 8 + (lane & 7)) * 40 +
                                ks * 16 + (t & 1) * 8;
                uint32_t r[4];
                ldsm_x4(r, smem_u32(&sBh[sof]));
                bfh[njp * 2 + 0][0] = r[0]; bfh[njp * 2 + 0][1] = r[1];
                bfh[njp * 2 + 1][0] = r[2]; bfh[njp * 2 + 1][1] = r[3];
                ldsm_x4(r, smem_u32(&sBl[sof]));
                bfl[njp * 2 + 0][0] = r[0]; bfl[njp * 2 + 0][1] = r[1];
                bfl[njp * 2 + 1][0] = r[2]; bfl[njp * 2 + 1][1] = r[3];
            }
#pragma unroll
            for (int mi = 0; mi < 4; mi++)
#pragma unroll
                for (int nj = 0; nj < 4; nj++) {
                    mma16816(acc[mi][nj], afh[mi], bfh[nj]);
                    mma16816(acc[mi][nj], afh[mi], bfl[nj]);
                    mma16816(acc[mi][nj], afl[mi], bfh[nj]);
                }
        }
        __syncthreads();
    }

#pragma unroll
    for (int mi = 0; mi < 4; mi++) {
#pragma unroll
        for (int nj = 0; nj < 4; nj++) {
            const int n = n0 + wn + nj * 8 + (lane & 3) * 2;
            const float b0 = bias[n], b1 = bias[n + 1];
#pragma unroll
            for (int half = 0; half < 2; half++) {
                const int m = m0 + wm + mi * 16 + (lane >> 2) + half * 8;
                const float v0 = acc[mi][nj][half * 2 + 0] + b0;
                const float v1 = acc[mi][nj][half * 2 + 1] + b1;
                if (MODE == 1) {
                    const int b = m >> 11;
                    const int s = m & (SEQ - 1);
                    const int h = n >> 6;
                    const int d = n & 63;
                    const size_t idx =
                        ((((size_t)b * N_HEAD + h) * SEQ) + s) * HEAD_DIM + d;
                    __nv_bfloat162 hv, lv;
                    hv.x = __float2bfloat16(v0);
                    hv.y = __float2bfloat16(v1);
                    lv.x = __float2bfloat16(v0 - __bfloat162float(hv.x));
                    lv.y = __float2bfloat16(v1 - __bfloat162float(hv.y));
                    *(__nv_bfloat162*)&outh[idx] = hv;
                    *(__nv_bfloat162*)&outl[idx] = lv;
                } else {
                    *(float2*)&out[(size_t)m * GN + n] = make_float2(v0, v1);
                }
            }
        }
    }
}

// ---------------------------------------------------------------------------
// Fused flash attention.  grid (SEQ/128, BH), 256 threads (8 warps x 16 rows).
// V kept in [key][dim] rows; PV B-fragments via ldmatrix.trans.
// ---------------------------------------------------------------------------
#define FPAD 72
#define FLASH_SMEM ((128 * FPAD * 2 + 64 * FPAD * 4) * 2)   // 73728

__global__ void __launch_bounds__(256) flash_kernel(
    const __nv_bfloat16* __restrict__ Qh, const __nv_bfloat16* __restrict__ Ql,
    const __nv_bfloat16* __restrict__ Kh, const __nv_bfloat16* __restrict__ Kl,
    const __nv_bfloat16* __restrict__ Vh, const __nv_bfloat16* __restrict__ Vl,
    __nv_bfloat16* __restrict__ Oh, __nv_bfloat16* __restrict__ Ol)
{
    extern __shared__ __nv_bfloat16 sm[];
    __nv_bfloat16* sQh = sm;                       // 128*FPAD
    __nv_bfloat16* sQl = sQh + 128 * FPAD;
    __nv_bfloat16* sKh = sQl + 128 * FPAD;         // 64*FPAD
    __nv_bfloat16* sKl = sKh + 64 * FPAD;
    __nv_bfloat16* sVh = sKl + 64 * FPAD;          // [key][dim]
    __nv_bfloat16* sVl = sVh + 64 * FPAD;

    const int tid = threadIdx.x;
    const int wid = tid >> 5;
    const int lane = tid & 31;
    const int i0 = blockIdx.x * 128;
    const int bh = blockIdx.y;
    const size_t base = (size_t)bh * SEQ * HEAD_DIM;

    for (int c = tid; c < 1024; c += 256) {
        const int row = c >> 3, c8 = (c & 7) * 8;
        *(uint4*)&sQh[row * FPAD + c8] =
            *(const uint4*)&Qh[base + (size_t)(i0 + row) * HEAD_DIM + c8];
        *(uint4*)&sQl[row * FPAD + c8] =
            *(const uint4*)&Ql[base + (size_t)(i0 + row) * HEAD_DIM + c8];
    }

    float oacc[8][4];
#pragma unroll
    for (int nt = 0; nt < 8; nt++)
#pragma unroll
        for (int c = 0; c < 4; c++) oacc[nt][c] = 0.f;
    float mrow[2] = {-1e30f, -1e30f};
    float lrow[2] = {0.f, 0.f};

    const int r0 = lane >> 2;
    const int nIter = i0 / 64 + 2;

    for (int it = 0; it < nIter; it++) {
        const int kk0 = it * 64;
        for (int c = tid; c < 512; c += 256) {
            const int row = c >> 3, c8 = (c & 7) * 8;
            *(uint4*)&sKh[row * FPAD + c8] =
                *(const uint4*)&Kh[base + (size_t)(kk0 + row) * HEAD_DIM + c8];
            *(uint4*)&sKl[row * FPAD + c8] =
                *(const uint4*)&Kl[base + (size_t)(kk0 + row) * HEAD_DIM + c8];
            *(uint4*)&sVh[row * FPAD + c8] =
                *(const uint4*)&Vh[base + (size_t)(kk0 + row) * HEAD_DIM + c8];
            *(uint4*)&sVl[row * FPAD + c8] =
                *(const uint4*)&Vl[base + (size_t)(kk0 + row) * HEAD_DIM + c8];
        }
        __syncthreads();

        // ---- S = Q K^T (3-term split) ----
        float sacc[8][4];
#pragma unroll
        for (int nt = 0; nt < 8; nt++)
#pragma unroll
            for (int c = 0; c < 4; c++) sacc[nt][c] = 0.f;

#pragma unroll
        for (int ks = 0; ks < 4; ks++) {
            uint32_t afh[4], afl[4];
            const int qof = (wid * 16 + (lane & 15)) * FPAD + ks * 16 + (lane >> 4) * 8;
            ldsm_x4(afh, smem_u32(&sQh[qof]));
            ldsm_x4(afl, smem_u32(&sQl[qof]));
            uint32_t bfh[8][2], bfl[8][2];
#pragma unroll
            for (int njp = 0; njp < 4; njp++) {
                const int t = lane >> 3;
                const int kof = (njp * 16 + (t >> 1) * 8 + (lane & 7)) * FPAD +
                                ks * 16 + (t & 1) * 8;
                uint32_t r[4];
                ldsm_x4(r, smem_u32(&sKh[kof]));
                bfh[njp * 2 + 0][0] = r[0]; bfh[njp * 2 + 0][1] = r[1];
                bfh[njp * 2 + 1][0] = r[2]; bfh[njp * 2 + 1][1] = r[3];
                ldsm_x4(r, smem_u32(&sKl[kof]));
                bfl[njp * 2 + 0][0] = r[0]; bfl[njp * 2 + 0][1] = r[1];
                bfl[njp * 2 + 1][0] = r[2]; bfl[njp * 2 + 1][1] = r[3];
            }
#pragma unroll
            for (int nt = 0; nt < 8; nt++) {
                mma16816(sacc[nt], afh, bfh[nt]);
                mma16816(sacc[nt], afh, bfl[nt]);
                mma16816(sacc[nt], afl, bfh[nt]);
            }
        }

        // ---- scale + causal mask + online softmax ----
        const float scale = 0.03125f;
        const bool domask = (kk0 + 63 > i0 + wid * 16);
        float tmax[2] = {-1e30f, -1e30f};
#pragma unroll
        for (int nt = 0; nt < 8; nt++) {
#pragma unroll
            for (int c = 0; c < 4; c++) {
                float s = sacc[nt][c] * scale;
                if (domask) {
                    const int gi = i0 + wid * 16 + r0 + (c >> 1) * 8;
                    const int gj = kk0 + nt * 8 + (lane & 3) * 2 + (c & 1);
                    if (gj > gi) s = -1e30f;
                }
                sacc[nt][c] = s;
                tmax[c >> 1] = fmaxf(tmax[c >> 1], s);
            }
        }
#pragma unroll
        for (int h2 = 0; h2 < 2; h2++) {
            tmax[h2] = fmaxf(tmax[h2], __shfl_xor_sync(0xffffffffu, tmax[h2], 1));
            tmax[h2] = fmaxf(tmax[h2], __shfl_xor_sync(0xffffffffu, tmax[h2], 2));
        }
        float fac[2], mnew[2];
#pragma unroll
        for (int h2 = 0; h2 < 2; h2++) {
            mnew[h2] = fmaxf(mrow[h2], tmax[h2]);
            fac[h2] = __expf(mrow[h2] - mnew[h2]);
            mrow[h2] = mnew[h2];
            lrow[h2] *= fac[h2];
        }
#pragma unroll
        for (int nt = 0; nt < 8; nt++)
#pragma unroll
            for (int c = 0; c < 4; c++) oacc[nt][c] *= fac[c >> 1];

#pragma unroll
        for (int nt = 0; nt < 8; nt++) {
#pragma unroll
            for (int c = 0; c < 4; c++) {
                const float p = __expf(sacc[nt][c] - mnew[c >> 1]);
                sacc[nt][c] = p;
                lrow[c >> 1] += p;
            }
        }

        // ---- pack P into A fragments (hi/lo) ----
        // A-fragment order: a0=(m0-7,k0-7) a1=(m8-15,k0-7) a2=(m0-7,k8-15) a3=(m8-15,k8-15)
        // sacc[2t] holds keys 0-7 (c0,c1 = m0-7; c2,c3 = m8-15); sacc[2t+1] keys 8-15.
        uint32_t phi[4][4], plo[4][4];
#pragma unroll
        for (int t = 0; t < 4; t++) {
#pragma unroll
            for (int q = 0; q < 4; q++) {
                const float pa = sacc[2 * t + (q >> 1)][(q & 1) * 2 + 0];
                const float pb = sacc[2 * t + (q >> 1)][(q & 1) * 2 + 1];
                __nv_bfloat162 h, l;
                h.x = __float2bfloat16(pa); h.y = __float2bfloat16(pb);
                l.x = __float2bfloat16(pa - __bfloat162float(h.x));
                l.y = __float2bfloat16(pb - __bfloat162float(h.y));
                // q = (sacc_sel<<1)|half maps directly to fragment slot:
                // q0->a0 (keys0-7,m0-7), q1->a1 (keys0-7,m8-15),
                // q2->a2 (keys8-15,m0-7), q3->a3 (keys8-15,m8-15)
                phi[t][q] = *(uint32_t*)&h;
                plo[t][q] = *(uint32_t*)&l;
            }
        }

        // ---- O += P V (3-term split), V via ldmatrix.trans ----
#pragma unroll
        for (int ks = 0; ks < 4; ks++) {
            uint32_t bfh[8][2], bfl[8][2];
#pragma unroll
            for (int njp = 0; njp < 4; njp++) {
                const int t = lane >> 3;
                const int vof = (ks * 16 + (t & 1) * 8 + (lane & 7)) * FPAD +
                                njp * 16 + (t >> 1) * 8;
                uint32_t r[4];
                ldsm_x4_t(r, smem_u32(&sVh[vof]));
                bfh[njp * 2 + 0][0] = r[0]; bfh[njp * 2 + 0][1] = r[1];
                bfh[njp * 2 + 1][0] = r[2]; bfh[njp * 2 + 1][1] = r[3];
                ldsm_x4_t(r, smem_u32(&sVl[vof]));
                bfl[njp * 2 + 0][0] = r[0]; bfl[njp * 2 + 0][1] = r[1];
                bfl[njp * 2 + 1][0] = r[2]; bfl[njp * 2 + 1][1] = r[3];
            }
#pragma unroll
            for (int nt = 0; nt < 8; nt++) {
                mma16816(oacc[nt], phi[ks], bfh[nt]);
                mma16816(oacc[nt], phi[ks], bfl[nt]);
                mma16816(oacc[nt], plo[ks], bfh[nt]);
            }
        }
        __syncthreads();
    }

    // ---- finalize ----
    float inv[2];
#pragma unroll
    for (int h2 = 0; h2 < 2; h2++) {
        float l = lrow[h2];
        l += __shfl_xor_sync(0xffffffffu, l, 1);
        l += __shfl_xor_sync(0xffffffffu, l, 2);
        inv[h2] = 1.f / l;
    }
    const int b = bh >> 4;
    const int h = bh & 15;
#pragma unroll
    for (int nt = 0; nt < 8; nt++) {
#pragma unroll
        for (int half = 0; half < 2; half++) {
            const int gi = i0 + wid * 16 + r0 + half * 8;
            const int d0 = nt * 8 + (lane & 3) * 2;
            const float v0 = oacc[nt][half * 2 + 0] * inv[half];
            const float v1 = oacc[nt][half * 2 + 1] * inv[half];
            const size_t idx = ((size_t)(b * SEQ + gi)) * D_MODEL + h * HEAD_DIM + d0;
            __nv_bfloat162 hv, lv;
            hv.x = __float2bfloat16(v0);
            hv.y = __float2bfloat16(v1);
            lv.x = __float2bfloat16(v0 - __bfloat162float(hv.x));
            lv.y = __float2bfloat16(v1 - __bfloat162float(hv.y));
            *(__nv_bfloat162*)&Oh[idx] = hv;
            *(__nv_bfloat162*)&Ol[idx] = lv;
        }
    }
}

// ---------------------------------------------------------------------------
__global__ void __launch_bounds__(256) split_kernel(
    const float4* __restrict__ in, __nv_bfloat162* __restrict__ hi,
    __nv_bfloat162* __restrict__ lo, int n4)
{
    const int stride = gridDim.x * blockDim.x;
    for (int i = blockIdx.x * blockDim.x + threadIdx.x; i < n4; i += stride) {
        float4 v = in[i];
        __nv_bfloat16 hx = __float2bfloat16(v.x);
        __nv_bfloat16 hy = __float2bfloat16(v.y);
        __nv_bfloat16 hz = __float2bfloat16(v.z);
        __nv_bfloat16 hw = __float2bfloat16(v.w);
        __nv_bfloat162 h0; h0.x = hx; h0.y = hy;
        __nv_bfloat162 h1; h1.x = hz; h1.y = hw;
        __nv_bfloat162 l0, l1;
        l0.x = __float2bfloat16(v.x - __bfloat162float(hx));
        l0.y = __float2bfloat16(v.y - __bfloat162float(hy));
        l1.x = __float2bfloat16(v.z - __bfloat162float(hz));
        l1.y = __float2bfloat16(v.w - __bfloat162float(hw));
        hi[i * 2] = h0; hi[i * 2 + 1] = h1;
        lo[i * 2] = l0; lo[i * 2 + 1] = l1;
    }
}

__global__ void __launch_bounds__(256) wsplit_kernel(
    const float* __restrict__ W, __nv_bfloat16* __restrict__ hiT,
    __nv_bfloat16* __restrict__ loT)
{
    __shared__ float t[32][33];
    const int n0 = blockIdx.x * 32, k0 = blockIdx.y * 32;
    const int tx = threadIdx.x & 31, ty = threadIdx.x >> 5;
#pragma unroll
    for (int r = 0; r < 4; r++) {
        const int kl = ty + r * 8;
        t[kl][tx] = W[(size_t)(k0 + kl) * D_MODEL + n0 + tx];
    }
    __syncthreads();
#pragma unroll
    for (int r = 0; r < 4; r++) {
        const int nl = ty + r * 8;
        const float x = t[tx][nl];
        const __nv_bfloat16 h = __float2bfloat16(x);
        hiT[(size_t)(n0 + nl) * D_MODEL + k0 + tx] = h;
        loT[(size_t)(n0 + nl) * D_MODEL + k0 + tx] =
            __float2bfloat16(x - __bfloat162float(h));
    }
}

// ---------------------------------------------------------------------------
extern "C" void kernel_launch(void* const* d_in, const int* in_sizes, int n_in,
                              void* d_out, int out_size)
{
    const float* q  = (const float*)d_in[0];
    const float* k  = (const float*)d_in[1];
    const float* v  = (const float*)d_in[2];
    const float* Wq = (const float*)d_in[3];
    const float* bq = (const float*)d_in[4];
    const float* Wk = (const float*)d_in[5];
    const float* bk = (const float*)d_in[6];
    const float* Wv = (const float*)d_in[7];
    const float* bv = (const float*)d_in[8];
    const float* Wo = (const float*)d_in[9];
    const float* bo = (const float*)d_in[10];

    __nv_bfloat16 *qh, *ql, *kh, *kl, *vh, *vl, *ah, *al;
    __nv_bfloat16 *Qh, *Ql, *Kh, *Kl, *Vh, *Vl;
    __nv_bfloat16 *wqh, *wql, *wkh, *wkl, *wvh, *wvl, *woh, *wol;
    cudaGetSymbolAddress((void**)&qh, g_qh);  cudaGetSymbolAddress((void**)&ql, g_ql);
    cudaGetSymbolAddress((void**)&kh, g_kh);  cudaGetSymbolAddress((void**)&kl, g_kl);
    cudaGetSymbolAddress((void**)&vh, g_vh);  cudaGetSymbolAddress((void**)&vl, g_vl);
    cudaGetSymbolAddress((void**)&ah, g_ah);  cudaGetSymbolAddress((void**)&al, g_al);
    cudaGetSymbolAddress((void**)&Qh, g_Qh);  cudaGetSymbolAddress((void**)&Ql, g_Ql);
    cudaGetSymbolAddress((void**)&Kh, g_Kh);  cudaGetSymbolAddress((void**)&Kl, g_Kl);
    cudaGetSymbolAddress((void**)&Vh, g_Vh);  cudaGetSymbolAddress((void**)&Vl, g_Vl);
    cudaGetSymbolAddress((void**)&wqh, g_Wqh); cudaGetSymbolAddress((void**)&wql, g_Wql);
    cudaGetSymbolAddress((void**)&wkh, g_Wkh); cudaGetSymbolAddress((void**)&wkl, g_Wkl);
    cudaGetSymbolAddress((void**)&wvh, g_Wvh); cudaGetSymbolAddress((void**)&wvl, g_Wvl);
    cudaGetSymbolAddress((void**)&woh, g_Woh); cudaGetSymbolAddress((void**)&wol, g_Wol);

    cudaFuncSetAttribute(flash_kernel,
                         cudaFuncAttributeMaxDynamicSharedMemorySize, FLASH_SMEM);
    cudaFuncSetAttribute(gemm_mma_kernel<0>,
                         cudaFuncAttributeMaxDynamicSharedMemorySize, GSMEM_BYTES);
    cudaFuncSetAttribute(gemm_mma_kernel<1>,
                         cudaFuncAttributeMaxDynamicSharedMemorySize, GSMEM_BYTES);

    dim3 gW(32, 32);
    wsplit_kernel<<<gW, 256>>>(Wq, wqh, wql);
    wsplit_kernel<<<gW, 256>>>(Wk, wkh, wkl);
    wsplit_kernel<<<gW, 256>>>(Wv, wvh, wvl);
    wsplit_kernel<<<gW, 256>>>(Wo, woh, wol);

    const int n4 = MROWS * D_MODEL / 4;
    split_kernel<<<2048, 256>>>((const float4*)q, (__nv_bfloat162*)qh,
                                (__nv_bfloat162*)ql, n4);
    split_kernel<<<2048, 256>>>((const float4*)k, (__nv_bfloat162*)kh,
                                (__nv_bfloat162*)kl, n4);
    split_kernel<<<2048, 256>>>((const float4*)v, (__nv_bfloat162*)vh,
                                (__nv_bfloat162*)vl, n4);

    dim3 gG(GN / 128, MROWS / 128);  // (8, 64)
    gemm_mma_kernel<1><<<gG, 256, GSMEM_BYTES>>>(qh, ql, wqh, wql, bq, nullptr, Qh, Ql);
    gemm_mma_kernel<1><<<gG, 256, GSMEM_BYTES>>>(kh, kl, wkh, wkl, bk, nullptr, Kh, Kl);
    gemm_mma_kernel<1><<<gG, 256, GSMEM_BYTES>>>(vh, vl, wvh, wvl, bv, nullptr, Vh, Vl);

    flash_kernel<<<dim3(SEQ / 128, BH), 256, FLASH_SMEM>>>(Qh, Ql, Kh, Kl, Vh, Vl,
                                                           ah, al);

    gemm_mma_kernel<0><<<gG, 256, GSMEM_BYTES>>>(ah, al, woh, wol, bo,
                                                 (float*)d_out, nullptr, nullptr);
}

// round 7
// speedup vs baseline: 3.0904x; 1.0583x over previous
#include <cuda_runtime.h>
#include <cuda_bf16.h>
#include <cstdint>

#define D_MODEL 1024
#define N_HEAD  16
#define HEAD_DIM 64
#define BATCH   4
#define SEQ     2048
#define BH      (BATCH * N_HEAD)          // 64
#define MROWS   (BATCH * SEQ)             // 8192
#define GK      1024
#define GN      1024

// ---------------------------------------------------------------------------
// Scratch (device globals)
// ---------------------------------------------------------------------------
__device__ __nv_bfloat16 g_qh[MROWS * D_MODEL], g_ql[MROWS * D_MODEL];
__device__ __nv_bfloat16 g_kh[MROWS * D_MODEL], g_kl[MROWS * D_MODEL];
__device__ __nv_bfloat16 g_vh[MROWS * D_MODEL], g_vl[MROWS * D_MODEL];
__device__ __nv_bfloat16 g_Qh[BH * SEQ * HEAD_DIM], g_Ql[BH * SEQ * HEAD_DIM];
__device__ __nv_bfloat16 g_Kh[BH * SEQ * HEAD_DIM], g_Kl[BH * SEQ * HEAD_DIM];
__device__ __nv_bfloat16 g_Vh[BH * SEQ * HEAD_DIM], g_Vl[BH * SEQ * HEAD_DIM];
__device__ __nv_bfloat16 g_ah[MROWS * D_MODEL], g_al[MROWS * D_MODEL];
__device__ __nv_bfloat16 g_Wqh[D_MODEL * D_MODEL], g_Wql[D_MODEL * D_MODEL];
__device__ __nv_bfloat16 g_Wkh[D_MODEL * D_MODEL], g_Wkl[D_MODEL * D_MODEL];
__device__ __nv_bfloat16 g_Wvh[D_MODEL * D_MODEL], g_Wvl[D_MODEL * D_MODEL];
__device__ __nv_bfloat16 g_Woh[D_MODEL * D_MODEL], g_Wol[D_MODEL * D_MODEL];

// ---------------------------------------------------------------------------
__device__ __forceinline__ uint32_t smem_u32(const void* p) {
    uint32_t a;
    asm("{ .reg .u64 t; cvta.to.shared.u64 t, %1; cvt.u32.u64 %0, t; }"
        : "=r"(a) : "l"(p));
    return a;
}

#define CP_ASYNC16(dst_u32, src_ptr) \
    asm volatile("cp.async.cg.shared.global [%0], [%1], 16;" \
        :: "r"(dst_u32), "l"(src_ptr))

__device__ __forceinline__ void ldsm_x4(uint32_t* r, uint32_t addr) {
    asm volatile("ldmatrix.sync.aligned.m8n8.x4.shared.b16 {%0,%1,%2,%3}, [%4];"
        : "=r"(r[0]), "=r"(r[1]), "=r"(r[2]), "=r"(r[3]) : "r"(addr));
}

__device__ __forceinline__ void ldsm_x4_t(uint32_t* r, uint32_t addr) {
    asm volatile("ldmatrix.sync.aligned.m8n8.x4.trans.shared.b16 {%0,%1,%2,%3}, [%4];"
        : "=r"(r[0]), "=r"(r[1]), "=r"(r[2]), "=r"(r[3]) : "r"(addr));
}

__device__ __forceinline__ void mma16816(float* d, const uint32_t* a,
                                         const uint32_t* b) {
    asm volatile(
        "mma.sync.aligned.m16n8k16.row.col.f32.bf16.bf16.f32 "
        "{%0,%1,%2,%3}, {%4,%5,%6,%7}, {%8,%9}, {%0,%1,%2,%3};"
        : "+f"(d[0]), "+f"(d[1]), "+f"(d[2]), "+f"(d[3])
        : "r"(a[0]), "r"(a[1]), "r"(a[2]), "r"(a[3]), "r"(b[0]), "r"(b[1]));
}

// ---------------------------------------------------------------------------
// HMMA bf16-split GEMM, 512 threads (16 warps), BM=128 BN=256 BK=32.
// Fragment reuse across the 3 split terms.  gridDim.z selects the projection
// (fused QKV).  MODE 1: bf16 hi/lo out in heads layout.  MODE 0: fp32 out.
// smem: Ah|Al (2 stages x 128 x 40) + Bh|Bl (2 stages x 256 x 40) = 122880 B.
// ---------------------------------------------------------------------------
#define NSLABS  32            // 1024 / 32
#define A_ST    (128 * 40)
#define B_ST    (256 * 40)
#define G2_SMEM ((2 * A_ST + 2 * B_ST) * 2 * 2)   // 122880

template <int MODE>
__global__ void __launch_bounds__(512) gemm_mma_kernel(
    const __nv_bfloat16* __restrict__ A0h, const __nv_bfloat16* __restrict__ A0l,
    const __nv_bfloat16* __restrict__ A1h, const __nv_bfloat16* __restrict__ A1l,
    const __nv_bfloat16* __restrict__ A2h, const __nv_bfloat16* __restrict__ A2l,
    const __nv_bfloat16* __restrict__ B0h, const __nv_bfloat16* __restrict__ B0l,
    const __nv_bfloat16* __restrict__ B1h, const __nv_bfloat16* __restrict__ B1l,
    const __nv_bfloat16* __restrict__ B2h, const __nv_bfloat16* __restrict__ B2l,
    const float* __restrict__ bias0, const float* __restrict__ bias1,
    const float* __restrict__ bias2,
    __nv_bfloat16* __restrict__ O0h, __nv_bfloat16* __restrict__ O0l,
    __nv_bfloat16* __restrict__ O1h, __nv_bfloat16* __restrict__ O1l,
    __nv_bfloat16* __restrict__ O2h, __nv_bfloat16* __restrict__ O2l,
    float* __restrict__ out32)
{
    extern __shared__ __nv_bfloat16 gsm[];
    __nv_bfloat16* sAh = gsm;                  // [2][128][40]
    __nv_bfloat16* sAl = sAh + 2 * A_ST;
    __nv_bfloat16* sBh = sAl + 2 * A_ST;       // [2][256][40]
    __nv_bfloat16* sBl = sBh + 2 * B_ST;

    const int z = blockIdx.z;
    const __nv_bfloat16* Ahi = (z == 0) ? A0h : (z == 1) ? A1h : A2h;
    const __nv_bfloat16* Alo = (z == 0) ? A0l : (z == 1) ? A1l : A2l;
    const __nv_bfloat16* Bhi = (z == 0) ? B0h : (z == 1) ? B1h : B2h;
    const __nv_bfloat16* Blo = (z == 0) ? B0l : (z == 1) ? B1l : B2l;
    const float* bias = (z == 0) ? bias0 : (z == 1) ? bias1 : bias2;
    __nv_bfloat16* outh = (z == 0) ? O0h : (z == 1) ? O1h : O2h;
    __nv_bfloat16* outl = (z == 0) ? O0l : (z == 1) ? O1l : O2l;

    const int tid = threadIdx.x;
    const int wid = tid >> 5;
    const int lane = tid & 31;
    const int m0 = blockIdx.y * 128;
    const int n0 = blockIdx.x * 256;
    const int wm = (wid & 1) * 64;       // 2 m-warps
    const int wn = (wid >> 1) * 32;      // 8 n-warps -> 256

    float acc[4][4][4];
#pragma unroll
    for (int i = 0; i < 4; i++)
#pragma unroll
        for (int j = 0; j < 4; j++)
#pragma unroll
            for (int c = 0; c < 4; c++) acc[i][j][c] = 0.f;

    const int ldrow = tid >> 2;            // 0..127
    const int ldcol = (tid & 3) * 8;       // 0,8,16,24

    auto issue_load = [&](int stage, int slab) {
        const int k0 = slab << 5;
        // A: 128 rows, one 16B chunk per thread per array
        {
            const size_t ga = (size_t)(m0 + ldrow) * GK + k0 + ldcol;
            const int sof = stage * A_ST + ldrow * 40 + ldcol;
            CP_ASYNC16(smem_u32(&sAh[sof]), Ahi + ga);
            CP_ASYNC16(smem_u32(&sAl[sof]), Alo + ga);
        }
        // B: 256 rows, two chunks per thread per array
#pragma unroll
        for (int r = 0; r < 2; r++) {
            const int row = ldrow + r * 128;
            const size_t gb = (size_t)(n0 + row) * GK + k0 + ldcol;
            const int sof = stage * B_ST + row * 40 + ldcol;
            CP_ASYNC16(smem_u32(&sBh[sof]), Bhi + gb);
            CP_ASYNC16(smem_u32(&sBl[sof]), Blo + gb);
        }
        asm volatile("cp.async.commit_group;" ::: "memory");
    };

    issue_load(0, 0);

    for (int i = 0; i < NSLABS; i++) {
        const int st = i & 1;
        if (i + 1 < NSLABS) {
            issue_load(st ^ 1, i + 1);
            asm volatile("cp.async.wait_group 1;" ::: "memory");
        } else {
            asm volatile("cp.async.wait_group 0;" ::: "memory");
        }
        __syncthreads();

#pragma unroll
        for (int ks = 0; ks < 2; ks++) {
            // B fragments for this warp's 32 columns
            uint32_t bfh[4][2], bfl[4][2];
#pragma unroll
            for (int njp = 0; njp < 2; njp++) {
                const int t = lane >> 3;
                const int sof = st * B_ST +
                                (wn + njp * 16 + (t >> 1) * 8 + (lane & 7)) * 40 +
                                ks * 16 + (t & 1) * 8;
                uint32_t r[4];
                ldsm_x4(r, smem_u32(&sBh[sof]));
                bfh[njp * 2 + 0][0] = r[0]; bfh[njp * 2 + 0][1] = r[1];
                bfh[njp * 2 + 1][0] = r[2]; bfh[njp * 2 + 1][1] = r[3];
                ldsm_x4(r, smem_u32(&sBl[sof]));
                bfl[njp * 2 + 0][0] = r[0]; bfl[njp * 2 + 0][1] = r[1];
                bfl[njp * 2 + 1][0] = r[2]; bfl[njp * 2 + 1][1] = r[3];
            }
            // A fragments per mi (keeps live registers low)
#pragma unroll
            for (int mi = 0; mi < 4; mi++) {
                uint32_t afh[4], afl[4];
                const int sof = st * A_ST + (wm + mi * 16 + (lane & 15)) * 40 +
                                ks * 16 + (lane >> 4) * 8;
                ldsm_x4(afh, smem_u32(&sAh[sof]));
                ldsm_x4(afl, smem_u32(&sAl[sof]));
#pragma unroll
                for (int nj = 0; nj < 4; nj++) {
                    mma16816(acc[mi][nj], afh, bfh[nj]);
                    mma16816(acc[mi][nj], afh, bfl[nj]);
                    mma16816(acc[mi][nj], afl, bfh[nj]);
                }
            }
        }
        __syncthreads();
    }

#pragma unroll
    for (int mi = 0; mi < 4; mi++) {
#pragma unroll
        for (int nj = 0; nj < 4; nj++) {
            const int n = n0 + wn + nj * 8 + (lane & 3) * 2;
            const float b0 = bias[n], b1 = bias[n + 1];
#pragma unroll
            for (int half = 0; half < 2; half++) {
                const int m = m0 + wm + mi * 16 + (lane >> 2) + half * 8;
                const float v0 = acc[mi][nj][half * 2 + 0] + b0;
                const float v1 = acc[mi][nj][half * 2 + 1] + b1;
                if (MODE == 1) {
                    const int b = m >> 11;
                    const int s = m & (SEQ - 1);
                    const int h = n >> 6;
                    const int d = n & 63;
                    const size_t idx =
                        ((((size_t)b * N_HEAD + h) * SEQ) + s) * HEAD_DIM + d;
                    __nv_bfloat162 hv, lv;
                    hv.x = __float2bfloat16(v0);
                    hv.y = __float2bfloat16(v1);
                    lv.x = __float2bfloat16(v0 - __bfloat162float(hv.x));
                    lv.y = __float2bfloat16(v1 - __bfloat162float(hv.y));
                    *(__nv_bfloat162*)&outh[idx] = hv;
                    *(__nv_bfloat162*)&outl[idx] = lv;
                } else {
                    *(float2*)&out32[(size_t)m * GN + n] = make_float2(v0, v1);
                }
            }
        }
    }
}

// ---------------------------------------------------------------------------
// Fused flash attention (unchanged from round 6).
// ---------------------------------------------------------------------------
#define FPAD 72
#define FLASH_SMEM ((128 * FPAD * 2 + 64 * FPAD * 4) * 2)   // 73728

__global__ void __launch_bounds__(256) flash_kernel(
    const __nv_bfloat16* __restrict__ Qh, const __nv_bfloat16* __restrict__ Ql,
    const __nv_bfloat16* __restrict__ Kh, const __nv_bfloat16* __restrict__ Kl,
    const __nv_bfloat16* __restrict__ Vh, const __nv_bfloat16* __restrict__ Vl,
    __nv_bfloat16* __restrict__ Oh, __nv_bfloat16* __restrict__ Ol)
{
    extern __shared__ __nv_bfloat16 sm[];
    __nv_bfloat16* sQh = sm;
    __nv_bfloat16* sQl = sQh + 128 * FPAD;
    __nv_bfloat16* sKh = sQl + 128 * FPAD;
    __nv_bfloat16* sKl = sKh + 64 * FPAD;
    __nv_bfloat16* sVh = sKl + 64 * FPAD;
    __nv_bfloat16* sVl = sVh + 64 * FPAD;

    const int tid = threadIdx.x;
    const int wid = tid >> 5;
    const int lane = tid & 31;
    const int i0 = blockIdx.x * 128;
    const int bh = blockIdx.y;
    const size_t base = (size_t)bh * SEQ * HEAD_DIM;

    for (int c = tid; c < 1024; c += 256) {
        const int row = c >> 3, c8 = (c & 7) * 8;
        *(uint4*)&sQh[row * FPAD + c8] =
            *(const uint4*)&Qh[base + (size_t)(i0 + row) * HEAD_DIM + c8];
        *(uint4*)&sQl[row * FPAD + c8] =
            *(const uint4*)&Ql[base + (size_t)(i0 + row) * HEAD_DIM + c8];
    }

    float oacc[8][4];
#pragma unroll
    for (int nt = 0; nt < 8; nt++)
#pragma unroll
        for (int c = 0; c < 4; c++) oacc[nt][c] = 0.f;
    float mrow[2] = {-1e30f, -1e30f};
    float lrow[2] = {0.f, 0.f};

    const int r0 = lane >> 2;
    const int nIter = i0 / 64 + 2;

    for (int it = 0; it < nIter; it++) {
        const int kk0 = it * 64;
        for (int c = tid; c < 512; c += 256) {
            const int row = c >> 3, c8 = (c & 7) * 8;
            *(uint4*)&sKh[row * FPAD + c8] =
                *(const uint4*)&Kh[base + (size_t)(kk0 + row) * HEAD_DIM + c8];
            *(uint4*)&sKl[row * FPAD + c8] =
                *(const uint4*)&Kl[base + (size_t)(kk0 + row) * HEAD_DIM + c8];
            *(uint4*)&sVh[row * FPAD + c8] =
                *(const uint4*)&Vh[base + (size_t)(kk0 + row) * HEAD_DIM + c8];
            *(uint4*)&sVl[row * FPAD + c8] =
                *(const uint4*)&Vl[base + (size_t)(kk0 + row) * HEAD_DIM + c8];
        }
        __syncthreads();

        float sacc[8][4];
#pragma unroll
        for (int nt = 0; nt < 8; nt++)
#pragma unroll
            for (int c = 0; c < 4; c++) sacc[nt][c] = 0.f;

#pragma unroll
        for (int ks = 0; ks < 4; ks++) {
            uint32_t afh[4], afl[4];
            const int qof = (wid * 16 + (lane & 15)) * FPAD + ks * 16 + (lane >> 4) * 8;
            ldsm_x4(afh, smem_u32(&sQh[qof]));
            ldsm_x4(afl, smem_u32(&sQl[qof]));
            uint32_t bfh[8][2], bfl[8][2];
#pragma unroll
            for (int njp = 0; njp < 4; njp++) {
                const int t = lane >> 3;
                const int kof = (njp * 16 + (t >> 1) * 8 + (lane & 7)) * FPAD +
                                ks * 16 + (t & 1) * 8;
                uint32_t r[4];
                ldsm_x4(r, smem_u32(&sKh[kof]));
                bfh[njp * 2 + 0][0] = r[0]; bfh[njp * 2 + 0][1] = r[1];
                bfh[njp * 2 + 1][0] = r[2]; bfh[njp * 2 + 1][1] = r[3];
                ldsm_x4(r, smem_u32(&sKl[kof]));
                bfl[njp * 2 + 0][0] = r[0]; bfl[njp * 2 + 0][1] = r[1];
                bfl[njp * 2 + 1][0] = r[2]; bfl[njp * 2 + 1][1] = r[3];
            }
#pragma unroll
            for (int nt = 0; nt < 8; nt++) {
                mma16816(sacc[nt], afh, bfh[nt]);
                mma16816(sacc[nt], afh, bfl[nt]);
                mma16816(sacc[nt], afl, bfh[nt]);
            }
        }

        const float scale = 0.03125f;
        const bool domask = (kk0 + 63 > i0 + wid * 16);
        float tmax[2] = {-1e30f, -1e30f};
#pragma unroll
        for (int nt = 0; nt < 8; nt++) {
#pragma unroll
            for (int c = 0; c < 4; c++) {
                float s = sacc[nt][c] * scale;
                if (domask) {
                    const int gi = i0 + wid * 16 + r0 + (c >> 1) * 8;
                    const int gj = kk0 + nt * 8 + (lane & 3) * 2 + (c & 1);
                    if (gj > gi) s = -1e30f;
                }
                sacc[nt][c] = s;
                tmax[c >> 1] = fmaxf(tmax[c >> 1], s);
            }
        }
#pragma unroll
        for (int h2 = 0; h2 < 2; h2++) {
            tmax[h2] = fmaxf(tmax[h2], __shfl_xor_sync(0xffffffffu, tmax[h2], 1));
            tmax[h2] = fmaxf(tmax[h2], __shfl_xor_sync(0xffffffffu, tmax[h2], 2));
        }
        float fac[2], mnew[2];
#pragma unroll
        for (int h2 = 0; h2 < 2; h2++) {
            mnew[h2] = fmaxf(mrow[h2], tmax[h2]);
            fac[h2] = __expf(mrow[h2] - mnew[h2]);
            mrow[h2] = mnew[h2];
            lrow[h2] *= fac[h2];
        }
#pragma unroll
        for (int nt = 0; nt < 8; nt++)
#pragma unroll
            for (int c = 0; c < 4; c++) oacc[nt][c] *= fac[c >> 1];

#pragma unroll
        for (int nt = 0; nt < 8; nt++) {
#pragma unroll
            for (int c = 0; c < 4; c++) {
                const float p = __expf(sacc[nt][c] - mnew[c >> 1]);
                sacc[nt][c] = p;
                lrow[c >> 1] += p;
            }
        }

        uint32_t phi[4][4], plo[4][4];
#pragma unroll
        for (int t = 0; t < 4; t++) {
#pragma unroll
            for (int q = 0; q < 4; q++) {
                const float pa = sacc[2 * t + (q >> 1)][(q & 1) * 2 + 0];
                const float pb = sacc[2 * t + (q >> 1)][(q & 1) * 2 + 1];
                __nv_bfloat162 h, l;
                h.x = __float2bfloat16(pa); h.y = __float2bfloat16(pb);
                l.x = __float2bfloat16(pa - __bfloat162float(h.x));
                l.y = __float2bfloat16(pb - __bfloat162float(h.y));
                phi[t][q] = *(uint32_t*)&h;
                plo[t][q] = *(uint32_t*)&l;
            }
        }

#pragma unroll
        for (int ks = 0; ks < 4; ks++) {
            uint32_t bfh[8][2], bfl[8][2];
#pragma unroll
            for (int njp = 0; njp < 4; njp++) {
                const int t = lane >> 3;
                const int vof = (ks * 16 + (t & 1) * 8 + (lane & 7)) * FPAD +
                                njp * 16 + (t >> 1) * 8;
                uint32_t r[4];
                ldsm_x4_t(r, smem_u32(&sVh[vof]));
                bfh[njp * 2 + 0][0] = r[0]; bfh[njp * 2 + 0][1] = r[1];
                bfh[njp * 2 + 1][0] = r[2]; bfh[njp * 2 + 1][1] = r[3];
                ldsm_x4_t(r, smem_u32(&sVl[vof]));
                bfl[njp * 2 + 0][0] = r[0]; bfl[njp * 2 + 0][1] = r[1];
                bfl[njp * 2 + 1][0] = r[2]; bfl[njp * 2 + 1][1] = r[3];
            }
#pragma unroll
            for (int nt = 0; nt < 8; nt++) {
                mma16816(oacc[nt], phi[ks], bfh[nt]);
                mma16816(oacc[nt], phi[ks], bfl[nt]);
                mma16816(oacc[nt], plo[ks], bfh[nt]);
            }
        }
        __syncthreads();
    }

    float inv[2];
#pragma unroll
    for (int h2 = 0; h2 < 2; h2++) {
        float l = lrow[h2];
        l += __shfl_xor_sync(0xffffffffu, l, 1);
        l += __shfl_xor_sync(0xffffffffu, l, 2);
        inv[h2] = 1.f / l;
    }
    const int b = bh >> 4;
    const int h = bh & 15;
#pragma unroll
    for (int nt = 0; nt < 8; nt++) {
#pragma unroll
        for (int half = 0; half < 2; half++) {
            const int gi = i0 + wid * 16 + r0 + half * 8;
            const int d0 = nt * 8 + (lane & 3) * 2;
            const float v0 = oacc[nt][half * 2 + 0] * inv[half];
            const float v1 = oacc[nt][half * 2 + 1] * inv[half];
            const size_t idx = ((size_t)(b * SEQ + gi)) * D_MODEL + h * HEAD_DIM + d0;
            __nv_bfloat162 hv, lv;
            hv.x = __float2bfloat16(v0);
            hv.y = __float2bfloat16(v1);
            lv.x = __float2bfloat16(v0 - __bfloat162float(hv.x));
            lv.y = __float2bfloat16(v1 - __bfloat162float(hv.y));
            *(__nv_bfloat162*)&Oh[idx] = hv;
            *(__nv_bfloat162*)&Ol[idx] = lv;
        }
    }
}

// ---------------------------------------------------------------------------
__global__ void __launch_bounds__(256) split_kernel(
    const float4* __restrict__ in, __nv_bfloat162* __restrict__ hi,
    __nv_bfloat162* __restrict__ lo, int n4)
{
    const int stride = gridDim.x * blockDim.x;
    for (int i = blockIdx.x * blockDim.x + threadIdx.x; i < n4; i += stride) {
        float4 v = in[i];
        __nv_bfloat16 hx = __float2bfloat16(v.x);
        __nv_bfloat16 hy = __float2bfloat16(v.y);
        __nv_bfloat16 hz = __float2bfloat16(v.z);
        __nv_bfloat16 hw = __float2bfloat16(v.w);
        __nv_bfloat162 h0; h0.x = hx; h0.y = hy;
        __nv_bfloat162 h1; h1.x = hz; h1.y = hw;
        __nv_bfloat162 l0, l1;
        l0.x = __float2bfloat16(v.x - __bfloat162float(hx));
        l0.y = __float2bfloat16(v.y - __bfloat162float(hy));
        l1.x = __float2bfloat16(v.z - __bfloat162float(hz));
        l1.y = __float2bfloat16(v.w - __bfloat162float(hw));
        hi[i * 2] = h0; hi[i * 2 + 1] = h1;
        lo[i * 2] = l0; lo[i * 2 + 1] = l1;
    }
}

__global__ void __launch_bounds__(256) wsplit_kernel(
    const float* __restrict__ W, __nv_bfloat16* __restrict__ hiT,
    __nv_bfloat16* __restrict__ loT)
{
    __shared__ float t[32][33];
    const int n0 = blockIdx.x * 32, k0 = blockIdx.y * 32;
    const int tx = threadIdx.x & 31, ty = threadIdx.x >> 5;
#pragma unroll
    for (int r = 0; r < 4; r++) {
        const int kl = ty + r * 8;
        t[kl][tx] = W[(size_t)(k0 + kl) * D_MODEL + n0 + tx];
    }
    __syncthreads();
#pragma unroll
    for (int r = 0; r < 4; r++) {
        const int nl = ty + r * 8;
        const float x = t[tx][nl];
        const __nv_bfloat16 h = __float2bfloat16(x);
        hiT[(size_t)(n0 + nl) * D_MODEL + k0 + tx] = h;
        loT[(size_t)(n0 + nl) * D_MODEL + k0 + tx] =
            __float2bfloat16(x - __bfloat162float(h));
    }
}

// ---------------------------------------------------------------------------
extern "C" void kernel_launch(void* const* d_in, const int* in_sizes, int n_in,
                              void* d_out, int out_size)
{
    const float* q  = (const float*)d_in[0];
    const float* k  = (const float*)d_in[1];
    const float* v  = (const float*)d_in[2];
    const float* Wq = (const float*)d_in[3];
    const float* bq = (const float*)d_in[4];
    const float* Wk = (const float*)d_in[5];
    const float* bk = (const float*)d_in[6];
    const float* Wv = (const float*)d_in[7];
    const float* bv = (const float*)d_in[8];
    const float* Wo = (const float*)d_in[9];
    const float* bo = (const float*)d_in[10];

    __nv_bfloat16 *qh, *ql, *kh, *kl, *vh, *vl, *ah, *al;
    __nv_bfloat16 *Qh, *Ql, *Kh, *Kl, *Vh, *Vl;
    __nv_bfloat16 *wqh, *wql, *wkh, *wkl, *wvh, *wvl, *woh, *wol;
    cudaGetSymbolAddress((void**)&qh, g_qh);  cudaGetSymbolAddress((void**)&ql, g_ql);
    cudaGetSymbolAddress((void**)&kh, g_kh);  cudaGetSymbolAddress((void**)&kl, g_kl);
    cudaGetSymbolAddress((void**)&vh, g_vh);  cudaGetSymbolAddress((void**)&vl, g_vl);
    cudaGetSymbolAddress((void**)&ah, g_ah);  cudaGetSymbolAddress((void**)&al, g_al);
    cudaGetSymbolAddress((void**)&Qh, g_Qh);  cudaGetSymbolAddress((void**)&Ql, g_Ql);
    cudaGetSymbolAddress((void**)&Kh, g_Kh);  cudaGetSymbolAddress((void**)&Kl, g_Kl);
    cudaGetSymbolAddress((void**)&Vh, g_Vh);  cudaGetSymbolAddress((void**)&Vl, g_Vl);
    cudaGetSymbolAddress((void**)&wqh, g_Wqh); cudaGetSymbolAddress((void**)&wql, g_Wql);
    cudaGetSymbolAddress((void**)&wkh, g_Wkh); cudaGetSymbolAddress((void**)&wkl, g_Wkl);
    cudaGetSymbolAddress((void**)&wvh, g_Wvh); cudaGetSymbolAddress((void**)&wvl, g_Wvl);
    cudaGetSymbolAddress((void**)&woh, g_Woh); cudaGetSymbolAddress((void**)&wol, g_Wol);

    cudaFuncSetAttribute(flash_kernel,
                         cudaFuncAttributeMaxDynamicSharedMemorySize, FLASH_SMEM);
    cudaFuncSetAttribute(gemm_mma_kernel<0>,
                         cudaFuncAttributeMaxDynamicSharedMemorySize, G2_SMEM);
    cudaFuncSetAttribute(gemm_mma_kernel<1>,
                         cudaFuncAttributeMaxDynamicSharedMemorySize, G2_SMEM);

    dim3 gW(32, 32);
    wsplit_kernel<<<gW, 256>>>(Wq, wqh, wql);
    wsplit_kernel<<<gW, 256>>>(Wk, wkh, wkl);
    wsplit_kernel<<<gW, 256>>>(Wv, wvh, wvl);
    wsplit_kernel<<<gW, 256>>>(Wo, woh, wol);

    const int n4 = MROWS * D_MODEL / 4;
    split_kernel<<<2048, 256>>>((const float4*)q, (__nv_bfloat162*)qh,
                                (__nv_bfloat162*)ql, n4);
    split_kernel<<<2048, 256>>>((const float4*)k, (__nv_bfloat162*)kh,
                                (__nv_bfloat162*)kl, n4);
    split_kernel<<<2048, 256>>>((const float4*)v, (__nv_bfloat162*)vh,
                                (__nv_bfloat162*)vl, n4);

    // Fused QKV projections: grid.z selects projection; 768 CTAs total.
    dim3 gQKV(GN / 256, MROWS / 128, 3);   // (4, 64, 3)
    gemm_mma_kernel<1><<<gQKV, 512, G2_SMEM>>>(
        qh, ql, kh, kl, vh, vl,
        wqh, wql, wkh, wkl, wvh, wvl,
        bq, bk, bv,
        Qh, Ql, Kh, Kl, Vh, Vl,
        nullptr);

    flash_kernel<<<dim3(SEQ / 128, BH), 256, FLASH_SMEM>>>(Qh, Ql, Kh, Kl, Vh, Vl,
                                                           ah, al);

    // Output projection -> fp32 d_out
    dim3 gO(GN / 256, MROWS / 128, 1);     // (4, 64, 1)
    gemm_mma_kernel<0><<<gO, 512, G2_SMEM>>>(
        ah, al, nullptr, nullptr, nullptr, nullptr,
        woh, wol, nullptr, nullptr, nullptr, nullptr,
        bo, nullptr, nullptr,
        nullptr, nullptr, nullptr, nullptr, nullptr, nullptr,
        (float*)d_out);
}

// round 8
// speedup vs baseline: 3.6223x; 1.1721x over previous
#include <cuda_runtime.h>
#include <cuda_bf16.h>
#include <cuda_fp16.h>
#include <cstdint>

#define D_MODEL 1024
#define N_HEAD  16
#define HEAD_DIM 64
#define BATCH   4
#define SEQ     2048
#define BH      (BATCH * N_HEAD)          // 64
#define MROWS   (BATCH * SEQ)             // 8192
#define GK      1024
#define GN      1024

// ---------------------------------------------------------------------------
// Scratch (device globals)
// ---------------------------------------------------------------------------
// fp16 single-operand activations for dense GEMMs
__device__ __half g_q16[MROWS * D_MODEL], g_k16[MROWS * D_MODEL], g_v16[MROWS * D_MODEL];
__device__ __half g_af[MROWS * D_MODEL];     // flash output, fp16, [b*s][d_model]
// projected Q/K/V, bf16 hi/lo, heads layout (flash consumes; 3-term precision)
__device__ __nv_bfloat16 g_Qh[BH * SEQ * HEAD_DIM], g_Ql[BH * SEQ * HEAD_DIM];
__device__ __nv_bfloat16 g_Kh[BH * SEQ * HEAD_DIM], g_Kl[BH * SEQ * HEAD_DIM];
__device__ __nv_bfloat16 g_Vh[BH * SEQ * HEAD_DIM], g_Vl[BH * SEQ * HEAD_DIM];
// transposed weights [N][K], fp16 hi/lo
__device__ __half g_Wqh[D_MODEL * D_MODEL], g_Wql[D_MODEL * D_MODEL];
__device__ __half g_Wkh[D_MODEL * D_MODEL], g_Wkl[D_MODEL * D_MODEL];
__device__ __half g_Wvh[D_MODEL * D_MODEL], g_Wvl[D_MODEL * D_MODEL];
__device__ __half g_Woh[D_MODEL * D_MODEL], g_Wol[D_MODEL * D_MODEL];

// ---------------------------------------------------------------------------
__device__ __forceinline__ uint32_t smem_u32(const void* p) {
    uint32_t a;
    asm("{ .reg .u64 t; cvta.to.shared.u64 t, %1; cvt.u32.u64 %0, t; }"
        : "=r"(a) : "l"(p));
    return a;
}

#define CP_ASYNC16(dst_u32, src_ptr) \
    asm volatile("cp.async.cg.shared.global [%0], [%1], 16;" \
        :: "r"(dst_u32), "l"(src_ptr))

__device__ __forceinline__ void ldsm_x4(uint32_t* r, uint32_t addr) {
    asm volatile("ldmatrix.sync.aligned.m8n8.x4.shared.b16 {%0,%1,%2,%3}, [%4];"
        : "=r"(r[0]), "=r"(r[1]), "=r"(r[2]), "=r"(r[3]) : "r"(addr));
}

__device__ __forceinline__ void ldsm_x4_t(uint32_t* r, uint32_t addr) {
    asm volatile("ldmatrix.sync.aligned.m8n8.x4.trans.shared.b16 {%0,%1,%2,%3}, [%4];"
        : "=r"(r[0]), "=r"(r[1]), "=r"(r[2]), "=r"(r[3]) : "r"(addr));
}

// bf16 mma (flash)
__device__ __forceinline__ void mma16816(float* d, const uint32_t* a,
                                         const uint32_t* b) {
    asm volatile(
        "mma.sync.aligned.m16n8k16.row.col.f32.bf16.bf16.f32 "
        "{%0,%1,%2,%3}, {%4,%5,%6,%7}, {%8,%9}, {%0,%1,%2,%3};"
        : "+f"(d[0]), "+f"(d[1]), "+f"(d[2]), "+f"(d[3])
        : "r"(a[0]), "r"(a[1]), "r"(a[2]), "r"(a[3]), "r"(b[0]), "r"(b[1]));
}

// fp16 mma (dense GEMMs)
__device__ __forceinline__ void mma16816h(float* d, const uint32_t* a,
                                          const uint32_t* b) {
    asm volatile(
        "mma.sync.aligned.m16n8k16.row.col.f32.f16.f16.f32 "
        "{%0,%1,%2,%3}, {%4,%5,%6,%7}, {%8,%9}, {%0,%1,%2,%3};"
        : "+f"(d[0]), "+f"(d[1]), "+f"(d[2]), "+f"(d[3])
        : "r"(a[0]), "r"(a[1]), "r"(a[2]), "r"(a[3]), "r"(b[0]), "r"(b[1]));
}

// ---------------------------------------------------------------------------
// fp16 2-term GEMM: C = A * (Whi + Wlo) + bias.  512 threads, BM=128 BN=256
// BK=32, double-buffered.  gridDim.z selects projection (fused QKV).
// MODE 1: bf16 hi/lo out in heads layout.  MODE 0: fp32 out.
// smem: A (2 x 128 x 40) + Bh|Bl (2 x 256 x 40 each) = 102400 B.
// ---------------------------------------------------------------------------
#define NSLABS  32            // 1024 / 32
#define A_ST    (128 * 40)
#define B_ST    (256 * 40)
#define G2_SMEM ((2 * A_ST + 4 * B_ST) * 2)   // 102400

template <int MODE>
__global__ void __launch_bounds__(512) gemm_mma_kernel(
    const __half* __restrict__ A0, const __half* __restrict__ A1,
    const __half* __restrict__ A2,
    const __half* __restrict__ B0h, const __half* __restrict__ B0l,
    const __half* __restrict__ B1h, const __half* __restrict__ B1l,
    const __half* __restrict__ B2h, const __half* __restrict__ B2l,
    const float* __restrict__ bias0, const float* __restrict__ bias1,
    const float* __restrict__ bias2,
    __nv_bfloat16* __restrict__ O0h, __nv_bfloat16* __restrict__ O0l,
    __nv_bfloat16* __restrict__ O1h, __nv_bfloat16* __restrict__ O1l,
    __nv_bfloat16* __restrict__ O2h, __nv_bfloat16* __restrict__ O2l,
    float* __restrict__ out32)
{
    extern __shared__ __half gsm[];
    __half* sA  = gsm;                   // [2][128][40]
    __half* sBh = sA + 2 * A_ST;         // [2][256][40]
    __half* sBl = sBh + 2 * B_ST;

    const int z = blockIdx.z;
    const __half* Ag  = (z == 0) ? A0 : (z == 1) ? A1 : A2;
    const __half* Bhi = (z == 0) ? B0h : (z == 1) ? B1h : B2h;
    const __half* Blo = (z == 0) ? B0l : (z == 1) ? B1l : B2l;
    const float* bias = (z == 0) ? bias0 : (z == 1) ? bias1 : bias2;
    __nv_bfloat16* outh = (z == 0) ? O0h : (z == 1) ? O1h : O2h;
    __nv_bfloat16* outl = (z == 0) ? O0l : (z == 1) ? O1l : O2l;

    const int tid = threadIdx.x;
    const int wid = tid >> 5;
    const int lane = tid & 31;
    const int m0 = blockIdx.y * 128;
    const int n0 = blockIdx.x * 256;
    const int wm = (wid & 1) * 64;       // 2 m-warps
    const int wn = (wid >> 1) * 32;      // 8 n-warps -> 256

    float acc[4][4][4];
#pragma unroll
    for (int i = 0; i < 4; i++)
#pragma unroll
        for (int j = 0; j < 4; j++)
#pragma unroll
            for (int c = 0; c < 4; c++) acc[i][j][c] = 0.f;

    const int ldrow = tid >> 2;            // 0..127
    const int ldcol = (tid & 3) * 8;       // 0,8,16,24

    auto issue_load = [&](int stage, int slab) {
        const int k0 = slab << 5;
        {
            const size_t ga = (size_t)(m0 + ldrow) * GK + k0 + ldcol;
            const int sof = stage * A_ST + ldrow * 40 + ldcol;
            CP_ASYNC16(smem_u32(&sA[sof]), Ag + ga);
        }
#pragma unroll
        for (int r = 0; r < 2; r++) {
            const int row = ldrow + r * 128;
            const size_t gb = (size_t)(n0 + row) * GK + k0 + ldcol;
            const int sof = stage * B_ST + row * 40 + ldcol;
            CP_ASYNC16(smem_u32(&sBh[sof]), Bhi + gb);
            CP_ASYNC16(smem_u32(&sBl[sof]), Blo + gb);
        }
        asm volatile("cp.async.commit_group;" ::: "memory");
    };

    issue_load(0, 0);

    for (int i = 0; i < NSLABS; i++) {
        const int st = i & 1;
        if (i + 1 < NSLABS) {
            issue_load(st ^ 1, i + 1);
            asm volatile("cp.async.wait_group 1;" ::: "memory");
        } else {
            asm volatile("cp.async.wait_group 0;" ::: "memory");
        }
        __syncthreads();

#pragma unroll
        for (int ks = 0; ks < 2; ks++) {
            uint32_t bfh[4][2], bfl[4][2];
#pragma unroll
            for (int njp = 0; njp < 2; njp++) {
                const int t = lane >> 3;
                const int sof = st * B_ST +
                                (wn + njp * 16 + (t >> 1) * 8 + (lane & 7)) * 40 +
                                ks * 16 + (t & 1) * 8;
                uint32_t r[4];
                ldsm_x4(r, smem_u32(&sBh[sof]));
                bfh[njp * 2 + 0][0] = r[0]; bfh[njp * 2 + 0][1] = r[1];
                bfh[njp * 2 + 1][0] = r[2]; bfh[njp * 2 + 1][1] = r[3];
                ldsm_x4(r, smem_u32(&sBl[sof]));
                bfl[njp * 2 + 0][0] = r[0]; bfl[njp * 2 + 0][1] = r[1];
                bfl[njp * 2 + 1][0] = r[2]; bfl[njp * 2 + 1][1] = r[3];
            }
#pragma unroll
            for (int mi = 0; mi < 4; mi++) {
                uint32_t af[4];
                const int sof = st * A_ST + (wm + mi * 16 + (lane & 15)) * 40 +
                                ks * 16 + (lane >> 4) * 8;
                ldsm_x4(af, smem_u32(&sA[sof]));
#pragma unroll
                for (int nj = 0; nj < 4; nj++) {
                    mma16816h(acc[mi][nj], af, bfh[nj]);
                    mma16816h(acc[mi][nj], af, bfl[nj]);
                }
            }
        }
        __syncthreads();
    }

#pragma unroll
    for (int mi = 0; mi < 4; mi++) {
#pragma unroll
        for (int nj = 0; nj < 4; nj++) {
            const int n = n0 + wn + nj * 8 + (lane & 3) * 2;
            const float b0 = bias[n], b1 = bias[n + 1];
#pragma unroll
            for (int half = 0; half < 2; half++) {
                const int m = m0 + wm + mi * 16 + (lane >> 2) + half * 8;
                const float v0 = acc[mi][nj][half * 2 + 0] + b0;
                const float v1 = acc[mi][nj][half * 2 + 1] + b1;
                if (MODE == 1) {
                    const int b = m >> 11;
                    const int s = m & (SEQ - 1);
                    const int h = n >> 6;
                    const int d = n & 63;
                    const size_t idx =
                        ((((size_t)b * N_HEAD + h) * SEQ) + s) * HEAD_DIM + d;
                    __nv_bfloat162 hv, lv;
                    hv.x = __float2bfloat16(v0);
                    hv.y = __float2bfloat16(v1);
                    lv.x = __float2bfloat16(v0 - __bfloat162float(hv.x));
                    lv.y = __float2bfloat16(v1 - __bfloat162float(hv.y));
                    *(__nv_bfloat162*)&outh[idx] = hv;
                    *(__nv_bfloat162*)&outl[idx] = lv;
                } else {
                    *(float2*)&out32[(size_t)m * GN + n] = make_float2(v0, v1);
                }
            }
        }
    }
}

// ---------------------------------------------------------------------------
// Fused flash attention (3-term bf16, unchanged math).  Writes fp16 output.
// ---------------------------------------------------------------------------
#define FPAD 72
#define FLASH_SMEM ((128 * FPAD * 2 + 64 * FPAD * 4) * 2)   // 73728

__global__ void __launch_bounds__(256) flash_kernel(
    const __nv_bfloat16* __restrict__ Qh, const __nv_bfloat16* __restrict__ Ql,
    const __nv_bfloat16* __restrict__ Kh, const __nv_bfloat16* __restrict__ Kl,
    const __nv_bfloat16* __restrict__ Vh, const __nv_bfloat16* __restrict__ Vl,
    __half* __restrict__ Oa)
{
    extern __shared__ __nv_bfloat16 sm[];
    __nv_bfloat16* sQh = sm;
    __nv_bfloat16* sQl = sQh + 128 * FPAD;
    __nv_bfloat16* sKh = sQl + 128 * FPAD;
    __nv_bfloat16* sKl = sKh + 64 * FPAD;
    __nv_bfloat16* sVh = sKl + 64 * FPAD;
    __nv_bfloat16* sVl = sVh + 64 * FPAD;

    const int tid = threadIdx.x;
    const int wid = tid >> 5;
    const int lane = tid & 31;
    const int i0 = blockIdx.x * 128;
    const int bh = blockIdx.y;
    const size_t base = (size_t)bh * SEQ * HEAD_DIM;

    for (int c = tid; c < 1024; c += 256) {
        const int row = c >> 3, c8 = (c & 7) * 8;
        *(uint4*)&sQh[row * FPAD + c8] =
            *(const uint4*)&Qh[base + (size_t)(i0 + row) * HEAD_DIM + c8];
        *(uint4*)&sQl[row * FPAD + c8] =
            *(const uint4*)&Ql[base + (size_t)(i0 + row) * HEAD_DIM + c8];
    }

    float oacc[8][4];
#pragma unroll
    for (int nt = 0; nt < 8; nt++)
#pragma unroll
        for (int c = 0; c < 4; c++) oacc[nt][c] = 0.f;
    float mrow[2] = {-1e30f, -1e30f};
    float lrow[2] = {0.f, 0.f};

    const int r0 = lane >> 2;
    const int nIter = i0 / 64 + 2;

    for (int it = 0; it < nIter; it++) {
        const int kk0 = it * 64;
        for (int c = tid; c < 512; c += 256) {
            const int row = c >> 3, c8 = (c & 7) * 8;
            *(uint4*)&sKh[row * FPAD + c8] =
                *(const uint4*)&Kh[base + (size_t)(kk0 + row) * HEAD_DIM + c8];
            *(uint4*)&sKl[row * FPAD + c8] =
                *(const uint4*)&Kl[base + (size_t)(kk0 + row) * HEAD_DIM + c8];
            *(uint4*)&sVh[row * FPAD + c8] =
                *(const uint4*)&Vh[base + (size_t)(kk0 + row) * HEAD_DIM + c8];
            *(uint4*)&sVl[row * FPAD + c8] =
                *(const uint4*)&Vl[base + (size_t)(kk0 + row) * HEAD_DIM + c8];
        }
        __syncthreads();

        float sacc[8][4];
#pragma unroll
        for (int nt = 0; nt < 8; nt++)
#pragma unroll
            for (int c = 0; c < 4; c++) sacc[nt][c] = 0.f;

#pragma unroll
        for (int ks = 0; ks < 4; ks++) {
            uint32_t afh[4], afl[4];
            const int qof = (wid * 16 + (lane & 15)) * FPAD + ks * 16 + (lane >> 4) * 8;
            ldsm_x4(afh, smem_u32(&sQh[qof]));
            ldsm_x4(afl, smem_u32(&sQl[qof]));
            uint32_t bfh[8][2], bfl[8][2];
#pragma unroll
            for (int njp = 0; njp < 4; njp++) {
                const int t = lane >> 3;
                const int kof = (njp * 16 + (t >> 1) * 8 + (lane & 7)) * FPAD +
                                ks * 16 + (t & 1) * 8;
                uint32_t r[4];
                ldsm_x4(r, smem_u32(&sKh[kof]));
                bfh[njp * 2 + 0][0] = r[0]; bfh[njp * 2 + 0][1] = r[1];
                bfh[njp * 2 + 1][0] = r[2]; bfh[njp * 2 + 1][1] = r[3];
                ldsm_x4(r, smem_u32(&sKl[kof]));
                bfl[njp * 2 + 0][0] = r[0]; bfl[njp * 2 + 0][1] = r[1];
                bfl[njp * 2 + 1][0] = r[2]; bfl[njp * 2 + 1][1] = r[3];
            }
#pragma unroll
            for (int nt = 0; nt < 8; nt++) {
                mma16816(sacc[nt], afh, bfh[nt]);
                mma16816(sacc[nt], afh, bfl[nt]);
                mma16816(sacc[nt], afl, bfh[nt]);
            }
        }

        const float scale = 0.03125f;
        const bool domask = (kk0 + 63 > i0 + wid * 16);
        float tmax[2] = {-1e30f, -1e30f};
#pragma unroll
        for (int nt = 0; nt < 8; nt++) {
#pragma unroll
            for (int c = 0; c < 4; c++) {
                float s = sacc[nt][c] * scale;
                if (domask) {
                    const int gi = i0 + wid * 16 + r0 + (c >> 1) * 8;
                    const int gj = kk0 + nt * 8 + (lane & 3) * 2 + (c & 1);
                    if (gj > gi) s = -1e30f;
                }
                sacc[nt][c] = s;
                tmax[c >> 1] = fmaxf(tmax[c >> 1], s);
            }
        }
#pragma unroll
        for (int h2 = 0; h2 < 2; h2++) {
            tmax[h2] = fmaxf(tmax[h2], __shfl_xor_sync(0xffffffffu, tmax[h2], 1));
            tmax[h2] = fmaxf(tmax[h2], __shfl_xor_sync(0xffffffffu, tmax[h2], 2));
        }
        float fac[2], mnew[2];
#pragma unroll
        for (int h2 = 0; h2 < 2; h2++) {
            mnew[h2] = fmaxf(mrow[h2], tmax[h2]);
            fac[h2] = __expf(mrow[h2] - mnew[h2]);
            mrow[h2] = mnew[h2];
            lrow[h2] *= fac[h2];
        }
#pragma unroll
        for (int nt = 0; nt < 8; nt++)
#pragma unroll
            for (int c = 0; c < 4; c++) oacc[nt][c] *= fac[c >> 1];

#pragma unroll
        for (int nt = 0; nt < 8; nt++) {
#pragma unroll
            for (int c = 0; c < 4; c++) {
                const float p = __expf(sacc[nt][c] - mnew[c >> 1]);
                sacc[nt][c] = p;
                lrow[c >> 1] += p;
            }
        }

        uint32_t phi[4][4], plo[4][4];
#pragma unroll
        for (int t = 0; t < 4; t++) {
#pragma unroll
            for (int q = 0; q < 4; q++) {
                const float pa = sacc[2 * t + (q >> 1)][(q & 1) * 2 + 0];
                const float pb = sacc[2 * t + (q >> 1)][(q & 1) * 2 + 1];
                __nv_bfloat162 h, l;
                h.x = __float2bfloat16(pa); h.y = __float2bfloat16(pb);
                l.x = __float2bfloat16(pa - __bfloat162float(h.x));
                l.y = __float2bfloat16(pb - __bfloat162float(h.y));
                phi[t][q] = *(uint32_t*)&h;
                plo[t][q] = *(uint32_t*)&l;
            }
        }

#pragma unroll
        for (int ks = 0; ks < 4; ks++) {
            uint32_t bfh[8][2], bfl[8][2];
#pragma unroll
            for (int njp = 0; njp < 4; njp++) {
                const int t = lane >> 3;
                const int vof = (ks * 16 + (t & 1) * 8 + (lane & 7)) * FPAD +
                                njp * 16 + (t >> 1) * 8;
                uint32_t r[4];
                ldsm_x4_t(r, smem_u32(&sVh[vof]));
                bfh[njp * 2 + 0][0] = r[0]; bfh[njp * 2 + 0][1] = r[1];
                bfh[njp * 2 + 1][0] = r[2]; bfh[njp * 2 + 1][1] = r[3];
                ldsm_x4_t(r, smem_u32(&sVl[vof]));
                bfl[njp * 2 + 0][0] = r[0]; bfl[njp * 2 + 0][1] = r[1];
                bfl[njp * 2 + 1][0] = r[2]; bfl[njp * 2 + 1][1] = r[3];
            }
#pragma unroll
            for (int nt = 0; nt < 8; nt++) {
                mma16816(oacc[nt], phi[ks], bfh[nt]);
                mma16816(oacc[nt], phi[ks], bfl[nt]);
                mma16816(oacc[nt], plo[ks], bfh[nt]);
            }
        }
        __syncthreads();
    }

    float inv[2];
#pragma unroll
    for (int h2 = 0; h2 < 2; h2++) {
        float l = lrow[h2];
        l += __shfl_xor_sync(0xffffffffu, l, 1);
        l += __shfl_xor_sync(0xffffffffu, l, 2);
        inv[h2] = 1.f / l;
    }
    const int b = bh >> 4;
    const int h = bh & 15;
#pragma unroll
    for (int nt = 0; nt < 8; nt++) {
#pragma unroll
        for (int half = 0; half < 2; half++) {
            const int gi = i0 + wid * 16 + r0 + half * 8;
            const int d0 = nt * 8 + (lane & 3) * 2;
            const float v0 = oacc[nt][half * 2 + 0] * inv[half];
            const float v1 = oacc[nt][half * 2 + 1] * inv[half];
            const size_t idx = ((size_t)(b * SEQ + gi)) * D_MODEL + h * HEAD_DIM + d0;
            *(__half2*)&Oa[idx] = __floats2half2_rn(v0, v1);
        }
    }
}

// ---------------------------------------------------------------------------
// fp32 -> fp16 convert (activations)
// ---------------------------------------------------------------------------
__global__ void __launch_bounds__(256) cvt_kernel(
    const float4* __restrict__ in, __half2* __restrict__ out, int n4)
{
    const int stride = gridDim.x * blockDim.x;
    for (int i = blockIdx.x * blockDim.x + threadIdx.x; i < n4; i += stride) {
        float4 v = in[i];
        out[i * 2 + 0] = __floats2half2_rn(v.x, v.y);
        out[i * 2 + 1] = __floats2half2_rn(v.z, v.w);
    }
}

// ---------------------------------------------------------------------------
// W[K,N] -> Wt hi/lo [N,K] fp16 (transpose + split)
// ---------------------------------------------------------------------------
__global__ void __launch_bounds__(256) wsplit_kernel(
    const float* __restrict__ W, __half* __restrict__ hiT,
    __half* __restrict__ loT)
{
    __shared__ float t[32][33];
    const int n0 = blockIdx.x * 32, k0 = blockIdx.y * 32;
    const int tx = threadIdx.x & 31, ty = threadIdx.x >> 5;
#pragma unroll
    for (int r = 0; r < 4; r++) {
        const int kl = ty + r * 8;
        t[kl][tx] = W[(size_t)(k0 + kl) * D_MODEL + n0 + tx];
    }
    __syncthreads();
#pragma unroll
    for (int r = 0; r < 4; r++) {
        const int nl = ty + r * 8;
        const float x = t[tx][nl];
        const __half h = __float2half_rn(x);
        hiT[(size_t)(n0 + nl) * D_MODEL + k0 + tx] = h;
        loT[(size_t)(n0 + nl) * D_MODEL + k0 + tx] =
            __float2half_rn(x - __half2float(h));
    }
}

// ---------------------------------------------------------------------------
extern "C" void kernel_launch(void* const* d_in, const int* in_sizes, int n_in,
                              void* d_out, int out_size)
{
    const float* q  = (const float*)d_in[0];
    const float* k  = (const float*)d_in[1];
    const float* v  = (const float*)d_in[2];
    const float* Wq = (const float*)d_in[3];
    const float* bq = (const float*)d_in[4];
    const float* Wk = (const float*)d_in[5];
    const float* bk = (const float*)d_in[6];
    const float* Wv = (const float*)d_in[7];
    const float* bv = (const float*)d_in[8];
    const float* Wo = (const float*)d_in[9];
    const float* bo = (const float*)d_in[10];

    __half *q16, *k16, *v16, *af;
    __nv_bfloat16 *Qh, *Ql, *Kh, *Kl, *Vh, *Vl;
    __half *wqh, *wql, *wkh, *wkl, *wvh, *wvl, *woh, *wol;
    cudaGetSymbolAddress((void**)&q16, g_q16);
    cudaGetSymbolAddress((void**)&k16, g_k16);
    cudaGetSymbolAddress((void**)&v16, g_v16);
    cudaGetSymbolAddress((void**)&af, g_af);
    cudaGetSymbolAddress((void**)&Qh, g_Qh);  cudaGetSymbolAddress((void**)&Ql, g_Ql);
    cudaGetSymbolAddress((void**)&Kh, g_Kh);  cudaGetSymbolAddress((void**)&Kl, g_Kl);
    cudaGetSymbolAddress((void**)&Vh, g_Vh);  cudaGetSymbolAddress((void**)&Vl, g_Vl);
    cudaGetSymbolAddress((void**)&wqh, g_Wqh); cudaGetSymbolAddress((void**)&wql, g_Wql);
    cudaGetSymbolAddress((void**)&wkh, g_Wkh); cudaGetSymbolAddress((void**)&wkl, g_Wkl);
    cudaGetSymbolAddress((void**)&wvh, g_Wvh); cudaGetSymbolAddress((void**)&wvl, g_Wvl);
    cudaGetSymbolAddress((void**)&woh, g_Woh); cudaGetSymbolAddress((void**)&wol, g_Wol);

    cudaFuncSetAttribute(flash_kernel,
                         cudaFuncAttributeMaxDynamicSharedMemorySize, FLASH_SMEM);
    cudaFuncSetAttribute(gemm_mma_kernel<0>,
                         cudaFuncAttributeMaxDynamicSharedMemorySize, G2_SMEM);
    cudaFuncSetAttribute(gemm_mma_kernel<1>,
                         cudaFuncAttributeMaxDynamicSharedMemorySize, G2_SMEM);

    dim3 gW(32, 32);
    wsplit_kernel<<<gW, 256>>>(Wq, wqh, wql);
    wsplit_kernel<<<gW, 256>>>(Wk, wkh, wkl);
    wsplit_kernel<<<gW, 256>>>(Wv, wvh, wvl);
    wsplit_kernel<<<gW, 256>>>(Wo, woh, wol);

    const int n4 = MROWS * D_MODEL / 4;
    cvt_kernel<<<2048, 256>>>((const float4*)q, (__half2*)q16, n4);
    cvt_kernel<<<2048, 256>>>((const float4*)k, (__half2*)k16, n4);
    cvt_kernel<<<2048, 256>>>((const float4*)v, (__half2*)v16, n4);

    // Fused QKV projections (fp16 2-term): grid.z selects projection.
    dim3 gQKV(GN / 256, MROWS / 128, 3);   // (4, 64, 3)
    gemm_mma_kernel<1><<<gQKV, 512, G2_SMEM>>>(
        q16, k16, v16,
        wqh, wql, wkh, wkl, wvh, wvl,
        bq, bk, bv,
        Qh, Ql, Kh, Kl, Vh, Vl,
        nullptr);

    flash_kernel<<<dim3(SEQ / 128, BH), 256, FLASH_SMEM>>>(Qh, Ql, Kh, Kl, Vh, Vl,
                                                           af);

    // Output projection (fp16 2-term) -> fp32 d_out
    dim3 gO(GN / 256, MROWS / 128, 1);
    gemm_mma_kernel<0><<<gO, 512, G2_SMEM>>>(
        af, nullptr, nullptr,
        woh, wol, nullptr, nullptr, nullptr, nullptr,
        bo, nullptr, nullptr,
        nullptr, nullptr, nullptr, nullptr, nullptr, nullptr,
        (float*)d_out);
}

// round 9
// speedup vs baseline: 4.6642x; 1.2876x over previous
#include <cuda_runtime.h>
#include <cuda_bf16.h>
#include <cuda_fp16.h>
#include <cstdint>

#define D_MODEL 1024
#define N_HEAD  16
#define HEAD_DIM 64
#define BATCH   4
#define SEQ     2048
#define BH      (BATCH * N_HEAD)          // 64
#define MROWS   (BATCH * SEQ)             // 8192
#define GK      1024
#define GN      1024

// ---------------------------------------------------------------------------
// Scratch (device globals)
// ---------------------------------------------------------------------------
__device__ __half g_q16[MROWS * D_MODEL], g_k16[MROWS * D_MODEL], g_v16[MROWS * D_MODEL];
__device__ __half g_af[MROWS * D_MODEL];     // flash output, fp16
// projected Q/K single fp16, V fp16 hi/lo, heads layout [bh][s][hd]
__device__ __half g_Q16[BH * SEQ * HEAD_DIM], g_K16[BH * SEQ * HEAD_DIM];
__device__ __half g_V16h[BH * SEQ * HEAD_DIM], g_V16l[BH * SEQ * HEAD_DIM];
// transposed weights [N][K], fp16 hi/lo
__device__ __half g_Wqh[D_MODEL * D_MODEL], g_Wql[D_MODEL * D_MODEL];
__device__ __half g_Wkh[D_MODEL * D_MODEL], g_Wkl[D_MODEL * D_MODEL];
__device__ __half g_Wvh[D_MODEL * D_MODEL], g_Wvl[D_MODEL * D_MODEL];
__device__ __half g_Woh[D_MODEL * D_MODEL], g_Wol[D_MODEL * D_MODEL];

// ---------------------------------------------------------------------------
__device__ __forceinline__ uint32_t smem_u32(const void* p) {
    uint32_t a;
    asm("{ .reg .u64 t; cvta.to.shared.u64 t, %1; cvt.u32.u64 %0, t; }"
        : "=r"(a) : "l"(p));
    return a;
}

#define CP_ASYNC16(dst_u32, src_ptr) \
    asm volatile("cp.async.cg.shared.global [%0], [%1], 16;" \
        :: "r"(dst_u32), "l"(src_ptr))

__device__ __forceinline__ void ldsm_x4(uint32_t* r, uint32_t addr) {
    asm volatile("ldmatrix.sync.aligned.m8n8.x4.shared.b16 {%0,%1,%2,%3}, [%4];"
        : "=r"(r[0]), "=r"(r[1]), "=r"(r[2]), "=r"(r[3]) : "r"(addr));
}

__device__ __forceinline__ void ldsm_x4_t(uint32_t* r, uint32_t addr) {
    asm volatile("ldmatrix.sync.aligned.m8n8.x4.trans.shared.b16 {%0,%1,%2,%3}, [%4];"
        : "=r"(r[0]), "=r"(r[1]), "=r"(r[2]), "=r"(r[3]) : "r"(addr));
}

__device__ __forceinline__ void mma16816h(float* d, const uint32_t* a,
                                          const uint32_t* b) {
    asm volatile(
        "mma.sync.aligned.m16n8k16.row.col.f32.f16.f16.f32 "
        "{%0,%1,%2,%3}, {%4,%5,%6,%7}, {%8,%9}, {%0,%1,%2,%3};"
        : "+f"(d[0]), "+f"(d[1]), "+f"(d[2]), "+f"(d[3])
        : "r"(a[0]), "r"(a[1]), "r"(a[2]), "r"(a[3]), "r"(b[0]), "r"(b[1]));
}

// ---------------------------------------------------------------------------
// fp16 2-term GEMM: C = A * (Whi + Wlo) + bias.  512 threads, BM=128 BN=256
// BK=32, 3-stage cp.async pipeline.  gridDim.z selects projection.
// MODE 1: z<2 -> single fp16 heads layout; z==2 -> fp16 hi/lo heads layout.
// MODE 0: fp32 row-major out.
// ---------------------------------------------------------------------------
#define NSLABS  32
#define A_ST    (128 * 40)
#define B_ST    (256 * 40)
#define G3_SMEM ((3 * A_ST + 6 * B_ST) * 2)   // 153600

template <int MODE>
__global__ void __launch_bounds__(512) gemm_mma_kernel(
    const __half* __restrict__ A0, const __half* __restrict__ A1,
    const __half* __restrict__ A2,
    const __half* __restrict__ B0h, const __half* __restrict__ B0l,
    const __half* __restrict__ B1h, const __half* __restrict__ B1l,
    const __half* __restrict__ B2h, const __half* __restrict__ B2l,
    const float* __restrict__ bias0, const float* __restrict__ bias1,
    const float* __restrict__ bias2,
    __half* __restrict__ OutS0, __half* __restrict__ OutS1,
    __half* __restrict__ Out2h, __half* __restrict__ Out2l,
    float* __restrict__ out32)
{
    extern __shared__ __half gsm[];
    __half* sA  = gsm;                   // [3][128][40]
    __half* sBh = sA + 3 * A_ST;         // [3][256][40]
    __half* sBl = sBh + 3 * B_ST;

    const int z = blockIdx.z;
    const __half* Ag  = (z == 0) ? A0 : (z == 1) ? A1 : A2;
    const __half* Bhi = (z == 0) ? B0h : (z == 1) ? B1h : B2h;
    const __half* Blo = (z == 0) ? B0l : (z == 1) ? B1l : B2l;
    const float* bias = (z == 0) ? bias0 : (z == 1) ? bias1 : bias2;

    const int tid = threadIdx.x;
    const int wid = tid >> 5;
    const int lane = tid & 31;
    const int m0 = blockIdx.y * 128;
    const int n0 = blockIdx.x * 256;
    const int wm = (wid & 1) * 64;
    const int wn = (wid >> 1) * 32;

    float acc[4][4][4];
#pragma unroll
    for (int i = 0; i < 4; i++)
#pragma unroll
        for (int j = 0; j < 4; j++)
#pragma unroll
            for (int c = 0; c < 4; c++) acc[i][j][c] = 0.f;

    const int ldrow = tid >> 2;
    const int ldcol = (tid & 3) * 8;

    auto issue_load = [&](int stage, int slab) {
        const int k0 = slab << 5;
        {
            const size_t ga = (size_t)(m0 + ldrow) * GK + k0 + ldcol;
            const int sof = stage * A_ST + ldrow * 40 + ldcol;
            CP_ASYNC16(smem_u32(&sA[sof]), Ag + ga);
        }
#pragma unroll
        for (int r = 0; r < 2; r++) {
            const int row = ldrow + r * 128;
            const size_t gb = (size_t)(n0 + row) * GK + k0 + ldcol;
            const int sof = stage * B_ST + row * 40 + ldcol;
            CP_ASYNC16(smem_u32(&sBh[sof]), Bhi + gb);
            CP_ASYNC16(smem_u32(&sBl[sof]), Blo + gb);
        }
        asm volatile("cp.async.commit_group;" ::: "memory");
    };

    issue_load(0, 0);
    issue_load(1, 1);

    int st = 0;
    for (int i = 0; i < NSLABS; i++) {
        if (i + 2 < NSLABS) {
            issue_load((st + 2) % 3, i + 2);
            asm volatile("cp.async.wait_group 2;" ::: "memory");
        } else if (i + 1 < NSLABS) {
            asm volatile("cp.async.wait_group 1;" ::: "memory");
        } else {
            asm volatile("cp.async.wait_group 0;" ::: "memory");
        }
        __syncthreads();

#pragma unroll
        for (int ks = 0; ks < 2; ks++) {
            uint32_t bfh[4][2], bfl[4][2];
#pragma unroll
            for (int njp = 0; njp < 2; njp++) {
                const int t = lane >> 3;
                const int sof = st * B_ST +
                                (wn + njp * 16 + (t >> 1) * 8 + (lane & 7)) * 40 +
                                ks * 16 + (t & 1) * 8;
                uint32_t r[4];
                ldsm_x4(r, smem_u32(&sBh[sof]));
                bfh[njp * 2 + 0][0] = r[0]; bfh[njp * 2 + 0][1] = r[1];
                bfh[njp * 2 + 1][0] = r[2]; bfh[njp * 2 + 1][1] = r[3];
                ldsm_x4(r, smem_u32(&sBl[sof]));
                bfl[njp * 2 + 0][0] = r[0]; bfl[njp * 2 + 0][1] = r[1];
                bfl[njp * 2 + 1][0] = r[2]; bfl[njp * 2 + 1][1] = r[3];
            }
#pragma unroll
            for (int mi = 0; mi < 4; mi++) {
                uint32_t af[4];
                const int sof = st * A_ST + (wm + mi * 16 + (lane & 15)) * 40 +
                                ks * 16 + (lane >> 4) * 8;
                ldsm_x4(af, smem_u32(&sA[sof]));
#pragma unroll
                for (int nj = 0; nj < 4; nj++) {
                    mma16816h(acc[mi][nj], af, bfh[nj]);
                    mma16816h(acc[mi][nj], af, bfl[nj]);
                }
            }
        }
        __syncthreads();
        st = (st + 1) % 3;
    }

#pragma unroll
    for (int mi = 0; mi < 4; mi++) {
#pragma unroll
        for (int nj = 0; nj < 4; nj++) {
            const int n = n0 + wn + nj * 8 + (lane & 3) * 2;
            const float b0 = bias[n], b1 = bias[n + 1];
#pragma unroll
            for (int half = 0; half < 2; half++) {
                const int m = m0 + wm + mi * 16 + (lane >> 2) + half * 8;
                const float v0 = acc[mi][nj][half * 2 + 0] + b0;
                const float v1 = acc[mi][nj][half * 2 + 1] + b1;
                if (MODE == 1) {
                    const int b = m >> 11;
                    const int s = m & (SEQ - 1);
                    const int h = n >> 6;
                    const int d = n & 63;
                    const size_t idx =
                        ((((size_t)b * N_HEAD + h) * SEQ) + s) * HEAD_DIM + d;
                    if (z < 2) {
                        __half* dst = (z == 0) ? OutS0 : OutS1;
                        *(__half2*)&dst[idx] = __floats2half2_rn(v0, v1);
                    } else {
                        const __half h0 = __float2half_rn(v0);
                        const __half h1 = __float2half_rn(v1);
                        __half2 hv; hv.x = h0; hv.y = h1;
                        __half2 lv;
                        lv.x = __float2half_rn(v0 - __half2float(h0));
                        lv.y = __float2half_rn(v1 - __half2float(h1));
                        *(__half2*)&Out2h[idx] = hv;
                        *(__half2*)&Out2l[idx] = lv;
                    }
                } else {
                    *(float2*)&out32[(size_t)m * GN + n] = make_float2(v0, v1);
                }
            }
        }
    }
}

// ---------------------------------------------------------------------------
// Fused flash attention, fp16 asymmetric precision.
// S = Q^ K^T (single fp16 both, 1 MMA); PV = P^ (Vhi + Vlo) (2 MMAs).
// grid (SEQ/128, BH), 256 threads.
// ---------------------------------------------------------------------------
#define FPAD 72
#define FLASH_SMEM ((128 * FPAD + 3 * 64 * FPAD) * 2)   // 46080

__global__ void __launch_bounds__(256) flash_kernel(
    const __half* __restrict__ Qg, const __half* __restrict__ Kg,
    const __half* __restrict__ Vgh, const __half* __restrict__ Vgl,
    __half* __restrict__ Oa)
{
    extern __shared__ __half fsm[];
    __half* sQ  = fsm;                       // 128*FPAD
    __half* sK  = sQ + 128 * FPAD;           // 64*FPAD
    __half* sVh = sK + 64 * FPAD;            // [key][dim]
    __half* sVl = sVh + 64 * FPAD;

    const int tid = threadIdx.x;
    const int wid = tid >> 5;
    const int lane = tid & 31;
    const int i0 = blockIdx.x * 128;
    const int bh = blockIdx.y;
    const size_t base = (size_t)bh * SEQ * HEAD_DIM;

    for (int c = tid; c < 1024; c += 256) {
        const int row = c >> 3, c8 = (c & 7) * 8;
        *(uint4*)&sQ[row * FPAD + c8] =
            *(const uint4*)&Qg[base + (size_t)(i0 + row) * HEAD_DIM + c8];
    }

    float oacc[8][4];
#pragma unroll
    for (int nt = 0; nt < 8; nt++)
#pragma unroll
        for (int c = 0; c < 4; c++) oacc[nt][c] = 0.f;
    float mrow[2] = {-1e30f, -1e30f};
    float lrow[2] = {0.f, 0.f};

    const int r0 = lane >> 2;
    const int nIter = i0 / 64 + 2;

    for (int it = 0; it < nIter; it++) {
        const int kk0 = it * 64;
        for (int c = tid; c < 512; c += 256) {
            const int row = c >> 3, c8 = (c & 7) * 8;
            *(uint4*)&sK[row * FPAD + c8] =
                *(const uint4*)&Kg[base + (size_t)(kk0 + row) * HEAD_DIM + c8];
            *(uint4*)&sVh[row * FPAD + c8] =
                *(const uint4*)&Vgh[base + (size_t)(kk0 + row) * HEAD_DIM + c8];
            *(uint4*)&sVl[row * FPAD + c8] =
                *(const uint4*)&Vgl[base + (size_t)(kk0 + row) * HEAD_DIM + c8];
        }
        __syncthreads();

        // ---- S = Q K^T (single-single fp16) ----
        float sacc[8][4];
#pragma unroll
        for (int nt = 0; nt < 8; nt++)
#pragma unroll
            for (int c = 0; c < 4; c++) sacc[nt][c] = 0.f;

#pragma unroll
        for (int ks = 0; ks < 4; ks++) {
            uint32_t af[4];
            const int qof = (wid * 16 + (lane & 15)) * FPAD + ks * 16 + (lane >> 4) * 8;
            ldsm_x4(af, smem_u32(&sQ[qof]));
            uint32_t bf[8][2];
#pragma unroll
            for (int njp = 0; njp < 4; njp++) {
                const int t = lane >> 3;
                const int kof = (njp * 16 + (t >> 1) * 8 + (lane & 7)) * FPAD +
                                ks * 16 + (t & 1) * 8;
                uint32_t r[4];
                ldsm_x4(r, smem_u32(&sK[kof]));
                bf[njp * 2 + 0][0] = r[0]; bf[njp * 2 + 0][1] = r[1];
                bf[njp * 2 + 1][0] = r[2]; bf[njp * 2 + 1][1] = r[3];
            }
#pragma unroll
            for (int nt = 0; nt < 8; nt++)
                mma16816h(sacc[nt], af, bf[nt]);
        }

        // ---- scale + causal mask + online softmax ----
        const float scale = 0.03125f;
        const bool domask = (kk0 + 63 > i0 + wid * 16);
        float tmax[2] = {-1e30f, -1e30f};
#pragma unroll
        for (int nt = 0; nt < 8; nt++) {
#pragma unroll
            for (int c = 0; c < 4; c++) {
                float s = sacc[nt][c] * scale;
                if (domask) {
                    const int gi = i0 + wid * 16 + r0 + (c >> 1) * 8;
                    const int gj = kk0 + nt * 8 + (lane & 3) * 2 + (c & 1);
                    if (gj > gi) s = -1e30f;
                }
                sacc[nt][c] = s;
                tmax[c >> 1] = fmaxf(tmax[c >> 1], s);
            }
        }
#pragma unroll
        for (int h2 = 0; h2 < 2; h2++) {
            tmax[h2] = fmaxf(tmax[h2], __shfl_xor_sync(0xffffffffu, tmax[h2], 1));
            tmax[h2] = fmaxf(tmax[h2], __shfl_xor_sync(0xffffffffu, tmax[h2], 2));
        }
        float fac[2], mnew[2];
#pragma unroll
        for (int h2 = 0; h2 < 2; h2++) {
            mnew[h2] = fmaxf(mrow[h2], tmax[h2]);
            fac[h2] = __expf(mrow[h2] - mnew[h2]);
            mrow[h2] = mnew[h2];
            lrow[h2] *= fac[h2];
        }
#pragma unroll
        for (int nt = 0; nt < 8; nt++)
#pragma unroll
            for (int c = 0; c < 4; c++) oacc[nt][c] *= fac[c >> 1];

#pragma unroll
        for (int nt = 0; nt < 8; nt++) {
#pragma unroll
            for (int c = 0; c < 4; c++) {
                const float p = __expf(sacc[nt][c] - mnew[c >> 1]);
                sacc[nt][c] = p;
                lrow[c >> 1] += p;
            }
        }

        // ---- pack P into fp16 A fragments ----
        uint32_t pf[4][4];
#pragma unroll
        for (int t = 0; t < 4; t++) {
#pragma unroll
            for (int q = 0; q < 4; q++) {
                const float pa = sacc[2 * t + (q >> 1)][(q & 1) * 2 + 0];
                const float pb = sacc[2 * t + (q >> 1)][(q & 1) * 2 + 1];
                const __half2 h = __floats2half2_rn(pa, pb);
                pf[t][q] = *(const uint32_t*)&h;
            }
        }

        // ---- O += P (Vhi + Vlo), V via ldmatrix.trans ----
#pragma unroll
        for (int ks = 0; ks < 4; ks++) {
            uint32_t bfh[8][2], bfl[8][2];
#pragma unroll
            for (int njp = 0; njp < 4; njp++) {
                const int t = lane >> 3;
                const int vof = (ks * 16 + (t & 1) * 8 + (lane & 7)) * FPAD +
                                njp * 16 + (t >> 1) * 8;
                uint32_t r[4];
                ldsm_x4_t(r, smem_u32(&sVh[vof]));
                bfh[njp * 2 + 0][0] = r[0]; bfh[njp * 2 + 0][1] = r[1];
                bfh[njp * 2 + 1][0] = r[2]; bfh[njp * 2 + 1][1] = r[3];
                ldsm_x4_t(r, smem_u32(&sVl[vof]));
                bfl[njp * 2 + 0][0] = r[0]; bfl[njp * 2 + 0][1] = r[1];
                bfl[njp * 2 + 1][0] = r[2]; bfl[njp * 2 + 1][1] = r[3];
            }
#pragma unroll
            for (int nt = 0; nt < 8; nt++) {
                mma16816h(oacc[nt], pf[ks], bfh[nt]);
                mma16816h(oacc[nt], pf[ks], bfl[nt]);
            }
        }
        __syncthreads();
    }

    // ---- finalize ----
    float inv[2];
#pragma unroll
    for (int h2 = 0; h2 < 2; h2++) {
        float l = lrow[h2];
        l += __shfl_xor_sync(0xffffffffu, l, 1);
        l += __shfl_xor_sync(0xffffffffu, l, 2);
        inv[h2] = 1.f / l;
    }
    const int b = bh >> 4;
    const int h = bh & 15;
#pragma unroll
    for (int nt = 0; nt < 8; nt++) {
#pragma unroll
        for (int half = 0; half < 2; half++) {
            const int gi = i0 + wid * 16 + r0 + half * 8;
            const int d0 = nt * 8 + (lane & 3) * 2;
            const float v0 = oacc[nt][half * 2 + 0] * inv[half];
            const float v1 = oacc[nt][half * 2 + 1] * inv[half];
            const size_t idx = ((size_t)(b * SEQ + gi)) * D_MODEL + h * HEAD_DIM + d0;
            *(__half2*)&Oa[idx] = __floats2half2_rn(v0, v1);
        }
    }
}

// ---------------------------------------------------------------------------
__global__ void __launch_bounds__(256) cvt_kernel(
    const float4* __restrict__ in, __half2* __restrict__ out, int n4)
{
    const int stride = gridDim.x * blockDim.x;
    for (int i = blockIdx.x * blockDim.x + threadIdx.x; i < n4; i += stride) {
        float4 v = in[i];
        out[i * 2 + 0] = __floats2half2_rn(v.x, v.y);
        out[i * 2 + 1] = __floats2half2_rn(v.z, v.w);
    }
}

__global__ void __launch_bounds__(256) wsplit_kernel(
    const float* __restrict__ W, __half* __restrict__ hiT,
    __half* __restrict__ loT)
{
    __shared__ float t[32][33];
    const int n0 = blockIdx.x * 32, k0 = blockIdx.y * 32;
    const int tx = threadIdx.x & 31, ty = threadIdx.x >> 5;
#pragma unroll
    for (int r = 0; r < 4; r++) {
        const int kl = ty + r * 8;
        t[kl][tx] = W[(size_t)(k0 + kl) * D_MODEL + n0 + tx];
    }
    __syncthreads();
#pragma unroll
    for (int r = 0; r < 4; r++) {
        const int nl = ty + r * 8;
        const float x = t[tx][nl];
        const __half h = __float2half_rn(x);
        hiT[(size_t)(n0 + nl) * D_MODEL + k0 + tx] = h;
        loT[(size_t)(n0 + nl) * D_MODEL + k0 + tx] =
            __float2half_rn(x - __half2float(h));
    }
}

// ---------------------------------------------------------------------------
extern "C" void kernel_launch(void* const* d_in, const int* in_sizes, int n_in,
                              void* d_out, int out_size)
{
    const float* q  = (const float*)d_in[0];
    const float* k  = (const float*)d_in[1];
    const float* v  = (const float*)d_in[2];
    const float* Wq = (const float*)d_in[3];
    const float* bq = (const float*)d_in[4];
    const float* Wk = (const float*)d_in[5];
    const float* bk = (const float*)d_in[6];
    const float* Wv = (const float*)d_in[7];
    const float* bv = (const float*)d_in[8];
    const float* Wo = (const float*)d_in[9];
    const float* bo = (const float*)d_in[10];

    __half *q16, *k16, *v16, *af, *Q16, *K16, *V16h, *V16l;
    __half *wqh, *wql, *wkh, *wkl, *wvh, *wvl, *woh, *wol;
    cudaGetSymbolAddress((void**)&q16, g_q16);
    cudaGetSymbolAddress((void**)&k16, g_k16);
    cudaGetSymbolAddress((void**)&v16, g_v16);
    cudaGetSymbolAddress((void**)&af, g_af);
    cudaGetSymbolAddress((void**)&Q16, g_Q16);
    cudaGetSymbolAddress((void**)&K16, g_K16);
    cudaGetSymbolAddress((void**)&V16h, g_V16h);
    cudaGetSymbolAddress((void**)&V16l, g_V16l);
    cudaGetSymbolAddress((void**)&wqh, g_Wqh); cudaGetSymbolAddress((void**)&wql, g_Wql);
    cudaGetSymbolAddress((void**)&wkh, g_Wkh); cudaGetSymbolAddress((void**)&wkl, g_Wkl);
    cudaGetSymbolAddress((void**)&wvh, g_Wvh); cudaGetSymbolAddress((void**)&wvl, g_Wvl);
    cudaGetSymbolAddress((void**)&woh, g_Woh); cudaGetSymbolAddress((void**)&wol, g_Wol);

    cudaFuncSetAttribute(flash_kernel,
                         cudaFuncAttributeMaxDynamicSharedMemorySize, FLASH_SMEM);
    cudaFuncSetAttribute(gemm_mma_kernel<0>,
                         cudaFuncAttributeMaxDynamicSharedMemorySize, G3_SMEM);
    cudaFuncSetAttribute(gemm_mma_kernel<1>,
                         cudaFuncAttributeMaxDynamicSharedMemorySize, G3_SMEM);

    dim3 gW(32, 32);
    wsplit_kernel<<<gW, 256>>>(Wq, wqh, wql);
    wsplit_kernel<<<gW, 256>>>(Wk, wkh, wkl);
    wsplit_kernel<<<gW, 256>>>(Wv, wvh, wvl);
    wsplit_kernel<<<gW, 256>>>(Wo, woh, wol);

    const int n4 = MROWS * D_MODEL / 4;
    cvt_kernel<<<2048, 256>>>((const float4*)q, (__half2*)q16, n4);
    cvt_kernel<<<2048, 256>>>((const float4*)k, (__half2*)k16, n4);
    cvt_kernel<<<2048, 256>>>((const float4*)v, (__half2*)v16, n4);

    // Fused QKV projections: z=0 -> Q single, z=1 -> K single, z=2 -> V hi/lo
    dim3 gQKV(GN / 256, MROWS / 128, 3);
    gemm_mma_kernel<1><<<gQKV, 512, G3_SMEM>>>(
        q16, k16, v16,
        wqh, wql, wkh, wkl, wvh, wvl,
        bq, bk, bv,
        Q16, K16, V16h, V16l,
        nullptr);

    flash_kernel<<<dim3(SEQ / 128, BH), 256, FLASH_SMEM>>>(Q16, K16, V16h, V16l,
                                                           af);

    // Output projection -> fp32 d_out
    dim3 gO(GN / 256, MROWS / 128, 1);
    gemm_mma_kernel<0><<<gO, 512, G3_SMEM>>>(
        af, nullptr, nullptr,
        woh, wol, nullptr, nullptr, nullptr, nullptr,
        bo, nullptr, nullptr,
        nullptr, nullptr, nullptr, nullptr,
        (float*)d_out);
}

// round 10
// speedup vs baseline: 6.3892x; 1.3698x over previous
#include <cuda_runtime.h>
#include <cuda_bf16.h>
#include <cuda_fp16.h>
#include <cstdint>

#define D_MODEL 1024
#define N_HEAD  16
#define HEAD_DIM 64
#define BATCH   4
#define SEQ     2048
#define BH      (BATCH * N_HEAD)          // 64
#define MROWS   (BATCH * SEQ)             // 8192
#define GK      1024
#define GN      1024

// ---------------------------------------------------------------------------
// Scratch (device globals)
// ---------------------------------------------------------------------------
__device__ __half g_q16[MROWS * D_MODEL], g_k16[MROWS * D_MODEL], g_v16[MROWS * D_MODEL];
__device__ __half g_af[MROWS * D_MODEL];     // flash output, fp16
// projected Q/K single fp16, V fp16 hi/lo, heads layout [bh][s][hd]
__device__ __half g_Q16[BH * SEQ * HEAD_DIM], g_K16[BH * SEQ * HEAD_DIM];
__device__ __half g_V16h[BH * SEQ * HEAD_DIM], g_V16l[BH * SEQ * HEAD_DIM];
// transposed weights [N][K], single fp16
__device__ __half g_Wq16[D_MODEL * D_MODEL], g_Wk16[D_MODEL * D_MODEL];
__device__ __half g_Wv16[D_MODEL * D_MODEL], g_Wo16[D_MODEL * D_MODEL];

// ---------------------------------------------------------------------------
__device__ __forceinline__ uint32_t smem_u32(const void* p) {
    uint32_t a;
    asm("{ .reg .u64 t; cvta.to.shared.u64 t, %1; cvt.u32.u64 %0, t; }"
        : "=r"(a) : "l"(p));
    return a;
}

#define CP_ASYNC16(dst_u32, src_ptr) \
    asm volatile("cp.async.cg.shared.global [%0], [%1], 16;" \
        :: "r"(dst_u32), "l"(src_ptr))

__device__ __forceinline__ void ldsm_x4(uint32_t* r, uint32_t addr) {
    asm volatile("ldmatrix.sync.aligned.m8n8.x4.shared.b16 {%0,%1,%2,%3}, [%4];"
        : "=r"(r[0]), "=r"(r[1]), "=r"(r[2]), "=r"(r[3]) : "r"(addr));
}

__device__ __forceinline__ void ldsm_x4_t(uint32_t* r, uint32_t addr) {
    asm volatile("ldmatrix.sync.aligned.m8n8.x4.trans.shared.b16 {%0,%1,%2,%3}, [%4];"
        : "=r"(r[0]), "=r"(r[1]), "=r"(r[2]), "=r"(r[3]) : "r"(addr));
}

__device__ __forceinline__ void mma16816h(float* d, const uint32_t* a,
                                          const uint32_t* b) {
    asm volatile(
        "mma.sync.aligned.m16n8k16.row.col.f32.f16.f16.f32 "
        "{%0,%1,%2,%3}, {%4,%5,%6,%7}, {%8,%9}, {%0,%1,%2,%3};"
        : "+f"(d[0]), "+f"(d[1]), "+f"(d[2]), "+f"(d[3])
        : "r"(a[0]), "r"(a[1]), "r"(a[2]), "r"(a[3]), "r"(b[0]), "r"(b[1]));
}

// ---------------------------------------------------------------------------
// fp16 single-term GEMM: C = A * W + bias.  512 threads, BM=128 BN=256 BK=32,
// 4-stage cp.async pipeline.  gridDim.z selects projection.
// MODE 1: z<2 -> single fp16 heads layout; z==2 -> fp16 hi/lo heads layout.
// MODE 0: fp32 row-major out.
// smem/stage: A 128x40 + B 256x40 fp16 = 30720 B; 4 stages = 122880 B.
// ---------------------------------------------------------------------------
#define NSLABS  32
#define S_A     (128 * 40)
#define S_B     (256 * 40)
#define S_ST    (S_A + S_B)
#define G4_SMEM (4 * S_ST * 2)   // 122880

template <int MODE>
__global__ void __launch_bounds__(512) gemm_mma_kernel(
    const __half* __restrict__ A0, const __half* __restrict__ A1,
    const __half* __restrict__ A2,
    const __half* __restrict__ B0, const __half* __restrict__ B1,
    const __half* __restrict__ B2,
    const float* __restrict__ bias0, const float* __restrict__ bias1,
    const float* __restrict__ bias2,
    __half* __restrict__ OutS0, __half* __restrict__ OutS1,
    __half* __restrict__ Out2h, __half* __restrict__ Out2l,
    float* __restrict__ out32)
{
    extern __shared__ __half gsm[];

    const int z = blockIdx.z;
    const __half* Ag = (z == 0) ? A0 : (z == 1) ? A1 : A2;
    const __half* Bg = (z == 0) ? B0 : (z == 1) ? B1 : B2;
    const float* bias = (z == 0) ? bias0 : (z == 1) ? bias1 : bias2;

    const int tid = threadIdx.x;
    const int wid = tid >> 5;
    const int lane = tid & 31;
    const int m0 = blockIdx.y * 128;
    const int n0 = blockIdx.x * 256;
    const int wm = (wid & 1) * 64;
    const int wn = (wid >> 1) * 32;

    float acc[4][4][4];
#pragma unroll
    for (int i = 0; i < 4; i++)
#pragma unroll
        for (int j = 0; j < 4; j++)
#pragma unroll
            for (int c = 0; c < 4; c++) acc[i][j][c] = 0.f;

    const int ldrow = tid >> 2;            // 0..127
    const int ldcol = (tid & 3) * 8;

    auto issue_load = [&](int stage, int slab) {
        const int k0 = slab << 5;
        __half* sA = gsm + stage * S_ST;
        __half* sB = sA + S_A;
        {
            const size_t ga = (size_t)(m0 + ldrow) * GK + k0 + ldcol;
            CP_ASYNC16(smem_u32(&sA[ldrow * 40 + ldcol]), Ag + ga);
        }
#pragma unroll
        for (int r = 0; r < 2; r++) {
            const int row = ldrow + r * 128;
            const size_t gb = (size_t)(n0 + row) * GK + k0 + ldcol;
            CP_ASYNC16(smem_u32(&sB[row * 40 + ldcol]), Bg + gb);
        }
        asm volatile("cp.async.commit_group;" ::: "memory");
    };

    issue_load(0, 0);
    issue_load(1, 1);
    issue_load(2, 2);

    int st = 0;
    for (int i = 0; i < NSLABS; i++) {
        if (i + 3 < NSLABS) {
            issue_load((st + 3) & 3, i + 3);
            asm volatile("cp.async.wait_group 3;" ::: "memory");
        } else if (i + 2 < NSLABS) {
            asm volatile("cp.async.wait_group 2;" ::: "memory");
        } else if (i + 1 < NSLABS) {
            asm volatile("cp.async.wait_group 1;" ::: "memory");
        } else {
            asm volatile("cp.async.wait_group 0;" ::: "memory");
        }
        __syncthreads();

        const __half* sA = gsm + st * S_ST;
        const __half* sB = sA + S_A;

#pragma unroll
        for (int ks = 0; ks < 2; ks++) {
            uint32_t bf[4][2];
#pragma unroll
            for (int njp = 0; njp < 2; njp++) {
                const int t = lane >> 3;
                const int sof = (wn + njp * 16 + (t >> 1) * 8 + (lane & 7)) * 40 +
                                ks * 16 + (t & 1) * 8;
                uint32_t r[4];
                ldsm_x4(r, smem_u32(&sB[sof]));
                bf[njp * 2 + 0][0] = r[0]; bf[njp * 2 + 0][1] = r[1];
                bf[njp * 2 + 1][0] = r[2]; bf[njp * 2 + 1][1] = r[3];
            }
#pragma unroll
            for (int mi = 0; mi < 4; mi++) {
                uint32_t af[4];
                const int sof = (wm + mi * 16 + (lane & 15)) * 40 +
                                ks * 16 + (lane >> 4) * 8;
                ldsm_x4(af, smem_u32(&sA[sof]));
#pragma unroll
                for (int nj = 0; nj < 4; nj++)
                    mma16816h(acc[mi][nj], af, bf[nj]);
            }
        }
        __syncthreads();
        st = (st + 1) & 3;
    }

#pragma unroll
    for (int mi = 0; mi < 4; mi++) {
#pragma unroll
        for (int nj = 0; nj < 4; nj++) {
            const int n = n0 + wn + nj * 8 + (lane & 3) * 2;
            const float b0 = bias[n], b1 = bias[n + 1];
#pragma unroll
            for (int half = 0; half < 2; half++) {
                const int m = m0 + wm + mi * 16 + (lane >> 2) + half * 8;
                const float v0 = acc[mi][nj][half * 2 + 0] + b0;
                const float v1 = acc[mi][nj][half * 2 + 1] + b1;
                if (MODE == 1) {
                    const int b = m >> 11;
                    const int s = m & (SEQ - 1);
                    const int h = n >> 6;
                    const int d = n & 63;
                    const size_t idx =
                        ((((size_t)b * N_HEAD + h) * SEQ) + s) * HEAD_DIM + d;
                    if (z < 2) {
                        __half* dst = (z == 0) ? OutS0 : OutS1;
                        *(__half2*)&dst[idx] = __floats2half2_rn(v0, v1);
                    } else {
                        const __half h0 = __float2half_rn(v0);
                        const __half h1 = __float2half_rn(v1);
                        __half2 hv; hv.x = h0; hv.y = h1;
                        __half2 lv;
                        lv.x = __float2half_rn(v0 - __half2float(h0));
                        lv.y = __float2half_rn(v1 - __half2float(h1));
                        *(__half2*)&Out2h[idx] = hv;
                        *(__half2*)&Out2l[idx] = lv;
                    }
                } else {
                    *(float2*)&out32[(size_t)m * GN + n] = make_float2(v0, v1);
                }
            }
        }
    }
}

// ---------------------------------------------------------------------------
// Fused flash attention, fp16 asymmetric precision (unchanged from round 9).
// ---------------------------------------------------------------------------
#define FPAD 72
#define FLASH_SMEM ((128 * FPAD + 3 * 64 * FPAD) * 2)   // 46080

__global__ void __launch_bounds__(256) flash_kernel(
    const __half* __restrict__ Qg, const __half* __restrict__ Kg,
    const __half* __restrict__ Vgh, const __half* __restrict__ Vgl,
    __half* __restrict__ Oa)
{
    extern __shared__ __half fsm[];
    __half* sQ  = fsm;
    __half* sK  = sQ + 128 * FPAD;
    __half* sVh = sK + 64 * FPAD;
    __half* sVl = sVh + 64 * FPAD;

    const int tid = threadIdx.x;
    const int wid = tid >> 5;
    const int lane = tid & 31;
    const int i0 = blockIdx.x * 128;
    const int bh = blockIdx.y;
    const size_t base = (size_t)bh * SEQ * HEAD_DIM;

    for (int c = tid; c < 1024; c += 256) {
        const int row = c >> 3, c8 = (c & 7) * 8;
        *(uint4*)&sQ[row * FPAD + c8] =
            *(const uint4*)&Qg[base + (size_t)(i0 + row) * HEAD_DIM + c8];
    }

    float oacc[8][4];
#pragma unroll
    for (int nt = 0; nt < 8; nt++)
#pragma unroll
        for (int c = 0; c < 4; c++) oacc[nt][c] = 0.f;
    float mrow[2] = {-1e30f, -1e30f};
    float lrow[2] = {0.f, 0.f};

    const int r0 = lane >> 2;
    const int nIter = i0 / 64 + 2;

    for (int it = 0; it < nIter; it++) {
        const int kk0 = it * 64;
        for (int c = tid; c < 512; c += 256) {
            const int row = c >> 3, c8 = (c & 7) * 8;
            *(uint4*)&sK[row * FPAD + c8] =
                *(const uint4*)&Kg[base + (size_t)(kk0 + row) * HEAD_DIM + c8];
            *(uint4*)&sVh[row * FPAD + c8] =
                *(const uint4*)&Vgh[base + (size_t)(kk0 + row) * HEAD_DIM + c8];
            *(uint4*)&sVl[row * FPAD + c8] =
                *(const uint4*)&Vgl[base + (size_t)(kk0 + row) * HEAD_DIM + c8];
        }
        __syncthreads();

        float sacc[8][4];
#pragma unroll
        for (int nt = 0; nt < 8; nt++)
#pragma unroll
            for (int c = 0; c < 4; c++) sacc[nt][c] = 0.f;

#pragma unroll
        for (int ks = 0; ks < 4; ks++) {
            uint32_t af[4];
            const int qof = (wid * 16 + (lane & 15)) * FPAD + ks * 16 + (lane >> 4) * 8;
            ldsm_x4(af, smem_u32(&sQ[qof]));
            uint32_t bf[8][2];
#pragma unroll
            for (int njp = 0; njp < 4; njp++) {
                const int t = lane >> 3;
                const int kof = (njp * 16 + (t >> 1) * 8 + (lane & 7)) * FPAD +
                                ks * 16 + (t & 1) * 8;
                uint32_t r[4];
                ldsm_x4(r, smem_u32(&sK[kof]));
                bf[njp * 2 + 0][0] = r[0]; bf[njp * 2 + 0][1] = r[1];
                bf[njp * 2 + 1][0] = r[2]; bf[njp * 2 + 1][1] = r[3];
            }
#pragma unroll
            for (int nt = 0; nt < 8; nt++)
                mma16816h(sacc[nt], af, bf[nt]);
        }

        const float scale = 0.03125f;
        const bool domask = (kk0 + 63 > i0 + wid * 16);
        float tmax[2] = {-1e30f, -1e30f};
#pragma unroll
        for (int nt = 0; nt < 8; nt++) {
#pragma unroll
            for (int c = 0; c < 4; c++) {
                float s = sacc[nt][c] * scale;
                if (domask) {
                    const int gi = i0 + wid * 16 + r0 + (c >> 1) * 8;
                    const int gj = kk0 + nt * 8 + (lane & 3) * 2 + (c & 1);
                    if (gj > gi) s = -1e30f;
                }
                sacc[nt][c] = s;
                tmax[c >> 1] = fmaxf(tmax[c >> 1], s);
            }
        }
#pragma unroll
        for (int h2 = 0; h2 < 2; h2++) {
            tmax[h2] = fmaxf(tmax[h2], __shfl_xor_sync(0xffffffffu, tmax[h2], 1));
            tmax[h2] = fmaxf(tmax[h2], __shfl_xor_sync(0xffffffffu, tmax[h2], 2));
        }
        float fac[2], mnew[2];
#pragma unroll
        for (int h2 = 0; h2 < 2; h2++) {
            mnew[h2] = fmaxf(mrow[h2], tmax[h2]);
            fac[h2] = __expf(mrow[h2] - mnew[h2]);
            mrow[h2] = mnew[h2];
            lrow[h2] *= fac[h2];
        }
#pragma unroll
        for (int nt = 0; nt < 8; nt++)
#pragma unroll
            for (int c = 0; c < 4; c++) oacc[nt][c] *= fac[c >> 1];

#pragma unroll
        for (int nt = 0; nt < 8; nt++) {
#pragma unroll
            for (int c = 0; c < 4; c++) {
                const float p = __expf(sacc[nt][c] - mnew[c >> 1]);
                sacc[nt][c] = p;
                lrow[c >> 1] += p;
            }
        }

        uint32_t pf[4][4];
#pragma unroll
        for (int t = 0; t < 4; t++) {
#pragma unroll
            for (int q = 0; q < 4; q++) {
                const float pa = sacc[2 * t + (q >> 1)][(q & 1) * 2 + 0];
                const float pb = sacc[2 * t + (q >> 1)][(q & 1) * 2 + 1];
                const __half2 h = __floats2half2_rn(pa, pb);
                pf[t][q] = *(const uint32_t*)&h;
            }
        }

#pragma unroll
        for (int ks = 0; ks < 4; ks++) {
            uint32_t bfh[8][2], bfl[8][2];
#pragma unroll
            for (int njp = 0; njp < 4; njp++) {
                const int t = lane >> 3;
                const int vof = (ks * 16 + (t & 1) * 8 + (lane & 7)) * FPAD +
                                njp * 16 + (t >> 1) * 8;
                uint32_t r[4];
                ldsm_x4_t(r, smem_u32(&sVh[vof]));
                bfh[njp * 2 + 0][0] = r[0]; bfh[njp * 2 + 0][1] = r[1];
                bfh[njp * 2 + 1][0] = r[2]; bfh[njp * 2 + 1][1] = r[3];
                ldsm_x4_t(r, smem_u32(&sVl[vof]));
                bfl[njp * 2 + 0][0] = r[0]; bfl[njp * 2 + 0][1] = r[1];
                bfl[njp * 2 + 1][0] = r[2]; bfl[njp * 2 + 1][1] = r[3];
            }
#pragma unroll
            for (int nt = 0; nt < 8; nt++) {
                mma16816h(oacc[nt], pf[ks], bfh[nt]);
                mma16816h(oacc[nt], pf[ks], bfl[nt]);
            }
        }
        __syncthreads();
    }

    float inv[2];
#pragma unroll
    for (int h2 = 0; h2 < 2; h2++) {
        float l = lrow[h2];
        l += __shfl_xor_sync(0xffffffffu, l, 1);
        l += __shfl_xor_sync(0xffffffffu, l, 2);
        inv[h2] = 1.f / l;
    }
    const int b = bh >> 4;
    const int h = bh & 15;
#pragma unroll
    for (int nt = 0; nt < 8; nt++) {
#pragma unroll
        for (int half = 0; half < 2; half++) {
            const int gi = i0 + wid * 16 + r0 + half * 8;
            const int d0 = nt * 8 + (lane & 3) * 2;
            const float v0 = oacc[nt][half * 2 + 0] * inv[half];
            const float v1 = oacc[nt][half * 2 + 1] * inv[half];
            const size_t idx = ((size_t)(b * SEQ + gi)) * D_MODEL + h * HEAD_DIM + d0;
            *(__half2*)&Oa[idx] = __floats2half2_rn(v0, v1);
        }
    }
}

// ---------------------------------------------------------------------------
// fp32 -> fp16 convert; grid.z selects which of q/k/v
// ---------------------------------------------------------------------------
__global__ void __launch_bounds__(256) cvt_kernel(
    const float4* __restrict__ in0, const float4* __restrict__ in1,
    const float4* __restrict__ in2,
    __half2* __restrict__ o0, __half2* __restrict__ o1,
    __half2* __restrict__ o2, int n4)
{
    const float4* in = (blockIdx.z == 0) ? in0 : (blockIdx.z == 1) ? in1 : in2;
    __half2* out = (blockIdx.z == 0) ? o0 : (blockIdx.z == 1) ? o1 : o2;
    const int stride = gridDim.x * blockDim.x;
    for (int i = blockIdx.x * blockDim.x + threadIdx.x; i < n4; i += stride) {
        float4 v = in[i];
        out[i * 2 + 0] = __floats2half2_rn(v.x, v.y);
        out[i * 2 + 1] = __floats2half2_rn(v.z, v.w);
    }
}

// ---------------------------------------------------------------------------
// W[K,N] -> Wt [N,K] fp16 (transpose + convert)
// ---------------------------------------------------------------------------
__global__ void __launch_bounds__(256) wt_kernel(
    const float* __restrict__ W, __half* __restrict__ Wt)
{
    __shared__ float t[32][33];
    const int n0 = blockIdx.x * 32, k0 = blockIdx.y * 32;
    const int tx = threadIdx.x & 31, ty = threadIdx.x >> 5;
#pragma unroll
    for (int r = 0; r < 4; r++) {
        const int kl = ty + r * 8;
        t[kl][tx] = W[(size_t)(k0 + kl) * D_MODEL + n0 + tx];
    }
    __syncthreads();
#pragma unroll
    for (int r = 0; r < 4; r++) {
        const int nl = ty + r * 8;
        Wt[(size_t)(n0 + nl) * D_MODEL + k0 + tx] = __float2half_rn(t[tx][nl]);
    }
}

// ---------------------------------------------------------------------------
extern "C" void kernel_launch(void* const* d_in, const int* in_sizes, int n_in,
                              void* d_out, int out_size)
{
    const float* q  = (const float*)d_in[0];
    const float* k  = (const float*)d_in[1];
    const float* v  = (const float*)d_in[2];
    const float* Wq = (const float*)d_in[3];
    const float* bq = (const float*)d_in[4];
    const float* Wk = (const float*)d_in[5];
    const float* bk = (const float*)d_in[6];
    const float* Wv = (const float*)d_in[7];
    const float* bv = (const float*)d_in[8];
    const float* Wo = (const float*)d_in[9];
    const float* bo = (const float*)d_in[10];

    __half *q16, *k16, *v16, *af, *Q16, *K16, *V16h, *V16l;
    __half *wq, *wk, *wv, *wo;
    cudaGetSymbolAddress((void**)&q16, g_q16);
    cudaGetSymbolAddress((void**)&k16, g_k16);
    cudaGetSymbolAddress((void**)&v16, g_v16);
    cudaGetSymbolAddress((void**)&af, g_af);
    cudaGetSymbolAddress((void**)&Q16, g_Q16);
    cudaGetSymbolAddress((void**)&K16, g_K16);
    cudaGetSymbolAddress((void**)&V16h, g_V16h);
    cudaGetSymbolAddress((void**)&V16l, g_V16l);
    cudaGetSymbolAddress((void**)&wq, g_Wq16);
    cudaGetSymbolAddress((void**)&wk, g_Wk16);
    cudaGetSymbolAddress((void**)&wv, g_Wv16);
    cudaGetSymbolAddress((void**)&wo, g_Wo16);

    cudaFuncSetAttribute(flash_kernel,
                         cudaFuncAttributeMaxDynamicSharedMemorySize, FLASH_SMEM);
    cudaFuncSetAttribute(gemm_mma_kernel<0>,
                         cudaFuncAttributeMaxDynamicSharedMemorySize, G4_SMEM);
    cudaFuncSetAttribute(gemm_mma_kernel<1>,
                         cudaFuncAttributeMaxDynamicSharedMemorySize, G4_SMEM);

    dim3 gW(32, 32);
    wt_kernel<<<gW, 256>>>(Wq, wq);
    wt_kernel<<<gW, 256>>>(Wk, wk);
    wt_kernel<<<gW, 256>>>(Wv, wv);
    wt_kernel<<<gW, 256>>>(Wo, wo);

    const int n4 = MROWS * D_MODEL / 4;
    cvt_kernel<<<dim3(1024, 1, 3), 256>>>(
        (const float4*)q, (const float4*)k, (const float4*)v,
        (__half2*)q16, (__half2*)k16, (__half2*)v16, n4);

    // Fused QKV projections: z=0 -> Q single, z=1 -> K single, z=2 -> V hi/lo
    dim3 gQKV(GN / 256, MROWS / 128, 3);
    gemm_mma_kernel<1><<<gQKV, 512, G4_SMEM>>>(
        q16, k16, v16,
        wq, wk, wv,
        bq, bk, bv,
        Q16, K16, V16h, V16l,
        nullptr);

    flash_kernel<<<dim3(SEQ / 128, BH), 256, FLASH_SMEM>>>(Q16, K16, V16h, V16l,
                                                           af);

    // Output projection -> fp32 d_out
    dim3 gO(GN / 256, MROWS / 128, 1);
    gemm_mma_kernel<0><<<gO, 512, G4_SMEM>>>(
        af, nullptr, nullptr,
        wo, nullptr, nullptr,
        bo, nullptr, nullptr,
        nullptr, nullptr, nullptr, nullptr,
        (float*)d_out);
}

// round 11
// speedup vs baseline: 7.8033x; 1.2213x over previous
#include <cuda_runtime.h>
#include <cuda_bf16.h>
#include <cuda_fp16.h>
#include <cstdint>

#define D_MODEL 1024
#define N_HEAD  16
#define HEAD_DIM 64
#define BATCH   4
#define SEQ     2048
#define BH      (BATCH * N_HEAD)          // 64
#define MROWS   (BATCH * SEQ)             // 8192
#define GK      1024
#define GN      1024

// ---------------------------------------------------------------------------
// Scratch (device globals)
// ---------------------------------------------------------------------------
__device__ __half g_q16[MROWS * D_MODEL], g_k16[MROWS * D_MODEL], g_v16[MROWS * D_MODEL];
__device__ __half g_af[MROWS * D_MODEL];     // flash output, fp16
// projected Q/K/V single fp16, heads layout [bh][s][hd]
__device__ __half g_Q16[BH * SEQ * HEAD_DIM], g_K16[BH * SEQ * HEAD_DIM];
__device__ __half g_V16[BH * SEQ * HEAD_DIM];
// transposed weights [N][K], single fp16
__device__ __half g_Wq16[D_MODEL * D_MODEL], g_Wk16[D_MODEL * D_MODEL];
__device__ __half g_Wv16[D_MODEL * D_MODEL], g_Wo16[D_MODEL * D_MODEL];

// ---------------------------------------------------------------------------
__device__ __forceinline__ uint32_t smem_u32(const void* p) {
    uint32_t a;
    asm("{ .reg .u64 t; cvta.to.shared.u64 t, %1; cvt.u32.u64 %0, t; }"
        : "=r"(a) : "l"(p));
    return a;
}

#define CP_ASYNC16(dst_u32, src_ptr) \
    asm volatile("cp.async.cg.shared.global [%0], [%1], 16;" \
        :: "r"(dst_u32), "l"(src_ptr))

__device__ __forceinline__ void ldsm_x4(uint32_t* r, uint32_t addr) {
    asm volatile("ldmatrix.sync.aligned.m8n8.x4.shared.b16 {%0,%1,%2,%3}, [%4];"
        : "=r"(r[0]), "=r"(r[1]), "=r"(r[2]), "=r"(r[3]) : "r"(addr));
}

__device__ __forceinline__ void ldsm_x4_t(uint32_t* r, uint32_t addr) {
    asm volatile("ldmatrix.sync.aligned.m8n8.x4.trans.shared.b16 {%0,%1,%2,%3}, [%4];"
        : "=r"(r[0]), "=r"(r[1]), "=r"(r[2]), "=r"(r[3]) : "r"(addr));
}

__device__ __forceinline__ void mma16816h(float* d, const uint32_t* a,
                                          const uint32_t* b) {
    asm volatile(
        "mma.sync.aligned.m16n8k16.row.col.f32.f16.f16.f32 "
        "{%0,%1,%2,%3}, {%4,%5,%6,%7}, {%8,%9}, {%0,%1,%2,%3};"
        : "+f"(d[0]), "+f"(d[1]), "+f"(d[2]), "+f"(d[3])
        : "r"(a[0]), "r"(a[1]), "r"(a[2]), "r"(a[3]), "r"(b[0]), "r"(b[1]));
}

// ---------------------------------------------------------------------------
// fp16 single-term GEMM: C = A * W + bias.  256 threads, BM=128 BN=128 BK=32,
// 4-stage cp.async pipeline, 81.9 KB smem -> 2 CTAs/SM.
// gridDim.z selects projection.  MODE 1: single fp16 heads layout out.
// MODE 0: fp32 row-major out.
// ---------------------------------------------------------------------------
#define NSLABS  32
#define S_A     (128 * 40)
#define S_ST    (2 * S_A)                 // A + B per stage (elements)
#define G4_SMEM (4 * S_ST * 2)            // 81920 bytes

template <int MODE>
__global__ void __launch_bounds__(256) gemm_mma_kernel(
    const __half* __restrict__ A0, const __half* __restrict__ A1,
    const __half* __restrict__ A2,
    const __half* __restrict__ B0, const __half* __restrict__ B1,
    const __half* __restrict__ B2,
    const float* __restrict__ bias0, const float* __restrict__ bias1,
    const float* __restrict__ bias2,
    __half* __restrict__ O0, __half* __restrict__ O1,
    __half* __restrict__ O2,
    float* __restrict__ out32)
{
    extern __shared__ __half gsm[];

    const int z = blockIdx.z;
    const __half* Ag = (z == 0) ? A0 : (z == 1) ? A1 : A2;
    const __half* Bg = (z == 0) ? B0 : (z == 1) ? B1 : B2;
    const float* bias = (z == 0) ? bias0 : (z == 1) ? bias1 : bias2;
    __half* outp = (z == 0) ? O0 : (z == 1) ? O1 : O2;

    const int tid = threadIdx.x;
    const int wid = tid >> 5;
    const int lane = tid & 31;
    const int m0 = blockIdx.y * 128;
    const int n0 = blockIdx.x * 128;
    const int wm = (wid & 1) * 64;
    const int wn = (wid >> 1) * 32;

    float acc[4][4][4];
#pragma unroll
    for (int i = 0; i < 4; i++)
#pragma unroll
        for (int j = 0; j < 4; j++)
#pragma unroll
            for (int c = 0; c < 4; c++) acc[i][j][c] = 0.f;

    const int ldrow = tid >> 2;            // 0..63 (+64)
    const int ldcol = (tid & 3) * 8;       // 0,8,16,24

    auto issue_load = [&](int stage, int slab) {
        const int k0 = slab << 5;
        __half* sA = gsm + stage * S_ST;
        __half* sB = sA + S_A;
#pragma unroll
        for (int r = 0; r < 2; r++) {
            const int row = ldrow + r * 64;
            const size_t ga = (size_t)(m0 + row) * GK + k0 + ldcol;
            const size_t gb = (size_t)(n0 + row) * GK + k0 + ldcol;
            CP_ASYNC16(smem_u32(&sA[row * 40 + ldcol]), Ag + ga);
            CP_ASYNC16(smem_u32(&sB[row * 40 + ldcol]), Bg + gb);
        }
        asm volatile("cp.async.commit_group;" ::: "memory");
    };

    issue_load(0, 0);
    issue_load(1, 1);
    issue_load(2, 2);

    int st = 0;
    for (int i = 0; i < NSLABS; i++) {
        if (i + 3 < NSLABS) {
            issue_load((st + 3) & 3, i + 3);
            asm volatile("cp.async.wait_group 3;" ::: "memory");
        } else if (i + 2 < NSLABS) {
            asm volatile("cp.async.wait_group 2;" ::: "memory");
        } else if (i + 1 < NSLABS) {
            asm volatile("cp.async.wait_group 1;" ::: "memory");
        } else {
            asm volatile("cp.async.wait_group 0;" ::: "memory");
        }
        __syncthreads();

        const __half* sA = gsm + st * S_ST;
        const __half* sB = sA + S_A;

#pragma unroll
        for (int ks = 0; ks < 2; ks++) {
            uint32_t bf[4][2];
#pragma unroll
            for (int njp = 0; njp < 2; njp++) {
                const int t = lane >> 3;
                const int sof = (wn + njp * 16 + (t >> 1) * 8 + (lane & 7)) * 40 +
                                ks * 16 + (t & 1) * 8;
                uint32_t r[4];
                ldsm_x4(r, smem_u32(&sB[sof]));
                bf[njp * 2 + 0][0] = r[0]; bf[njp * 2 + 0][1] = r[1];
                bf[njp * 2 + 1][0] = r[2]; bf[njp * 2 + 1][1] = r[3];
            }
#pragma unroll
            for (int mi = 0; mi < 4; mi++) {
                uint32_t af[4];
                const int sof = (wm + mi * 16 + (lane & 15)) * 40 +
                                ks * 16 + (lane >> 4) * 8;
                ldsm_x4(af, smem_u32(&sA[sof]));
#pragma unroll
                for (int nj = 0; nj < 4; nj++)
                    mma16816h(acc[mi][nj], af, bf[nj]);
            }
        }
        __syncthreads();
        st = (st + 1) & 3;
    }

#pragma unroll
    for (int mi = 0; mi < 4; mi++) {
#pragma unroll
        for (int nj = 0; nj < 4; nj++) {
            const int n = n0 + wn + nj * 8 + (lane & 3) * 2;
            const float b0 = bias[n], b1 = bias[n + 1];
#pragma unroll
            for (int half = 0; half < 2; half++) {
                const int m = m0 + wm + mi * 16 + (lane >> 2) + half * 8;
                const float v0 = acc[mi][nj][half * 2 + 0] + b0;
                const float v1 = acc[mi][nj][half * 2 + 1] + b1;
                if (MODE == 1) {
                    const int b = m >> 11;
                    const int s = m & (SEQ - 1);
                    const int h = n >> 6;
                    const int d = n & 63;
                    const size_t idx =
                        ((((size_t)b * N_HEAD + h) * SEQ) + s) * HEAD_DIM + d;
                    *(__half2*)&outp[idx] = __floats2half2_rn(v0, v1);
                } else {
                    *(float2*)&out32[(size_t)m * GN + n] = make_float2(v0, v1);
                }
            }
        }
    }
}

// ---------------------------------------------------------------------------
// Fused flash attention, all-fp16 (Q,K,V,P single fp16).
// S = Q K^T (1 MMA set); PV = P V (1 MMA set).
// grid (SEQ/128, BH), 256 threads.
// ---------------------------------------------------------------------------
#define FPAD 72
#define FLASH_SMEM ((128 * FPAD + 2 * 64 * FPAD) * 2)   // 36864

__global__ void __launch_bounds__(256) flash_kernel(
    const __half* __restrict__ Qg, const __half* __restrict__ Kg,
    const __half* __restrict__ Vg, __half* __restrict__ Oa)
{
    extern __shared__ __half fsm[];
    __half* sQ = fsm;                        // 128*FPAD
    __half* sK = sQ + 128 * FPAD;            // 64*FPAD
    __half* sV = sK + 64 * FPAD;             // [key][dim]

    const int tid = threadIdx.x;
    const int wid = tid >> 5;
    const int lane = tid & 31;
    const int i0 = blockIdx.x * 128;
    const int bh = blockIdx.y;
    const size_t base = (size_t)bh * SEQ * HEAD_DIM;

    for (int c = tid; c < 1024; c += 256) {
        const int row = c >> 3, c8 = (c & 7) * 8;
        *(uint4*)&sQ[row * FPAD + c8] =
            *(const uint4*)&Qg[base + (size_t)(i0 + row) * HEAD_DIM + c8];
    }

    float oacc[8][4];
#pragma unroll
    for (int nt = 0; nt < 8; nt++)
#pragma unroll
        for (int c = 0; c < 4; c++) oacc[nt][c] = 0.f;
    float mrow[2] = {-1e30f, -1e30f};
    float lrow[2] = {0.f, 0.f};

    const int r0 = lane >> 2;
    const int nIter = i0 / 64 + 2;

    for (int it = 0; it < nIter; it++) {
        const int kk0 = it * 64;
        for (int c = tid; c < 512; c += 256) {
            const int row = c >> 3, c8 = (c & 7) * 8;
            *(uint4*)&sK[row * FPAD + c8] =
                *(const uint4*)&Kg[base + (size_t)(kk0 + row) * HEAD_DIM + c8];
            *(uint4*)&sV[row * FPAD + c8] =
                *(const uint4*)&Vg[base + (size_t)(kk0 + row) * HEAD_DIM + c8];
        }
        __syncthreads();

        // ---- S = Q K^T ----
        float sacc[8][4];
#pragma unroll
        for (int nt = 0; nt < 8; nt++)
#pragma unroll
            for (int c = 0; c < 4; c++) sacc[nt][c] = 0.f;

#pragma unroll
        for (int ks = 0; ks < 4; ks++) {
            uint32_t af[4];
            const int qof = (wid * 16 + (lane & 15)) * FPAD + ks * 16 + (lane >> 4) * 8;
            ldsm_x4(af, smem_u32(&sQ[qof]));
            uint32_t bf[8][2];
#pragma unroll
            for (int njp = 0; njp < 4; njp++) {
                const int t = lane >> 3;
                const int kof = (njp * 16 + (t >> 1) * 8 + (lane & 7)) * FPAD +
                                ks * 16 + (t & 1) * 8;
                uint32_t r[4];
                ldsm_x4(r, smem_u32(&sK[kof]));
                bf[njp * 2 + 0][0] = r[0]; bf[njp * 2 + 0][1] = r[1];
                bf[njp * 2 + 1][0] = r[2]; bf[njp * 2 + 1][1] = r[3];
            }
#pragma unroll
            for (int nt = 0; nt < 8; nt++)
                mma16816h(sacc[nt], af, bf[nt]);
        }

        // ---- scale + causal mask + online softmax ----
        const float scale = 0.03125f;
        const bool domask = (kk0 + 63 > i0 + wid * 16);
        float tmax[2] = {-1e30f, -1e30f};
#pragma unroll
        for (int nt = 0; nt < 8; nt++) {
#pragma unroll
            for (int c = 0; c < 4; c++) {
                float s = sacc[nt][c] * scale;
                if (domask) {
                    const int gi = i0 + wid * 16 + r0 + (c >> 1) * 8;
                    const int gj = kk0 + nt * 8 + (lane & 3) * 2 + (c & 1);
                    if (gj > gi) s = -1e30f;
                }
                sacc[nt][c] = s;
                tmax[c >> 1] = fmaxf(tmax[c >> 1], s);
            }
        }
#pragma unroll
        for (int h2 = 0; h2 < 2; h2++) {
            tmax[h2] = fmaxf(tmax[h2], __shfl_xor_sync(0xffffffffu, tmax[h2], 1));
            tmax[h2] = fmaxf(tmax[h2], __shfl_xor_sync(0xffffffffu, tmax[h2], 2));
        }
        float fac[2], mnew[2];
#pragma unroll
        for (int h2 = 0; h2 < 2; h2++) {
            mnew[h2] = fmaxf(mrow[h2], tmax[h2]);
            fac[h2] = __expf(mrow[h2] - mnew[h2]);
            mrow[h2] = mnew[h2];
            lrow[h2] *= fac[h2];
        }
#pragma unroll
        for (int nt = 0; nt < 8; nt++)
#pragma unroll
            for (int c = 0; c < 4; c++) oacc[nt][c] *= fac[c >> 1];

#pragma unroll
        for (int nt = 0; nt < 8; nt++) {
#pragma unroll
            for (int c = 0; c < 4; c++) {
                const float p = __expf(sacc[nt][c] - mnew[c >> 1]);
                sacc[nt][c] = p;
                lrow[c >> 1] += p;
            }
        }

        // ---- pack P into fp16 A fragments ----
        uint32_t pf[4][4];
#pragma unroll
        for (int t = 0; t < 4; t++) {
#pragma unroll
            for (int q = 0; q < 4; q++) {
                const float pa = sacc[2 * t + (q >> 1)][(q & 1) * 2 + 0];
                const float pb = sacc[2 * t + (q >> 1)][(q & 1) * 2 + 1];
                const __half2 h = __floats2half2_rn(pa, pb);
                pf[t][q] = *(const uint32_t*)&h;
            }
        }

        // ---- O += P V ----
#pragma unroll
        for (int ks = 0; ks < 4; ks++) {
            uint32_t bf[8][2];
#pragma unroll
            for (int njp = 0; njp < 4; njp++) {
                const int t = lane >> 3;
                const int vof = (ks * 16 + (t & 1) * 8 + (lane & 7)) * FPAD +
                                njp * 16 + (t >> 1) * 8;
                uint32_t r[4];
                ldsm_x4_t(r, smem_u32(&sV[vof]));
                bf[njp * 2 + 0][0] = r[0]; bf[njp * 2 + 0][1] = r[1];
                bf[njp * 2 + 1][0] = r[2]; bf[njp * 2 + 1][1] = r[3];
            }
#pragma unroll
            for (int nt = 0; nt < 8; nt++)
                mma16816h(oacc[nt], pf[ks], bf[nt]);
        }
        __syncthreads();
    }

    // ---- finalize ----
    float inv[2];
#pragma unroll
    for (int h2 = 0; h2 < 2; h2++) {
        float l = lrow[h2];
        l += __shfl_xor_sync(0xffffffffu, l, 1);
        l += __shfl_xor_sync(0xffffffffu, l, 2);
        inv[h2] = 1.f / l;
    }
    const int b = bh >> 4;
    const int h = bh & 15;
#pragma unroll
    for (int nt = 0; nt < 8; nt++) {
#pragma unroll
        for (int half = 0; half < 2; half++) {
            const int gi = i0 + wid * 16 + r0 + half * 8;
            const int d0 = nt * 8 + (lane & 3) * 2;
            const float v0 = oacc[nt][half * 2 + 0] * inv[half];
            const float v1 = oacc[nt][half * 2 + 1] * inv[half];
            const size_t idx = ((size_t)(b * SEQ + gi)) * D_MODEL + h * HEAD_DIM + d0;
            *(__half2*)&Oa[idx] = __floats2half2_rn(v0, v1);
        }
    }
}

// ---------------------------------------------------------------------------
// fp32 -> fp16 convert; grid.z selects which of q/k/v
// ---------------------------------------------------------------------------
__global__ void __launch_bounds__(256) cvt_kernel(
    const float4* __restrict__ in0, const float4* __restrict__ in1,
    const float4* __restrict__ in2,
    __half2* __restrict__ o0, __half2* __restrict__ o1,
    __half2* __restrict__ o2, int n4)
{
    const float4* in = (blockIdx.z == 0) ? in0 : (blockIdx.z == 1) ? in1 : in2;
    __half2* out = (blockIdx.z == 0) ? o0 : (blockIdx.z == 1) ? o1 : o2;
    const int stride = gridDim.x * blockDim.x;
    for (int i = blockIdx.x * blockDim.x + threadIdx.x; i < n4; i += stride) {
        float4 v = in[i];
        out[i * 2 + 0] = __floats2half2_rn(v.x, v.y);
        out[i * 2 + 1] = __floats2half2_rn(v.z, v.w);
    }
}

// ---------------------------------------------------------------------------
// W[K,N] -> Wt [N,K] fp16 (transpose + convert); grid.z selects matrix
// ---------------------------------------------------------------------------
__global__ void __launch_bounds__(256) wt_kernel(
    const float* __restrict__ W0, const float* __restrict__ W1,
    const float* __restrict__ W2, const float* __restrict__ W3,
    __half* __restrict__ T0, __half* __restrict__ T1,
    __half* __restrict__ T2, __half* __restrict__ T3)
{
    const int z = blockIdx.z;
    const float* W = (z == 0) ? W0 : (z == 1) ? W1 : (z == 2) ? W2 : W3;
    __half* Wt = (z == 0) ? T0 : (z == 1) ? T1 : (z == 2) ? T2 : T3;

    __shared__ float t[32][33];
    const int n0 = blockIdx.x * 32, k0 = blockIdx.y * 32;
    const int tx = threadIdx.x & 31, ty = threadIdx.x >> 5;
#pragma unroll
    for (int r = 0; r < 4; r++) {
        const int kl = ty + r * 8;
        t[kl][tx] = W[(size_t)(k0 + kl) * D_MODEL + n0 + tx];
    }
    __syncthreads();
#pragma unroll
    for (int r = 0; r < 4; r++) {
        const int nl = ty + r * 8;
        Wt[(size_t)(n0 + nl) * D_MODEL + k0 + tx] = __float2half_rn(t[tx][nl]);
    }
}

// ---------------------------------------------------------------------------
extern "C" void kernel_launch(void* const* d_in, const int* in_sizes, int n_in,
                              void* d_out, int out_size)
{
    const float* q  = (const float*)d_in[0];
    const float* k  = (const float*)d_in[1];
    const float* v  = (const float*)d_in[2];
    const float* Wq = (const float*)d_in[3];
    const float* bq = (const float*)d_in[4];
    const float* Wk = (const float*)d_in[5];
    const float* bk = (const float*)d_in[6];
    const float* Wv = (const float*)d_in[7];
    const float* bv = (const float*)d_in[8];
    const float* Wo = (const float*)d_in[9];
    const float* bo = (const float*)d_in[10];

    __half *q16, *k16, *v16, *af, *Q16, *K16, *V16;
    __half *wq, *wk, *wv, *wo;
    cudaGetSymbolAddress((void**)&q16, g_q16);
    cudaGetSymbolAddress((void**)&k16, g_k16);
    cudaGetSymbolAddress((void**)&v16, g_v16);
    cudaGetSymbolAddress((void**)&af, g_af);
    cudaGetSymbolAddress((void**)&Q16, g_Q16);
    cudaGetSymbolAddress((void**)&K16, g_K16);
    cudaGetSymbolAddress((void**)&V16, g_V16);
    cudaGetSymbolAddress((void**)&wq, g_Wq16);
    cudaGetSymbolAddress((void**)&wk, g_Wk16);
    cudaGetSymbolAddress((void**)&wv, g_Wv16);
    cudaGetSymbolAddress((void**)&wo, g_Wo16);

    cudaFuncSetAttribute(flash_kernel,
                         cudaFuncAttributeMaxDynamicSharedMemorySize, FLASH_SMEM);
    cudaFuncSetAttribute(gemm_mma_kernel<0>,
                         cudaFuncAttributeMaxDynamicSharedMemorySize, G4_SMEM);
    cudaFuncSetAttribute(gemm_mma_kernel<1>,
                         cudaFuncAttributeMaxDynamicSharedMemorySize, G4_SMEM);

    wt_kernel<<<dim3(32, 32, 4), 256>>>(Wq, Wk, Wv, Wo, wq, wk, wv, wo);

    const int n4 = MROWS * D_MODEL / 4;
    cvt_kernel<<<dim3(1024, 1, 3), 256>>>(
        (const float4*)q, (const float4*)k, (const float4*)v,
        (__half2*)q16, (__half2*)k16, (__half2*)v16, n4);

    // Fused QKV projections -> single fp16 heads layout
    dim3 gQKV(GN / 128, MROWS / 128, 3);   // (8, 64, 3)
    gemm_mma_kernel<1><<<gQKV, 256, G4_SMEM>>>(
        q16, k16, v16,
        wq, wk, wv,
        bq, bk, bv,
        Q16, K16, V16,
        nullptr);

    flash_kernel<<<dim3(SEQ / 128, BH), 256, FLASH_SMEM>>>(Q16, K16, V16, af);

    // Output projection -> fp32 d_out
    dim3 gO(GN / 128, MROWS / 128, 1);     // (8, 64, 1)
    gemm_mma_kernel<0><<<gO, 256, G4_SMEM>>>(
        af, nullptr, nullptr,
        wo, nullptr, nullptr,
        bo, nullptr, nullptr,
        nullptr, nullptr, nullptr,
        (float*)d_out);
}

// round 12
// speedup vs baseline: 8.1416x; 1.0434x over previous
#include <cuda_runtime.h>
#include <cuda_bf16.h>
#include <cuda_fp16.h>
#include <cstdint>

#define D_MODEL 1024
#define N_HEAD  16
#define HEAD_DIM 64
#define BATCH   4
#define SEQ     2048
#define BH      (BATCH * N_HEAD)          // 64
#define MROWS   (BATCH * SEQ)             // 8192
#define GK      1024
#define GN      1024

// ---------------------------------------------------------------------------
// Scratch (device globals)
// ---------------------------------------------------------------------------
__device__ __half g_q16[MROWS * D_MODEL], g_k16[MROWS * D_MODEL], g_v16[MROWS * D_MODEL];
__device__ __half g_af[MROWS * D_MODEL];     // flash output, fp16
// projected Q/K/V single fp16, heads layout [bh][s][hd] (Q pre-scaled by 1/32)
__device__ __half g_Q16[BH * SEQ * HEAD_DIM], g_K16[BH * SEQ * HEAD_DIM];
__device__ __half g_V16[BH * SEQ * HEAD_DIM];
// transposed weights [N][K], single fp16
__device__ __half g_Wq16[D_MODEL * D_MODEL], g_Wk16[D_MODEL * D_MODEL];
__device__ __half g_Wv16[D_MODEL * D_MODEL], g_Wo16[D_MODEL * D_MODEL];

// ---------------------------------------------------------------------------
__device__ __forceinline__ uint32_t smem_u32(const void* p) {
    uint32_t a;
    asm("{ .reg .u64 t; cvta.to.shared.u64 t, %1; cvt.u32.u64 %0, t; }"
        : "=r"(a) : "l"(p));
    return a;
}

#define CP_ASYNC16(dst_u32, src_ptr) \
    asm volatile("cp.async.cg.shared.global [%0], [%1], 16;" \
        :: "r"(dst_u32), "l"(src_ptr))

__device__ __forceinline__ void ldsm_x4(uint32_t* r, uint32_t addr) {
    asm volatile("ldmatrix.sync.aligned.m8n8.x4.shared.b16 {%0,%1,%2,%3}, [%4];"
        : "=r"(r[0]), "=r"(r[1]), "=r"(r[2]), "=r"(r[3]) : "r"(addr));
}

__device__ __forceinline__ void ldsm_x4_t(uint32_t* r, uint32_t addr) {
    asm volatile("ldmatrix.sync.aligned.m8n8.x4.trans.shared.b16 {%0,%1,%2,%3}, [%4];"
        : "=r"(r[0]), "=r"(r[1]), "=r"(r[2]), "=r"(r[3]) : "r"(addr));
}

__device__ __forceinline__ void mma16816h(float* d, const uint32_t* a,
                                          const uint32_t* b) {
    asm volatile(
        "mma.sync.aligned.m16n8k16.row.col.f32.f16.f16.f32 "
        "{%0,%1,%2,%3}, {%4,%5,%6,%7}, {%8,%9}, {%0,%1,%2,%3};"
        : "+f"(d[0]), "+f"(d[1]), "+f"(d[2]), "+f"(d[3])
        : "r"(a[0]), "r"(a[1]), "r"(a[2]), "r"(a[3]), "r"(b[0]), "r"(b[1]));
}

// ---------------------------------------------------------------------------
// fp16 single-term GEMM: C = A * W + bias.  256 threads, BM=128 BN=128 BK=32,
// 4-stage cp.async pipeline, 81.9 KB smem -> 2 CTAs/SM.
// MODE 1: single fp16 heads layout out (z==0 scales by 1/32).
// MODE 0: fp32 row-major out.
// ---------------------------------------------------------------------------
#define NSLABS  32
#define S_A     (128 * 40)
#define S_ST    (2 * S_A)
#define G4_SMEM (4 * S_ST * 2)            // 81920

template <int MODE>
__global__ void __launch_bounds__(256) gemm_mma_kernel(
    const __half* __restrict__ A0, const __half* __restrict__ A1,
    const __half* __restrict__ A2,
    const __half* __restrict__ B0, const __half* __restrict__ B1,
    const __half* __restrict__ B2,
    const float* __restrict__ bias0, const float* __restrict__ bias1,
    const float* __restrict__ bias2,
    __half* __restrict__ O0, __half* __restrict__ O1,
    __half* __restrict__ O2,
    float* __restrict__ out32)
{
    extern __shared__ __half gsm[];

    const int z = blockIdx.z;
    const __half* Ag = (z == 0) ? A0 : (z == 1) ? A1 : A2;
    const __half* Bg = (z == 0) ? B0 : (z == 1) ? B1 : B2;
    const float* bias = (z == 0) ? bias0 : (z == 1) ? bias1 : bias2;
    __half* outp = (z == 0) ? O0 : (z == 1) ? O1 : O2;
    const float oscale = (MODE == 1 && z == 0) ? 0.03125f : 1.0f;

    const int tid = threadIdx.x;
    const int wid = tid >> 5;
    const int lane = tid & 31;
    const int m0 = blockIdx.y * 128;
    const int n0 = blockIdx.x * 128;
    const int wm = (wid & 1) * 64;
    const int wn = (wid >> 1) * 32;

    float acc[4][4][4];
#pragma unroll
    for (int i = 0; i < 4; i++)
#pragma unroll
        for (int j = 0; j < 4; j++)
#pragma unroll
            for (int c = 0; c < 4; c++) acc[i][j][c] = 0.f;

    const int ldrow = tid >> 2;
    const int ldcol = (tid & 3) * 8;

    auto issue_load = [&](int stage, int slab) {
        const int k0 = slab << 5;
        __half* sA = gsm + stage * S_ST;
        __half* sB = sA + S_A;
#pragma unroll
        for (int r = 0; r < 2; r++) {
            const int row = ldrow + r * 64;
            const size_t ga = (size_t)(m0 + row) * GK + k0 + ldcol;
            const size_t gb = (size_t)(n0 + row) * GK + k0 + ldcol;
            CP_ASYNC16(smem_u32(&sA[row * 40 + ldcol]), Ag + ga);
            CP_ASYNC16(smem_u32(&sB[row * 40 + ldcol]), Bg + gb);
        }
        asm volatile("cp.async.commit_group;" ::: "memory");
    };

    issue_load(0, 0);
    issue_load(1, 1);
    issue_load(2, 2);

    int st = 0;
    for (int i = 0; i < NSLABS; i++) {
        if (i + 3 < NSLABS) {
            issue_load((st + 3) & 3, i + 3);
            asm volatile("cp.async.wait_group 3;" ::: "memory");
        } else if (i + 2 < NSLABS) {
            asm volatile("cp.async.wait_group 2;" ::: "memory");
        } else if (i + 1 < NSLABS) {
            asm volatile("cp.async.wait_group 1;" ::: "memory");
        } else {
            asm volatile("cp.async.wait_group 0;" ::: "memory");
        }
        __syncthreads();

        const __half* sA = gsm + st * S_ST;
        const __half* sB = sA + S_A;

#pragma unroll
        for (int ks = 0; ks < 2; ks++) {
            uint32_t bf[4][2];
#pragma unroll
            for (int njp = 0; njp < 2; njp++) {
                const int t = lane >> 3;
                const int sof = (wn + njp * 16 + (t >> 1) * 8 + (lane & 7)) * 40 +
                                ks * 16 + (t & 1) * 8;
                uint32_t r[4];
                ldsm_x4(r, smem_u32(&sB[sof]));
                bf[njp * 2 + 0][0] = r[0]; bf[njp * 2 + 0][1] = r[1];
                bf[njp * 2 + 1][0] = r[2]; bf[njp * 2 + 1][1] = r[3];
            }
#pragma unroll
            for (int mi = 0; mi < 4; mi++) {
                uint32_t af[4];
                const int sof = (wm + mi * 16 + (lane & 15)) * 40 +
                                ks * 16 + (lane >> 4) * 8;
                ldsm_x4(af, smem_u32(&sA[sof]));
#pragma unroll
                for (int nj = 0; nj < 4; nj++)
                    mma16816h(acc[mi][nj], af, bf[nj]);
            }
        }
        __syncthreads();
        st = (st + 1) & 3;
    }

#pragma unroll
    for (int mi = 0; mi < 4; mi++) {
#pragma unroll
        for (int nj = 0; nj < 4; nj++) {
            const int n = n0 + wn + nj * 8 + (lane & 3) * 2;
            const float b0 = bias[n], b1 = bias[n + 1];
#pragma unroll
            for (int half = 0; half < 2; half++) {
                const int m = m0 + wm + mi * 16 + (lane >> 2) + half * 8;
                const float v0 = (acc[mi][nj][half * 2 + 0] + b0) * oscale;
                const float v1 = (acc[mi][nj][half * 2 + 1] + b1) * oscale;
                if (MODE == 1) {
                    const int b = m >> 11;
                    const int s = m & (SEQ - 1);
                    const int h = n >> 6;
                    const int d = n & 63;
                    const size_t idx =
                        ((((size_t)b * N_HEAD + h) * SEQ) + s) * HEAD_DIM + d;
                    *(__half2*)&outp[idx] = __floats2half2_rn(v0, v1);
                } else {
                    *(float2*)&out32[(size_t)m * GN + n] = make_float2(v0, v1);
                }
            }
        }
    }
}

// ---------------------------------------------------------------------------
// Fused flash attention, all-fp16, cp.async double-buffered K/V tiles.
// Q pre-scaled by 1/32.  grid (SEQ/128, BH), 256 threads.
// smem: Q 128x72 + 2x(K 64x72 + V 64x72) = 55296 B.
// ---------------------------------------------------------------------------
#define FPAD 72
#define KV_ST (2 * 64 * FPAD)            // K+V per stage (elements)
#define FLASH_SMEM ((128 * FPAD + 2 * KV_ST) * 2)   // 55296

__global__ void __launch_bounds__(256) flash_kernel(
    const __half* __restrict__ Qg, const __half* __restrict__ Kg,
    const __half* __restrict__ Vg, __half* __restrict__ Oa)
{
    extern __shared__ __half fsm[];
    __half* sQ = fsm;                        // 128*FPAD
    __half* kvBase = sQ + 128 * FPAD;        // 2 stages of [K 64x72 | V 64x72]

    const int tid = threadIdx.x;
    const int wid = tid >> 5;
    const int lane = tid & 31;
    const int i0 = blockIdx.x * 128;
    const int bh = blockIdx.y;
    const size_t base = (size_t)bh * SEQ * HEAD_DIM;

    // Q tile (plain loads; covered by first loop barrier)
    for (int c = tid; c < 1024; c += 256) {
        const int row = c >> 3, c8 = (c & 7) * 8;
        *(uint4*)&sQ[row * FPAD + c8] =
            *(const uint4*)&Qg[base + (size_t)(i0 + row) * HEAD_DIM + c8];
    }

    const int ldrow = tid >> 2;              // 0..63
    const int ldcol = (tid & 3) * 16;        // 0,16,32,48 (halfs)

    auto issue_kv = [&](int it, int buf) {
        const int kk0 = it * 64;
        __half* sK = kvBase + buf * KV_ST;
        __half* sV = sK + 64 * FPAD;
#pragma unroll
        for (int r = 0; r < 2; r++) {
            const int col = ldcol + r * 8;
            const size_t g = base + (size_t)(kk0 + ldrow) * HEAD_DIM + col;
            CP_ASYNC16(smem_u32(&sK[ldrow * FPAD + col]), Kg + g);
            CP_ASYNC16(smem_u32(&sV[ldrow * FPAD + col]), Vg + g);
        }
        asm volatile("cp.async.commit_group;" ::: "memory");
    };

    float oacc[8][4];
#pragma unroll
    for (int nt = 0; nt < 8; nt++)
#pragma unroll
        for (int c = 0; c < 4; c++) oacc[nt][c] = 0.f;
    float mrow[2] = {-1e30f, -1e30f};
    float lrow[2] = {0.f, 0.f};

    const int r0 = lane >> 2;
    const int nIter = i0 / 64 + 2;

    issue_kv(0, 0);

    for (int it = 0; it < nIter; it++) {
        asm volatile("cp.async.wait_group 0;" ::: "memory");
        __syncthreads();
        if (it + 1 < nIter) issue_kv(it + 1, (it + 1) & 1);

        const __half* sK = kvBase + (it & 1) * KV_ST;
        const __half* sV = sK + 64 * FPAD;
        const int kk0 = it * 64;

        // ---- S = Q K^T (Q pre-scaled) ----
        float sacc[8][4];
#pragma unroll
        for (int nt = 0; nt < 8; nt++)
#pragma unroll
            for (int c = 0; c < 4; c++) sacc[nt][c] = 0.f;

#pragma unroll
        for (int ks = 0; ks < 4; ks++) {
            uint32_t af[4];
            const int qof = (wid * 16 + (lane & 15)) * FPAD + ks * 16 + (lane >> 4) * 8;
            ldsm_x4(af, smem_u32(&sQ[qof]));
            uint32_t bf[8][2];
#pragma unroll
            for (int njp = 0; njp < 4; njp++) {
                const int t = lane >> 3;
                const int kof = (njp * 16 + (t >> 1) * 8 + (lane & 7)) * FPAD +
                                ks * 16 + (t & 1) * 8;
                uint32_t r[4];
                ldsm_x4(r, smem_u32(&sK[kof]));
                bf[njp * 2 + 0][0] = r[0]; bf[njp * 2 + 0][1] = r[1];
                bf[njp * 2 + 1][0] = r[2]; bf[njp * 2 + 1][1] = r[3];
            }
#pragma unroll
            for (int nt = 0; nt < 8; nt++)
                mma16816h(sacc[nt], af, bf[nt]);
        }

        // ---- causal mask + online softmax ----
        const bool domask = (kk0 + 63 > i0 + wid * 16);
        float tmax[2] = {-1e30f, -1e30f};
#pragma unroll
        for (int nt = 0; nt < 8; nt++) {
#pragma unroll
            for (int c = 0; c < 4; c++) {
                float s = sacc[nt][c];
                if (domask) {
                    const int gi = i0 + wid * 16 + r0 + (c >> 1) * 8;
                    const int gj = kk0 + nt * 8 + (lane & 3) * 2 + (c & 1);
                    if (gj > gi) s = -1e30f;
                }
                sacc[nt][c] = s;
                tmax[c >> 1] = fmaxf(tmax[c >> 1], s);
            }
        }
#pragma unroll
        for (int h2 = 0; h2 < 2; h2++) {
            tmax[h2] = fmaxf(tmax[h2], __shfl_xor_sync(0xffffffffu, tmax[h2], 1));
            tmax[h2] = fmaxf(tmax[h2], __shfl_xor_sync(0xffffffffu, tmax[h2], 2));
        }
        float fac[2], mnew[2];
#pragma unroll
        for (int h2 = 0; h2 < 2; h2++) {
            mnew[h2] = fmaxf(mrow[h2], tmax[h2]);
            fac[h2] = __expf(mrow[h2] - mnew[h2]);
            mrow[h2] = mnew[h2];
            lrow[h2] *= fac[h2];
        }
#pragma unroll
        for (int nt = 0; nt < 8; nt++)
#pragma unroll
            for (int c = 0; c < 4; c++) oacc[nt][c] *= fac[c >> 1];

#pragma unroll
        for (int nt = 0; nt < 8; nt++) {
#pragma unroll
            for (int c = 0; c < 4; c++) {
                const float p = __expf(sacc[nt][c] - mnew[c >> 1]);
                sacc[nt][c] = p;
                lrow[c >> 1] += p;
            }
        }

        // ---- pack P into fp16 A fragments ----
        uint32_t pf[4][4];
#pragma unroll
        for (int t = 0; t < 4; t++) {
#pragma unroll
            for (int q = 0; q < 4; q++) {
                const float pa = sacc[2 * t + (q >> 1)][(q & 1) * 2 + 0];
                const float pb = sacc[2 * t + (q >> 1)][(q & 1) * 2 + 1];
                const __half2 h = __floats2half2_rn(pa, pb);
                pf[t][q] = *(const uint32_t*)&h;
            }
        }

        // ---- O += P V ----
#pragma unroll
        for (int ks = 0; ks < 4; ks++) {
            uint32_t bf[8][2];
#pragma unroll
            for (int njp = 0; njp < 4; njp++) {
                const int t = lane >> 3;
                const int vof = (ks * 16 + (t & 1) * 8 + (lane & 7)) * FPAD +
                                njp * 16 + (t >> 1) * 8;
                uint32_t r[4];
                ldsm_x4_t(r, smem_u32(&sV[vof]));
                bf[njp * 2 + 0][0] = r[0]; bf[njp * 2 + 0][1] = r[1];
                bf[njp * 2 + 1][0] = r[2]; bf[njp * 2 + 1][1] = r[3];
            }
#pragma unroll
            for (int nt = 0; nt < 8; nt++)
                mma16816h(oacc[nt], pf[ks], bf[nt]);
        }
        __syncthreads();
    }

    // ---- finalize ----
    float inv[2];
#pragma unroll
    for (int h2 = 0; h2 < 2; h2++) {
        float l = lrow[h2];
        l += __shfl_xor_sync(0xffffffffu, l, 1);
        l += __shfl_xor_sync(0xffffffffu, l, 2);
        inv[h2] = 1.f / l;
    }
    const int b = bh >> 4;
    const int h = bh & 15;
#pragma unroll
    for (int nt = 0; nt < 8; nt++) {
#pragma unroll
        for (int half = 0; half < 2; half++) {
            const int gi = i0 + wid * 16 + r0 + half * 8;
            const int d0 = nt * 8 + (lane & 3) * 2;
            const float v0 = oacc[nt][half * 2 + 0] * inv[half];
            const float v1 = oacc[nt][half * 2 + 1] * inv[half];
            const size_t idx = ((size_t)(b * SEQ + gi)) * D_MODEL + h * HEAD_DIM + d0;
            *(__half2*)&Oa[idx] = __floats2half2_rn(v0, v1);
        }
    }
}

// ---------------------------------------------------------------------------
__global__ void __launch_bounds__(256) cvt_kernel(
    const float4* __restrict__ in0, const float4* __restrict__ in1,
    const float4* __restrict__ in2,
    __half2* __restrict__ o0, __half2* __restrict__ o1,
    __half2* __restrict__ o2, int n4)
{
    const float4* in = (blockIdx.z == 0) ? in0 : (blockIdx.z == 1) ? in1 : in2;
    __half2* out = (blockIdx.z == 0) ? o0 : (blockIdx.z == 1) ? o1 : o2;
    const int stride = gridDim.x * blockDim.x;
    for (int i = blockIdx.x * blockDim.x + threadIdx.x; i < n4; i += stride) {
        float4 v = in[i];
        out[i * 2 + 0] = __floats2half2_rn(v.x, v.y);
        out[i * 2 + 1] = __floats2half2_rn(v.z, v.w);
    }
}

__global__ void __launch_bounds__(256) wt_kernel(
    const float* __restrict__ W0, const float* __restrict__ W1,
    const float* __restrict__ W2, const float* __restrict__ W3,
    __half* __restrict__ T0, __half* __restrict__ T1,
    __half* __restrict__ T2, __half* __restrict__ T3)
{
    const int z = blockIdx.z;
    const float* W = (z == 0) ? W0 : (z == 1) ? W1 : (z == 2) ? W2 : W3;
    __half* Wt = (z == 0) ? T0 : (z == 1) ? T1 : (z == 2) ? T2 : T3;

    __shared__ float t[32][33];
    const int n0 = blockIdx.x * 32, k0 = blockIdx.y * 32;
    const int tx = threadIdx.x & 31, ty = threadIdx.x >> 5;
#pragma unroll
    for (int r = 0; r < 4; r++) {
        const int kl = ty + r * 8;
        t[kl][tx] = W[(size_t)(k0 + kl) * D_MODEL + n0 + tx];
    }
    __syncthreads();
#pragma unroll
    for (int r = 0; r < 4; r++) {
        const int nl = ty + r * 8;
        Wt[(size_t)(n0 + nl) * D_MODEL + k0 + tx] = __float2half_rn(t[tx][nl]);
    }
}

// ---------------------------------------------------------------------------
extern "C" void kernel_launch(void* const* d_in, const int* in_sizes, int n_in,
                              void* d_out, int out_size)
{
    const float* q  = (const float*)d_in[0];
    const float* k  = (const float*)d_in[1];
    const float* v  = (const float*)d_in[2];
    const float* Wq = (const float*)d_in[3];
    const float* bq = (const float*)d_in[4];
    const float* Wk = (const float*)d_in[5];
    const float* bk = (const float*)d_in[6];
    const float* Wv = (const float*)d_in[7];
    const float* bv = (const float*)d_in[8];
    const float* Wo = (const float*)d_in[9];
    const float* bo = (const float*)d_in[10];

    __half *q16, *k16, *v16, *af, *Q16, *K16, *V16;
    __half *wq, *wk, *wv, *wo;
    cudaGetSymbolAddress((void**)&q16, g_q16);
    cudaGetSymbolAddress((void**)&k16, g_k16);
    cudaGetSymbolAddress((void**)&v16, g_v16);
    cudaGetSymbolAddress((void**)&af, g_af);
    cudaGetSymbolAddress((void**)&Q16, g_Q16);
    cudaGetSymbolAddress((void**)&K16, g_K16);
    cudaGetSymbolAddress((void**)&V16, g_V16);
    cudaGetSymbolAddress((void**)&wq, g_Wq16);
    cudaGetSymbolAddress((void**)&wk, g_Wk16);
    cudaGetSymbolAddress((void**)&wv, g_Wv16);
    cudaGetSymbolAddress((void**)&wo, g_Wo16);

    cudaFuncSetAttribute(flash_kernel,
                         cudaFuncAttributeMaxDynamicSharedMemorySize, FLASH_SMEM);
    cudaFuncSetAttribute(gemm_mma_kernel<0>,
                         cudaFuncAttributeMaxDynamicSharedMemorySize, G4_SMEM);
    cudaFuncSetAttribute(gemm_mma_kernel<1>,
                         cudaFuncAttributeMaxDynamicSharedMemorySize, G4_SMEM);

    wt_kernel<<<dim3(32, 32, 4), 256>>>(Wq, Wk, Wv, Wo, wq, wk, wv, wo);

    const int n4 = MROWS * D_MODEL / 4;
    cvt_kernel<<<dim3(1024, 1, 3), 256>>>(
        (const float4*)q, (const float4*)k, (const float4*)v,
        (__half2*)q16, (__half2*)k16, (__half2*)v16, n4);

    // Fused QKV projections -> single fp16 heads layout (Q scaled by 1/32)
    dim3 gQKV(GN / 128, MROWS / 128, 3);
    gemm_mma_kernel<1><<<gQKV, 256, G4_SMEM>>>(
        q16, k16, v16,
        wq, wk, wv,
        bq, bk, bv,
        Q16, K16, V16,
        nullptr);

    flash_kernel<<<dim3(SEQ / 128, BH), 256, FLASH_SMEM>>>(Q16, K16, V16, af);

    // Output projection -> fp32 d_out
    dim3 gO(GN / 128, MROWS / 128, 1);
    gemm_mma_kernel<0><<<gO, 256, G4_SMEM>>>(
        af, nullptr, nullptr,
        wo, nullptr, nullptr,
        bo, nullptr, nullptr,
        nullptr, nullptr, nullptr,
        (float*)d_out);
}

// round 13
// speedup vs baseline: 8.2829x; 1.0174x over previous
#include <cuda_runtime.h>
#include <cuda_bf16.h>
#include <cuda_fp16.h>
#include <cstdint>

#define D_MODEL 1024
#define N_HEAD  16
#define HEAD_DIM 64
#define BATCH   4
#define SEQ     2048
#define BH      (BATCH * N_HEAD)          // 64
#define MROWS   (BATCH * SEQ)             // 8192
#define GK      1024
#define GN      1024

// ---------------------------------------------------------------------------
// Scratch (device globals)
// ---------------------------------------------------------------------------
__device__ __half g_q16[MROWS * D_MODEL], g_k16[MROWS * D_MODEL], g_v16[MROWS * D_MODEL];
__device__ __half g_af[MROWS * D_MODEL];     // flash output, fp16
// projected Q/K/V single fp16, heads layout [bh][s][hd]
// (Q pre-scaled by log2(e)/32 -> scores are base-2 logits)
__device__ __half g_Q16[BH * SEQ * HEAD_DIM], g_K16[BH * SEQ * HEAD_DIM];
__device__ __half g_V16[BH * SEQ * HEAD_DIM];
// transposed weights [N][K], single fp16
__device__ __half g_Wq16[D_MODEL * D_MODEL], g_Wk16[D_MODEL * D_MODEL];
__device__ __half g_Wv16[D_MODEL * D_MODEL], g_Wo16[D_MODEL * D_MODEL];

// ---------------------------------------------------------------------------
__device__ __forceinline__ uint32_t smem_u32(const void* p) {
    uint32_t a;
    asm("{ .reg .u64 t; cvta.to.shared.u64 t, %1; cvt.u32.u64 %0, t; }"
        : "=r"(a) : "l"(p));
    return a;
}

#define CP_ASYNC16(dst_u32, src_ptr) \
    asm volatile("cp.async.cg.shared.global [%0], [%1], 16;" \
        :: "r"(dst_u32), "l"(src_ptr))

__device__ __forceinline__ void ldsm_x4(uint32_t* r, uint32_t addr) {
    asm volatile("ldmatrix.sync.aligned.m8n8.x4.shared.b16 {%0,%1,%2,%3}, [%4];"
        : "=r"(r[0]), "=r"(r[1]), "=r"(r[2]), "=r"(r[3]) : "r"(addr));
}

__device__ __forceinline__ void ldsm_x4_t(uint32_t* r, uint32_t addr) {
    asm volatile("ldmatrix.sync.aligned.m8n8.x4.trans.shared.b16 {%0,%1,%2,%3}, [%4];"
        : "=r"(r[0]), "=r"(r[1]), "=r"(r[2]), "=r"(r[3]) : "r"(addr));
}

__device__ __forceinline__ void mma16816h(float* d, const uint32_t* a,
                                          const uint32_t* b) {
    asm volatile(
        "mma.sync.aligned.m16n8k16.row.col.f32.f16.f16.f32 "
        "{%0,%1,%2,%3}, {%4,%5,%6,%7}, {%8,%9}, {%0,%1,%2,%3};"
        : "+f"(d[0]), "+f"(d[1]), "+f"(d[2]), "+f"(d[3])
        : "r"(a[0]), "r"(a[1]), "r"(a[2]), "r"(a[3]), "r"(b[0]), "r"(b[1]));
}

// ---------------------------------------------------------------------------
// fp16 single-term GEMM: C = A * W + bias.  256 threads, BM=128 BN=128 BK=32,
// 4-stage cp.async pipeline, 81.9 KB smem -> 2 CTAs/SM.
// MODE 1: single fp16 heads layout out (z==0 scales by log2e/32).
// MODE 0: fp32 row-major out.
// ---------------------------------------------------------------------------
#define NSLABS  32
#define S_A     (128 * 40)
#define S_ST    (2 * S_A)
#define G4_SMEM (4 * S_ST * 2)            // 81920

template <int MODE>
__global__ void __launch_bounds__(256) gemm_mma_kernel(
    const __half* __restrict__ A0, const __half* __restrict__ A1,
    const __half* __restrict__ A2,
    const __half* __restrict__ B0, const __half* __restrict__ B1,
    const __half* __restrict__ B2,
    const float* __restrict__ bias0, const float* __restrict__ bias1,
    const float* __restrict__ bias2,
    __half* __restrict__ O0, __half* __restrict__ O1,
    __half* __restrict__ O2,
    float* __restrict__ out32)
{
    extern __shared__ __half gsm[];

    const int z = blockIdx.z;
    const __half* Ag = (z == 0) ? A0 : (z == 1) ? A1 : A2;
    const __half* Bg = (z == 0) ? B0 : (z == 1) ? B1 : B2;
    const float* bias = (z == 0) ? bias0 : (z == 1) ? bias1 : bias2;
    __half* outp = (z == 0) ? O0 : (z == 1) ? O1 : O2;
    // Q: fold softmax scale 1/32 and log2(e) (exp2-domain softmax)
    const float oscale = (MODE == 1 && z == 0) ? 0.03125f * 1.4426950408889634f
                                               : 1.0f;

    const int tid = threadIdx.x;
    const int wid = tid >> 5;
    const int lane = tid & 31;
    const int m0 = blockIdx.y * 128;
    const int n0 = blockIdx.x * 128;
    const int wm = (wid & 1) * 64;
    const int wn = (wid >> 1) * 32;

    float acc[4][4][4];
#pragma unroll
    for (int i = 0; i < 4; i++)
#pragma unroll
        for (int j = 0; j < 4; j++)
#pragma unroll
            for (int c = 0; c < 4; c++) acc[i][j][c] = 0.f;

    const int ldrow = tid >> 2;
    const int ldcol = (tid & 3) * 8;

    auto issue_load = [&](int stage, int slab) {
        const int k0 = slab << 5;
        __half* sA = gsm + stage * S_ST;
        __half* sB = sA + S_A;
#pragma unroll
        for (int r = 0; r < 2; r++) {
            const int row = ldrow + r * 64;
            const size_t ga = (size_t)(m0 + row) * GK + k0 + ldcol;
            const size_t gb = (size_t)(n0 + row) * GK + k0 + ldcol;
            CP_ASYNC16(smem_u32(&sA[row * 40 + ldcol]), Ag + ga);
            CP_ASYNC16(smem_u32(&sB[row * 40 + ldcol]), Bg + gb);
        }
        asm volatile("cp.async.commit_group;" ::: "memory");
    };

    issue_load(0, 0);
    issue_load(1, 1);
    issue_load(2, 2);

    int st = 0;
    for (int i = 0; i < NSLABS; i++) {
        if (i + 3 < NSLABS) {
            issue_load((st + 3) & 3, i + 3);
            asm volatile("cp.async.wait_group 3;" ::: "memory");
        } else if (i + 2 < NSLABS) {
            asm volatile("cp.async.wait_group 2;" ::: "memory");
        } else if (i + 1 < NSLABS) {
            asm volatile("cp.async.wait_group 1;" ::: "memory");
        } else {
            asm volatile("cp.async.wait_group 0;" ::: "memory");
        }
        __syncthreads();

        const __half* sA = gsm + st * S_ST;
        const __half* sB = sA + S_A;

#pragma unroll
        for (int ks = 0; ks < 2; ks++) {
            uint32_t bf[4][2];
#pragma unroll
            for (int njp = 0; njp < 2; njp++) {
                const int t = lane >> 3;
                const int sof = (wn + njp * 16 + (t >> 1) * 8 + (lane & 7)) * 40 +
                                ks * 16 + (t & 1) * 8;
                uint32_t r[4];
                ldsm_x4(r, smem_u32(&sB[sof]));
                bf[njp * 2 + 0][0] = r[0]; bf[njp * 2 + 0][1] = r[1];
                bf[njp * 2 + 1][0] = r[2]; bf[njp * 2 + 1][1] = r[3];
            }
#pragma unroll
            for (int mi = 0; mi < 4; mi++) {
                uint32_t af[4];
                const int sof = (wm + mi * 16 + (lane & 15)) * 40 +
                                ks * 16 + (lane >> 4) * 8;
                ldsm_x4(af, smem_u32(&sA[sof]));
#pragma unroll
                for (int nj = 0; nj < 4; nj++)
                    mma16816h(acc[mi][nj], af, bf[nj]);
            }
        }
        __syncthreads();
        st = (st + 1) & 3;
    }

#pragma unroll
    for (int mi = 0; mi < 4; mi++) {
#pragma unroll
        for (int nj = 0; nj < 4; nj++) {
            const int n = n0 + wn + nj * 8 + (lane & 3) * 2;
            const float b0 = bias[n], b1 = bias[n + 1];
#pragma unroll
            for (int half = 0; half < 2; half++) {
                const int m = m0 + wm + mi * 16 + (lane >> 2) + half * 8;
                const float v0 = (acc[mi][nj][half * 2 + 0] + b0) * oscale;
                const float v1 = (acc[mi][nj][half * 2 + 1] + b1) * oscale;
                if (MODE == 1) {
                    const int b = m >> 11;
                    const int s = m & (SEQ - 1);
                    const int h = n >> 6;
                    const int d = n & 63;
                    const size_t idx =
                        ((((size_t)b * N_HEAD + h) * SEQ) + s) * HEAD_DIM + d;
                    *(__half2*)&outp[idx] = __floats2half2_rn(v0, v1);
                } else {
                    *(float2*)&out32[(size_t)m * GN + n] = make_float2(v0, v1);
                }
            }
        }
    }
}

// ---------------------------------------------------------------------------
// Fused flash attention, all-fp16, cp.async double-buffered K/V tiles,
// exp2-domain softmax (Q pre-scaled by log2e/32).
// Heavy (high-i0) CTAs launch first for causal load balance.
// grid (SEQ/128, BH), 256 threads.
// ---------------------------------------------------------------------------
#define FPAD 72
#define KV_ST (2 * 64 * FPAD)            // K+V per stage (elements)
#define FLASH_SMEM ((128 * FPAD + 2 * KV_ST) * 2)   // 55296

__global__ void __launch_bounds__(256) flash_kernel(
    const __half* __restrict__ Qg, const __half* __restrict__ Kg,
    const __half* __restrict__ Vg, __half* __restrict__ Oa)
{
    extern __shared__ __half fsm[];
    __half* sQ = fsm;                        // 128*FPAD
    __half* kvBase = sQ + 128 * FPAD;        // 2 stages of [K 64x72 | V 64x72]

    const int tid = threadIdx.x;
    const int wid = tid >> 5;
    const int lane = tid & 31;
    // reversed order: heavy causal tiles (large i0) first
    const int i0 = (gridDim.x - 1 - blockIdx.x) * 128;
    const int bh = blockIdx.y;
    const size_t base = (size_t)bh * SEQ * HEAD_DIM;

    // Q tile (plain loads; covered by first loop barrier)
    for (int c = tid; c < 1024; c += 256) {
        const int row = c >> 3, c8 = (c & 7) * 8;
        *(uint4*)&sQ[row * FPAD + c8] =
            *(const uint4*)&Qg[base + (size_t)(i0 + row) * HEAD_DIM + c8];
    }

    const int ldrow = tid >> 2;              // 0..63
    const int ldcol = (tid & 3) * 16;        // 0,16,32,48 (halfs)

    auto issue_kv = [&](int it, int buf) {
        const int kk0 = it * 64;
        __half* sK = kvBase + buf * KV_ST;
        __half* sV = sK + 64 * FPAD;
#pragma unroll
        for (int r = 0; r < 2; r++) {
            const int col = ldcol + r * 8;
            const size_t g = base + (size_t)(kk0 + ldrow) * HEAD_DIM + col;
            CP_ASYNC16(smem_u32(&sK[ldrow * FPAD + col]), Kg + g);
            CP_ASYNC16(smem_u32(&sV[ldrow * FPAD + col]), Vg + g);
        }
        asm volatile("cp.async.commit_group;" ::: "memory");
    };

    float oacc[8][4];
#pragma unroll
    for (int nt = 0; nt < 8; nt++)
#pragma unroll
        for (int c = 0; c < 4; c++) oacc[nt][c] = 0.f;
    float mrow[2] = {-1e30f, -1e30f};
    float lrow[2] = {0.f, 0.f};

    const int r0 = lane >> 2;
    const int nIter = i0 / 64 + 2;

    issue_kv(0, 0);

    for (int it = 0; it < nIter; it++) {
        asm volatile("cp.async.wait_group 0;" ::: "memory");
        __syncthreads();
        if (it + 1 < nIter) issue_kv(it + 1, (it + 1) & 1);

        const __half* sK = kvBase + (it & 1) * KV_ST;
        const __half* sV = sK + 64 * FPAD;
        const int kk0 = it * 64;

        // ---- S = Q K^T (base-2 logits; Q pre-scaled) ----
        float sacc[8][4];
#pragma unroll
        for (int nt = 0; nt < 8; nt++)
#pragma unroll
            for (int c = 0; c < 4; c++) sacc[nt][c] = 0.f;

#pragma unroll
        for (int ks = 0; ks < 4; ks++) {
            uint32_t af[4];
            const int qof = (wid * 16 + (lane & 15)) * FPAD + ks * 16 + (lane >> 4) * 8;
            ldsm_x4(af, smem_u32(&sQ[qof]));
            uint32_t bf[8][2];
#pragma unroll
            for (int njp = 0; njp < 4; njp++) {
                const int t = lane >> 3;
                const int kof = (njp * 16 + (t >> 1) * 8 + (lane & 7)) * FPAD +
                                ks * 16 + (t & 1) * 8;
                uint32_t r[4];
                ldsm_x4(r, smem_u32(&sK[kof]));
                bf[njp * 2 + 0][0] = r[0]; bf[njp * 2 + 0][1] = r[1];
                bf[njp * 2 + 1][0] = r[2]; bf[njp * 2 + 1][1] = r[3];
            }
#pragma unroll
            for (int nt = 0; nt < 8; nt++)
                mma16816h(sacc[nt], af, bf[nt]);
        }

        // ---- causal mask + online softmax (exp2 domain) ----
        const bool domask = (kk0 + 63 > i0 + wid * 16);
        float tmax[2] = {-1e30f, -1e30f};
#pragma unroll
        for (int nt = 0; nt < 8; nt++) {
#pragma unroll
            for (int c = 0; c < 4; c++) {
                float s = sacc[nt][c];
                if (domask) {
                    const int gi = i0 + wid * 16 + r0 + (c >> 1) * 8;
                    const int gj = kk0 + nt * 8 + (lane & 3) * 2 + (c & 1);
                    if (gj > gi) s = -1e30f;
                }
                sacc[nt][c] = s;
                tmax[c >> 1] = fmaxf(tmax[c >> 1], s);
            }
        }
#pragma unroll
        for (int h2 = 0; h2 < 2; h2++) {
            tmax[h2] = fmaxf(tmax[h2], __shfl_xor_sync(0xffffffffu, tmax[h2], 1));
            tmax[h2] = fmaxf(tmax[h2], __shfl_xor_sync(0xffffffffu, tmax[h2], 2));
        }
        float fac[2], mnew[2];
#pragma unroll
        for (int h2 = 0; h2 < 2; h2++) {
            mnew[h2] = fmaxf(mrow[h2], tmax[h2]);
            fac[h2] = exp2f(mrow[h2] - mnew[h2]);
            mrow[h2] = mnew[h2];
            lrow[h2] *= fac[h2];
        }
#pragma unroll
        for (int nt = 0; nt < 8; nt++)
#pragma unroll
            for (int c = 0; c < 4; c++) oacc[nt][c] *= fac[c >> 1];

#pragma unroll
        for (int nt = 0; nt < 8; nt++) {
#pragma unroll
            for (int c = 0; c < 4; c++) {
                const float p = exp2f(sacc[nt][c] - mnew[c >> 1]);
                sacc[nt][c] = p;
                lrow[c >> 1] += p;
            }
        }

        // ---- pack P into fp16 A fragments ----
        uint32_t pf[4][4];
#pragma unroll
        for (int t = 0; t < 4; t++) {
#pragma unroll
            for (int q = 0; q < 4; q++) {
                const float pa = sacc[2 * t + (q >> 1)][(q & 1) * 2 + 0];
                const float pb = sacc[2 * t + (q >> 1)][(q & 1) * 2 + 1];
                const __half2 h = __floats2half2_rn(pa, pb);
                pf[t][q] = *(const uint32_t*)&h;
            }
        }

        // ---- O += P V ----
#pragma unroll
        for (int ks = 0; ks < 4; ks++) {
            uint32_t bf[8][2];
#pragma unroll
            for (int njp = 0; njp < 4; njp++) {
                const int t = lane >> 3;
                const int vof = (ks * 16 + (t & 1) * 8 + (lane & 7)) * FPAD +
                                njp * 16 + (t >> 1) * 8;
                uint32_t r[4];
                ldsm_x4_t(r, smem_u32(&sV[vof]));
                bf[njp * 2 + 0][0] = r[0]; bf[njp * 2 + 0][1] = r[1];
                bf[njp * 2 + 1][0] = r[2]; bf[njp * 2 + 1][1] = r[3];
            }
#pragma unroll
            for (int nt = 0; nt < 8; nt++)
                mma16816h(oacc[nt], pf[ks], bf[nt]);
        }
        // no trailing barrier: next iteration's top wait+syncthreads orders
        // buffer reuse (double buffer spans two iterations).
    }

    // ---- finalize ----
    float inv[2];
#pragma unroll
    for (int h2 = 0; h2 < 2; h2++) {
        float l = lrow[h2];
        l += __shfl_xor_sync(0xffffffffu, l, 1);
        l += __shfl_xor_sync(0xffffffffu, l, 2);
        inv[h2] = 1.f / l;
    }
    const int b = bh >> 4;
    const int h = bh & 15;
#pragma unroll
    for (int nt = 0; nt < 8; nt++) {
#pragma unroll
        for (int half = 0; half < 2; half++) {
            const int gi = i0 + wid * 16 + r0 + half * 8;
            const int d0 = nt * 8 + (lane & 3) * 2;
            const float v0 = oacc[nt][half * 2 + 0] * inv[half];
            const float v1 = oacc[nt][half * 2 + 1] * inv[half];
            const size_t idx = ((size_t)(b * SEQ + gi)) * D_MODEL + h * HEAD_DIM + d0;
            *(__half2*)&Oa[idx] = __floats2half2_rn(v0, v1);
        }
    }
}

// ---------------------------------------------------------------------------
__global__ void __launch_bounds__(256) cvt_kernel(
    const float4* __restrict__ in0, const float4* __restrict__ in1,
    const float4* __restrict__ in2,
    __half2* __restrict__ o0, __half2* __restrict__ o1,
    __half2* __restrict__ o2, int n4)
{
    const float4* in = (blockIdx.z == 0) ? in0 : (blockIdx.z == 1) ? in1 : in2;
    __half2* out = (blockIdx.z == 0) ? o0 : (blockIdx.z == 1) ? o1 : o2;
    const int stride = gridDim.x * blockDim.x;
    for (int i = blockIdx.x * blockDim.x + threadIdx.x; i < n4; i += stride) {
        float4 v = in[i];
        out[i * 2 + 0] = __floats2half2_rn(v.x, v.y);
        out[i * 2 + 1] = __floats2half2_rn(v.z, v.w);
    }
}

__global__ void __launch_bounds__(256) wt_kernel(
    const float* __restrict__ W0, const float* __restrict__ W1,
    const float* __restrict__ W2, const float* __restrict__ W3,
    __half* __restrict__ T0, __half* __restrict__ T1,
    __half* __restrict__ T2, __half* __restrict__ T3)
{
    const int z = blockIdx.z;
    const float* W = (z == 0) ? W0 : (z == 1) ? W1 : (z == 2) ? W2 : W3;
    __half* Wt = (z == 0) ? T0 : (z == 1) ? T1 : (z == 2) ? T2 : T3;

    __shared__ float t[32][33];
    const int n0 = blockIdx.x * 32, k0 = blockIdx.y * 32;
    const int tx = threadIdx.x & 31, ty = threadIdx.x >> 5;
#pragma unroll
    for (int r = 0; r < 4; r++) {
        const int kl = ty + r * 8;
        t[kl][tx] = W[(size_t)(k0 + kl) * D_MODEL + n0 + tx];
    }
    __syncthreads();
#pragma unroll
    for (int r = 0; r < 4; r++) {
        const int nl = ty + r * 8;
        Wt[(size_t)(n0 + nl) * D_MODEL + k0 + tx] = __float2half_rn(t[tx][nl]);
    }
}

// ---------------------------------------------------------------------------
extern "C" void kernel_launch(void* const* d_in, const int* in_sizes, int n_in,
                              void* d_out, int out_size)
{
    const float* q  = (const float*)d_in[0];
    const float* k  = (const float*)d_in[1];
    const float* v  = (const float*)d_in[2];
    const float* Wq = (const float*)d_in[3];
    const float* bq = (const float*)d_in[4];
    const float* Wk = (const float*)d_in[5];
    const float* bk = (const float*)d_in[6];
    const float* Wv = (const float*)d_in[7];
    const float* bv = (const float*)d_in[8];
    const float* Wo = (const float*)d_in[9];
    const float* bo = (const float*)d_in[10];

    __half *q16, *k16, *v16, *af, *Q16, *K16, *V16;
    __half *wq, *wk, *wv, *wo;
    cudaGetSymbolAddress((void**)&q16, g_q16);
    cudaGetSymbolAddress((void**)&k16, g_k16);
    cudaGetSymbolAddress((void**)&v16, g_v16);
    cudaGetSymbolAddress((void**)&af, g_af);
    cudaGetSymbolAddress((void**)&Q16, g_Q16);
    cudaGetSymbolAddress((void**)&K16, g_K16);
    cudaGetSymbolAddress((void**)&V16, g_V16);
    cudaGetSymbolAddress((void**)&wq, g_Wq16);
    cudaGetSymbolAddress((void**)&wk, g_Wk16);
    cudaGetSymbolAddress((void**)&wv, g_Wv16);
    cudaGetSymbolAddress((void**)&wo, g_Wo16);

    cudaFuncSetAttribute(flash_kernel,
                         cudaFuncAttributeMaxDynamicSharedMemorySize, FLASH_SMEM);
    cudaFuncSetAttribute(gemm_mma_kernel<0>,
                         cudaFuncAttributeMaxDynamicSharedMemorySize, G4_SMEM);
    cudaFuncSetAttribute(gemm_mma_kernel<1>,
                         cudaFuncAttributeMaxDynamicSharedMemorySize, G4_SMEM);

    wt_kernel<<<dim3(32, 32, 4), 256>>>(Wq, Wk, Wv, Wo, wq, wk, wv, wo);

    const int n4 = MROWS * D_MODEL / 4;
    cvt_kernel<<<dim3(1024, 1, 3), 256>>>(
        (const float4*)q, (const float4*)k, (const float4*)v,
        (__half2*)q16, (__half2*)k16, (__half2*)v16, n4);

    // Fused QKV projections -> single fp16 heads layout (Q scaled log2e/32)
    dim3 gQKV(GN / 128, MROWS / 128, 3);
    gemm_mma_kernel<1><<<gQKV, 256, G4_SMEM>>>(
        q16, k16, v16,
        wq, wk, wv,
        bq, bk, bv,
        Q16, K16, V16,
        nullptr);

    flash_kernel<<<dim3(SEQ / 128, BH), 256, FLASH_SMEM>>>(Q16, K16, V16, af);

    // Output projection -> fp32 d_out
    dim3 gO(GN / 128, MROWS / 128, 1);
    gemm_mma_kernel<0><<<gO, 256, G4_SMEM>>>(
        af, nullptr, nullptr,
        wo, nullptr, nullptr,
        bo, nullptr, nullptr,
        nullptr, nullptr, nullptr,
        (float*)d_out);
}

// round 14
// speedup vs baseline: 8.4238x; 1.0170x over previous
#include <cuda_runtime.h>
#include <cuda_bf16.h>
#include <cuda_fp16.h>
#include <cstdint>

#define D_MODEL 1024
#define N_HEAD  16
#define HEAD_DIM 64
#define BATCH   4
#define SEQ     2048
#define BH      (BATCH * N_HEAD)          // 64
#define MROWS   (BATCH * SEQ)             // 8192
#define GK      1024
#define GN      1024

// ---------------------------------------------------------------------------
// Scratch (device globals)
// ---------------------------------------------------------------------------
__device__ __half g_q16[MROWS * D_MODEL], g_k16[MROWS * D_MODEL], g_v16[MROWS * D_MODEL];
__device__ __half g_af[MROWS * D_MODEL];     // flash output, fp16
// projected Q/K/V single fp16, heads layout [bh][s][hd]
// (Q pre-scaled by log2(e)/32 -> scores are base-2 logits)
__device__ __half g_Q16[BH * SEQ * HEAD_DIM], g_K16[BH * SEQ * HEAD_DIM];
__device__ __half g_V16[BH * SEQ * HEAD_DIM];
// transposed weights [N][K], single fp16
__device__ __half g_Wq16[D_MODEL * D_MODEL], g_Wk16[D_MODEL * D_MODEL];
__device__ __half g_Wv16[D_MODEL * D_MODEL], g_Wo16[D_MODEL * D_MODEL];

// ---------------------------------------------------------------------------
__device__ __forceinline__ uint32_t smem_u32(const void* p) {
    uint32_t a;
    asm("{ .reg .u64 t; cvta.to.shared.u64 t, %1; cvt.u32.u64 %0, t; }"
        : "=r"(a) : "l"(p));
    return a;
}

#define CP_ASYNC16(dst_u32, src_ptr) \
    asm volatile("cp.async.cg.shared.global [%0], [%1], 16;" \
        :: "r"(dst_u32), "l"(src_ptr))

__device__ __forceinline__ void ldsm_x4(uint32_t* r, uint32_t addr) {
    asm volatile("ldmatrix.sync.aligned.m8n8.x4.shared.b16 {%0,%1,%2,%3}, [%4];"
        : "=r"(r[0]), "=r"(r[1]), "=r"(r[2]), "=r"(r[3]) : "r"(addr));
}

__device__ __forceinline__ void ldsm_x4_t(uint32_t* r, uint32_t addr) {
    asm volatile("ldmatrix.sync.aligned.m8n8.x4.trans.shared.b16 {%0,%1,%2,%3}, [%4];"
        : "=r"(r[0]), "=r"(r[1]), "=r"(r[2]), "=r"(r[3]) : "r"(addr));
}

__device__ __forceinline__ void mma16816h(float* d, const uint32_t* a,
                                          const uint32_t* b) {
    asm volatile(
        "mma.sync.aligned.m16n8k16.row.col.f32.f16.f16.f32 "
        "{%0,%1,%2,%3}, {%4,%5,%6,%7}, {%8,%9}, {%0,%1,%2,%3};"
        : "+f"(d[0]), "+f"(d[1]), "+f"(d[2]), "+f"(d[3])
        : "r"(a[0]), "r"(a[1]), "r"(a[2]), "r"(a[3]), "r"(b[0]), "r"(b[1]));
}

__device__ __forceinline__ uint32_t ex2_f16x2(uint32_t x) {
    uint32_t r;
    asm("ex2.approx.f16x2 %0, %1;" : "=r"(r) : "r"(x));
    return r;
}

// ---------------------------------------------------------------------------
// fp16 single-term GEMM: C = A * W + bias.  256 threads, BM=128 BN=128 BK=32,
// 4-stage cp.async pipeline, 81.9 KB smem -> 2 CTAs/SM.
// MODE 1: single fp16 heads layout out (z==0 scales by log2e/32).
// MODE 0: fp32 row-major out.
// ---------------------------------------------------------------------------
#define NSLABS  32
#define S_A     (128 * 40)
#define S_ST    (2 * S_A)
#define G4_SMEM (4 * S_ST * 2)            // 81920

template <int MODE>
__global__ void __launch_bounds__(256) gemm_mma_kernel(
    const __half* __restrict__ A0, const __half* __restrict__ A1,
    const __half* __restrict__ A2,
    const __half* __restrict__ B0, const __half* __restrict__ B1,
    const __half* __restrict__ B2,
    const float* __restrict__ bias0, const float* __restrict__ bias1,
    const float* __restrict__ bias2,
    __half* __restrict__ O0, __half* __restrict__ O1,
    __half* __restrict__ O2,
    float* __restrict__ out32)
{
    extern __shared__ __half gsm[];

    const int z = blockIdx.z;
    const __half* Ag = (z == 0) ? A0 : (z == 1) ? A1 : A2;
    const __half* Bg = (z == 0) ? B0 : (z == 1) ? B1 : B2;
    const float* bias = (z == 0) ? bias0 : (z == 1) ? bias1 : bias2;
    __half* outp = (z == 0) ? O0 : (z == 1) ? O1 : O2;
    const float oscale = (MODE == 1 && z == 0) ? 0.03125f * 1.4426950408889634f
                                               : 1.0f;

    const int tid = threadIdx.x;
    const int wid = tid >> 5;
    const int lane = tid & 31;
    const int m0 = blockIdx.y * 128;
    const int n0 = blockIdx.x * 128;
    const int wm = (wid & 1) * 64;
    const int wn = (wid >> 1) * 32;

    float acc[4][4][4];
#pragma unroll
    for (int i = 0; i < 4; i++)
#pragma unroll
        for (int j = 0; j < 4; j++)
#pragma unroll
            for (int c = 0; c < 4; c++) acc[i][j][c] = 0.f;

    const int ldrow = tid >> 2;
    const int ldcol = (tid & 3) * 8;

    auto issue_load = [&](int stage, int slab) {
        const int k0 = slab << 5;
        __half* sA = gsm + stage * S_ST;
        __half* sB = sA + S_A;
#pragma unroll
        for (int r = 0; r < 2; r++) {
            const int row = ldrow + r * 64;
            const size_t ga = (size_t)(m0 + row) * GK + k0 + ldcol;
            const size_t gb = (size_t)(n0 + row) * GK + k0 + ldcol;
            CP_ASYNC16(smem_u32(&sA[row * 40 + ldcol]), Ag + ga);
            CP_ASYNC16(smem_u32(&sB[row * 40 + ldcol]), Bg + gb);
        }
        asm volatile("cp.async.commit_group;" ::: "memory");
    };

    issue_load(0, 0);
    issue_load(1, 1);
    issue_load(2, 2);

    int st = 0;
    for (int i = 0; i < NSLABS; i++) {
        if (i + 3 < NSLABS) {
            issue_load((st + 3) & 3, i + 3);
            asm volatile("cp.async.wait_group 3;" ::: "memory");
        } else if (i + 2 < NSLABS) {
            asm volatile("cp.async.wait_group 2;" ::: "memory");
        } else if (i + 1 < NSLABS) {
            asm volatile("cp.async.wait_group 1;" ::: "memory");
        } else {
            asm volatile("cp.async.wait_group 0;" ::: "memory");
        }
        __syncthreads();

        const __half* sA = gsm + st * S_ST;
        const __half* sB = sA + S_A;

#pragma unroll
        for (int ks = 0; ks < 2; ks++) {
            uint32_t bf[4][2];
#pragma unroll
            for (int njp = 0; njp < 2; njp++) {
                const int t = lane >> 3;
                const int sof = (wn + njp * 16 + (t >> 1) * 8 + (lane & 7)) * 40 +
                                ks * 16 + (t & 1) * 8;
                uint32_t r[4];
                ldsm_x4(r, smem_u32(&sB[sof]));
                bf[njp * 2 + 0][0] = r[0]; bf[njp * 2 + 0][1] = r[1];
                bf[njp * 2 + 1][0] = r[2]; bf[njp * 2 + 1][1] = r[3];
            }
#pragma unroll
            for (int mi = 0; mi < 4; mi++) {
                uint32_t af[4];
                const int sof = (wm + mi * 16 + (lane & 15)) * 40 +
                                ks * 16 + (lane >> 4) * 8;
                ldsm_x4(af, smem_u32(&sA[sof]));
#pragma unroll
                for (int nj = 0; nj < 4; nj++)
                    mma16816h(acc[mi][nj], af, bf[nj]);
            }
        }
        __syncthreads();
        st = (st + 1) & 3;
    }

#pragma unroll
    for (int mi = 0; mi < 4; mi++) {
#pragma unroll
        for (int nj = 0; nj < 4; nj++) {
            const int n = n0 + wn + nj * 8 + (lane & 3) * 2;
            const float b0 = bias[n], b1 = bias[n + 1];
#pragma unroll
            for (int half = 0; half < 2; half++) {
                const int m = m0 + wm + mi * 16 + (lane >> 2) + half * 8;
                const float v0 = (acc[mi][nj][half * 2 + 0] + b0) * oscale;
                const float v1 = (acc[mi][nj][half * 2 + 1] + b1) * oscale;
                if (MODE == 1) {
                    const int b = m >> 11;
                    const int s = m & (SEQ - 1);
                    const int h = n >> 6;
                    const int d = n & 63;
                    const size_t idx =
                        ((((size_t)b * N_HEAD + h) * SEQ) + s) * HEAD_DIM + d;
                    *(__half2*)&outp[idx] = __floats2half2_rn(v0, v1);
                } else {
                    *(float2*)&out32[(size_t)m * GN + n] = make_float2(v0, v1);
                }
            }
        }
    }
}

// ---------------------------------------------------------------------------
// Fused flash attention, all-fp16, cp.async double-buffered K/V tiles,
// exp2-domain softmax with f16x2 EX2 tail.  Heavy CTAs launch first.
// grid (SEQ/128, BH), 256 threads.
// ---------------------------------------------------------------------------
#define FPAD 72
#define KV_ST (2 * 64 * FPAD)            // K+V per stage (elements)
#define FLASH_SMEM ((128 * FPAD + 2 * KV_ST) * 2)   // 55296

__global__ void __launch_bounds__(256) flash_kernel(
    const __half* __restrict__ Qg, const __half* __restrict__ Kg,
    const __half* __restrict__ Vg, __half* __restrict__ Oa)
{
    extern __shared__ __half fsm[];
    __half* sQ = fsm;                        // 128*FPAD
    __half* kvBase = sQ + 128 * FPAD;        // 2 stages of [K 64x72 | V 64x72]

    const int tid = threadIdx.x;
    const int wid = tid >> 5;
    const int lane = tid & 31;
    // reversed order: heavy causal tiles (large i0) first
    const int i0 = (gridDim.x - 1 - blockIdx.x) * 128;
    const int bh = blockIdx.y;
    const size_t base = (size_t)bh * SEQ * HEAD_DIM;

    for (int c = tid; c < 1024; c += 256) {
        const int row = c >> 3, c8 = (c & 7) * 8;
        *(uint4*)&sQ[row * FPAD + c8] =
            *(const uint4*)&Qg[base + (size_t)(i0 + row) * HEAD_DIM + c8];
    }

    const int ldrow = tid >> 2;              // 0..63
    const int ldcol = (tid & 3) * 16;        // 0,16,32,48 (halfs)

    auto issue_kv = [&](int it, int buf) {
        const int kk0 = it * 64;
        __half* sK = kvBase + buf * KV_ST;
        __half* sV = sK + 64 * FPAD;
#pragma unroll
        for (int r = 0; r < 2; r++) {
            const int col = ldcol + r * 8;
            const size_t g = base + (size_t)(kk0 + ldrow) * HEAD_DIM + col;
            CP_ASYNC16(smem_u32(&sK[ldrow * FPAD + col]), Kg + g);
            CP_ASYNC16(smem_u32(&sV[ldrow * FPAD + col]), Vg + g);
        }
        asm volatile("cp.async.commit_group;" ::: "memory");
    };

    float oacc[8][4];
#pragma unroll
    for (int nt = 0; nt < 8; nt++)
#pragma unroll
        for (int c = 0; c < 4; c++) oacc[nt][c] = 0.f;
    float mrow[2] = {-1e30f, -1e30f};
    float lrow[2] = {0.f, 0.f};

    const int r0 = lane >> 2;
    const int nIter = i0 / 64 + 2;

    issue_kv(0, 0);

    for (int it = 0; it < nIter; it++) {
        asm volatile("cp.async.wait_group 0;" ::: "memory");
        __syncthreads();
        if (it + 1 < nIter) issue_kv(it + 1, (it + 1) & 1);

        const __half* sK = kvBase + (it & 1) * KV_ST;
        const __half* sV = sK + 64 * FPAD;
        const int kk0 = it * 64;

        // ---- S = Q K^T (base-2 logits; Q pre-scaled) ----
        float sacc[8][4];
#pragma unroll
        for (int nt = 0; nt < 8; nt++)
#pragma unroll
            for (int c = 0; c < 4; c++) sacc[nt][c] = 0.f;

#pragma unroll
        for (int ks = 0; ks < 4; ks++) {
            uint32_t af[4];
            const int qof = (wid * 16 + (lane & 15)) * FPAD + ks * 16 + (lane >> 4) * 8;
            ldsm_x4(af, smem_u32(&sQ[qof]));
            uint32_t bf[8][2];
#pragma unroll
            for (int njp = 0; njp < 4; njp++) {
                const int t = lane >> 3;
                const int kof = (njp * 16 + (t >> 1) * 8 + (lane & 7)) * FPAD +
                                ks * 16 + (t & 1) * 8;
                uint32_t r[4];
                ldsm_x4(r, smem_u32(&sK[kof]));
                bf[njp * 2 + 0][0] = r[0]; bf[njp * 2 + 0][1] = r[1];
                bf[njp * 2 + 1][0] = r[2]; bf[njp * 2 + 1][1] = r[3];
            }
#pragma unroll
            for (int nt = 0; nt < 8; nt++)
                mma16816h(sacc[nt], af, bf[nt]);
        }

        // ---- causal mask + running max ----
        const bool domask = (kk0 + 63 > i0 + wid * 16);
        float tmax[2] = {-1e30f, -1e30f};
#pragma unroll
        for (int nt = 0; nt < 8; nt++) {
#pragma unroll
            for (int c = 0; c < 4; c++) {
                float s = sacc[nt][c];
                if (domask) {
                    const int gi = i0 + wid * 16 + r0 + (c >> 1) * 8;
                    const int gj = kk0 + nt * 8 + (lane & 3) * 2 + (c & 1);
                    if (gj > gi) s = -1e30f;
                }
                sacc[nt][c] = s;
                tmax[c >> 1] = fmaxf(tmax[c >> 1], s);
            }
        }
#pragma unroll
        for (int h2 = 0; h2 < 2; h2++) {
            tmax[h2] = fmaxf(tmax[h2], __shfl_xor_sync(0xffffffffu, tmax[h2], 1));
            tmax[h2] = fmaxf(tmax[h2], __shfl_xor_sync(0xffffffffu, tmax[h2], 2));
        }
        float fac[2], mnew[2];
#pragma unroll
        for (int h2 = 0; h2 < 2; h2++) {
            mnew[h2] = fmaxf(mrow[h2], tmax[h2]);
            fac[h2] = exp2f(mrow[h2] - mnew[h2]);
            mrow[h2] = mnew[h2];
            lrow[h2] *= fac[h2];
        }
        // rescale O only if some row's max advanced (warp-uniform branch)
        if (__any_sync(0xffffffffu, (fac[0] != 1.f) | (fac[1] != 1.f))) {
#pragma unroll
            for (int nt = 0; nt < 8; nt++)
#pragma unroll
                for (int c = 0; c < 4; c++) oacc[nt][c] *= fac[c >> 1];
        }

        // ---- p = exp2(s - mnew): fp32 diff, f16x2 EX2; pf is the PV A-frag ----
        uint32_t pf[4][4];
        __half2 lsum[2];
        lsum[0] = __floats2half2_rn(0.f, 0.f);
        lsum[1] = __floats2half2_rn(0.f, 0.f);
#pragma unroll
        for (int t = 0; t < 4; t++) {
#pragma unroll
            for (int q = 0; q < 4; q++) {
                const int nt = 2 * t + (q >> 1);
                const int hh = q & 1;              // row-half (c>>1)
                const float da = sacc[nt][hh * 2 + 0] - mnew[hh];
                const float db = sacc[nt][hh * 2 + 1] - mnew[hh];
                const __half2 dh = __floats2half2_rn(da, db);
                const uint32_t ph = ex2_f16x2(*(const uint32_t*)&dh);
                pf[t][q] = ph;
                lsum[hh] = __hadd2(lsum[hh], *(const __half2*)&ph);
            }
        }
#pragma unroll
        for (int h2 = 0; h2 < 2; h2++) {
            const float2 lf = __half22float2(lsum[h2]);
            lrow[h2] += lf.x + lf.y;
        }

        // ---- O += P V ----
#pragma unroll
        for (int ks = 0; ks < 4; ks++) {
            uint32_t bf[8][2];
#pragma unroll
            for (int njp = 0; njp < 4; njp++) {
                const int t = lane >> 3;
                const int vof = (ks * 16 + (t & 1) * 8 + (lane & 7)) * FPAD +
                                njp * 16 + (t >> 1) * 8;
                uint32_t r[4];
                ldsm_x4_t(r, smem_u32(&sV[vof]));
                bf[njp * 2 + 0][0] = r[0]; bf[njp * 2 + 0][1] = r[1];
                bf[njp * 2 + 1][0] = r[2]; bf[njp * 2 + 1][1] = r[3];
            }
#pragma unroll
            for (int nt = 0; nt < 8; nt++)
                mma16816h(oacc[nt], pf[ks], bf[nt]);
        }
        // no trailing barrier: double buffer spans two iterations.
    }

    // ---- finalize ----
    float inv[2];
#pragma unroll
    for (int h2 = 0; h2 < 2; h2++) {
        float l = lrow[h2];
        l += __shfl_xor_sync(0xffffffffu, l, 1);
        l += __shfl_xor_sync(0xffffffffu, l, 2);
        inv[h2] = 1.f / l;
    }
    const int b = bh >> 4;
    const int h = bh & 15;
#pragma unroll
    for (int nt = 0; nt < 8; nt++) {
#pragma unroll
        for (int half = 0; half < 2; half++) {
            const int gi = i0 + wid * 16 + r0 + half * 8;
            const int d0 = nt * 8 + (lane & 3) * 2;
            const float v0 = oacc[nt][half * 2 + 0] * inv[half];
            const float v1 = oacc[nt][half * 2 + 1] * inv[half];
            const size_t idx = ((size_t)(b * SEQ + gi)) * D_MODEL + h * HEAD_DIM + d0;
            *(__half2*)&Oa[idx] = __floats2half2_rn(v0, v1);
        }
    }
}

// ---------------------------------------------------------------------------
__global__ void __launch_bounds__(256) cvt_kernel(
    const float4* __restrict__ in0, const float4* __restrict__ in1,
    const float4* __restrict__ in2,
    __half2* __restrict__ o0, __half2* __restrict__ o1,
    __half2* __restrict__ o2, int n4)
{
    const float4* in = (blockIdx.z == 0) ? in0 : (blockIdx.z == 1) ? in1 : in2;
    __half2* out = (blockIdx.z == 0) ? o0 : (blockIdx.z == 1) ? o1 : o2;
    const int stride = gridDim.x * blockDim.x;
    for (int i = blockIdx.x * blockDim.x + threadIdx.x; i < n4; i += stride) {
        float4 v = in[i];
        out[i * 2 + 0] = __floats2half2_rn(v.x, v.y);
        out[i * 2 + 1] = __floats2half2_rn(v.z, v.w);
    }
}

__global__ void __launch_bounds__(256) wt_kernel(
    const float* __restrict__ W0, const float* __restrict__ W1,
    const float* __restrict__ W2, const float* __restrict__ W3,
    __half* __restrict__ T0, __half* __restrict__ T1,
    __half* __restrict__ T2, __half* __restrict__ T3)
{
    const int z = blockIdx.z;
    const float* W = (z == 0) ? W0 : (z == 1) ? W1 : (z == 2) ? W2 : W3;
    __half* Wt = (z == 0) ? T0 : (z == 1) ? T1 : (z == 2) ? T2 : T3;

    __shared__ float t[32][33];
    const int n0 = blockIdx.x * 32, k0 = blockIdx.y * 32;
    const int tx = threadIdx.x & 31, ty = threadIdx.x >> 5;
#pragma unroll
    for (int r = 0; r < 4; r++) {
        const int kl = ty + r * 8;
        t[kl][tx] = W[(size_t)(k0 + kl) * D_MODEL + n0 + tx];
    }
    __syncthreads();
#pragma unroll
    for (int r = 0; r < 4; r++) {
        const int nl = ty + r * 8;
        Wt[(size_t)(n0 + nl) * D_MODEL + k0 + tx] = __float2half_rn(t[tx][nl]);
    }
}

// ---------------------------------------------------------------------------
extern "C" void kernel_launch(void* const* d_in, const int* in_sizes, int n_in,
                              void* d_out, int out_size)
{
    const float* q  = (const float*)d_in[0];
    const float* k  = (const float*)d_in[1];
    const float* v  = (const float*)d_in[2];
    const float* Wq = (const float*)d_in[3];
    const float* bq = (const float*)d_in[4];
    const float* Wk = (const float*)d_in[5];
    const float* bk = (const float*)d_in[6];
    const float* Wv = (const float*)d_in[7];
    const float* bv = (const float*)d_in[8];
    const float* Wo = (const float*)d_in[9];
    const float* bo = (const float*)d_in[10];

    __half *q16, *k16, *v16, *af, *Q16, *K16, *V16;
    __half *wq, *wk, *wv, *wo;
    cudaGetSymbolAddress((void**)&q16, g_q16);
    cudaGetSymbolAddress((void**)&k16, g_k16);
    cudaGetSymbolAddress((void**)&v16, g_v16);
    cudaGetSymbolAddress((void**)&af, g_af);
    cudaGetSymbolAddress((void**)&Q16, g_Q16);
    cudaGetSymbolAddress((void**)&K16, g_K16);
    cudaGetSymbolAddress((void**)&V16, g_V16);
    cudaGetSymbolAddress((void**)&wq, g_Wq16);
    cudaGetSymbolAddress((void**)&wk, g_Wk16);
    cudaGetSymbolAddress((void**)&wv, g_Wv16);
    cudaGetSymbolAddress((void**)&wo, g_Wo16);

    cudaFuncSetAttribute(flash_kernel,
                         cudaFuncAttributeMaxDynamicSharedMemorySize, FLASH_SMEM);
    cudaFuncSetAttribute(gemm_mma_kernel<0>,
                         cudaFuncAttributeMaxDynamicSharedMemorySize, G4_SMEM);
    cudaFuncSetAttribute(gemm_mma_kernel<1>,
                         cudaFuncAttributeMaxDynamicSharedMemorySize, G4_SMEM);

    wt_kernel<<<dim3(32, 32, 4), 256>>>(Wq, Wk, Wv, Wo, wq, wk, wv, wo);

    const int n4 = MROWS * D_MODEL / 4;
    cvt_kernel<<<dim3(1024, 1, 3), 256>>>(
        (const float4*)q, (const float4*)k, (const float4*)v,
        (__half2*)q16, (__half2*)k16, (__half2*)v16, n4);

    // Fused QKV projections -> single fp16 heads layout (Q scaled log2e/32)
    dim3 gQKV(GN / 128, MROWS / 128, 3);
    gemm_mma_kernel<1><<<gQKV, 256, G4_SMEM>>>(
        q16, k16, v16,
        wq, wk, wv,
        bq, bk, bv,
        Q16, K16, V16,
        nullptr);

    flash_kernel<<<dim3(SEQ / 128, BH), 256, FLASH_SMEM>>>(Q16, K16, V16, af);

    // Output projection -> fp32 d_out
    dim3 gO(GN / 128, MROWS / 128, 1);
    gemm_mma_kernel<0><<<gO, 256, G4_SMEM>>>(
        af, nullptr, nullptr,
        wo, nullptr, nullptr,
        bo, nullptr, nullptr,
        nullptr, nullptr, nullptr,
        (float*)d_out);
}